// round 1
// baseline (speedup 1.0000x reference)
#include <cuda_runtime.h>

#define BB 2
#define SS 2048
#define EE 1024
#define NH 16
#define NKV 4
#define HD 64
#define TOKENS (BB*SS)

// Scratch (device globals; no allocation allowed)
__device__ float g_Q[TOKENS * NH * HD];   // [tok][h*64+d]
__device__ float g_K[TOKENS * NKV * HD];  // [tok][hkv*64+d]
__device__ float g_V[TOKENS * NKV * HD];
__device__ float g_Y[TOKENS * NH * HD];   // attention output pre-proj

// ---------------------------------------------------------------------------
// Fused QKV GEMM: C[4096, 1536] = X[4096,1024] @ [Wq;Wk;Wv]^T, scattered into
// g_Q / g_K / g_V. 64x64 tile, BK=16, 256 threads, 4x4 per-thread microtile.
// ---------------------------------------------------------------------------
__global__ __launch_bounds__(256) void qkv_gemm(
    const float* __restrict__ X,
    const float* __restrict__ Wq,
    const float* __restrict__ Wk,
    const float* __restrict__ Wv)
{
    __shared__ __align__(16) float As[16][64];
    __shared__ __align__(16) float Bs[16][64];

    int n0 = blockIdx.x * 64;
    int m0 = blockIdx.y * 64;

    const float* Wb;
    float* Cb;
    int ldc;
    if (n0 < 1024)      { Wb = Wq + (size_t)n0 * 1024;          Cb = g_Q + n0;          ldc = 1024; }
    else if (n0 < 1280) { Wb = Wk + (size_t)(n0 - 1024) * 1024; Cb = g_K + (n0 - 1024); ldc = 256;  }
    else                { Wb = Wv + (size_t)(n0 - 1280) * 1024; Cb = g_V + (n0 - 1280); ldc = 256;  }

    int t = threadIdx.x;
    int lrow = t >> 2;       // 0..63
    int seg  = t & 3;        // 0..3
    int ty = t >> 4;         // 0..15
    int tx = t & 15;         // 0..15

    float c[4][4] = {};

    for (int k0 = 0; k0 < 1024; k0 += 16) {
        float4 av = *(const float4*)&X[(size_t)(m0 + lrow) * 1024 + k0 + seg * 4];
        float4 bv = *(const float4*)&Wb[(size_t)lrow * 1024 + k0 + seg * 4];
        As[seg*4+0][lrow] = av.x; As[seg*4+1][lrow] = av.y;
        As[seg*4+2][lrow] = av.z; As[seg*4+3][lrow] = av.w;
        Bs[seg*4+0][lrow] = bv.x; Bs[seg*4+1][lrow] = bv.y;
        Bs[seg*4+2][lrow] = bv.z; Bs[seg*4+3][lrow] = bv.w;
        __syncthreads();
        #pragma unroll
        for (int k = 0; k < 16; k++) {
            float4 a = *(const float4*)&As[k][ty * 4];
            float4 b = *(const float4*)&Bs[k][tx * 4];
            c[0][0] += a.x*b.x; c[0][1] += a.x*b.y; c[0][2] += a.x*b.z; c[0][3] += a.x*b.w;
            c[1][0] += a.y*b.x; c[1][1] += a.y*b.y; c[1][2] += a.y*b.z; c[1][3] += a.y*b.w;
            c[2][0] += a.z*b.x; c[2][1] += a.z*b.y; c[2][2] += a.z*b.z; c[2][3] += a.z*b.w;
            c[3][0] += a.w*b.x; c[3][1] += a.w*b.y; c[3][2] += a.w*b.z; c[3][3] += a.w*b.w;
        }
        __syncthreads();
    }

    #pragma unroll
    for (int i = 0; i < 4; i++)
        #pragma unroll
        for (int j = 0; j < 4; j++)
            Cb[(size_t)(m0 + ty*4 + i) * ldc + tx*4 + j] = c[i][j];
}

// ---------------------------------------------------------------------------
// Output proj GEMM: out[4096,1024] = g_Y @ Wproj^T
// ---------------------------------------------------------------------------
__global__ __launch_bounds__(256) void proj_gemm(
    const float* __restrict__ Wp, float* __restrict__ out)
{
    __shared__ __align__(16) float As[16][64];
    __shared__ __align__(16) float Bs[16][64];

    int n0 = blockIdx.x * 64;
    int m0 = blockIdx.y * 64;

    int t = threadIdx.x;
    int lrow = t >> 2, seg = t & 3;
    int ty = t >> 4, tx = t & 15;

    float c[4][4] = {};

    for (int k0 = 0; k0 < 1024; k0 += 16) {
        float4 av = *(const float4*)&g_Y[(size_t)(m0 + lrow) * 1024 + k0 + seg * 4];
        float4 bv = *(const float4*)&Wp[(size_t)(n0 + lrow) * 1024 + k0 + seg * 4];
        As[seg*4+0][lrow] = av.x; As[seg*4+1][lrow] = av.y;
        As[seg*4+2][lrow] = av.z; As[seg*4+3][lrow] = av.w;
        Bs[seg*4+0][lrow] = bv.x; Bs[seg*4+1][lrow] = bv.y;
        Bs[seg*4+2][lrow] = bv.z; Bs[seg*4+3][lrow] = bv.w;
        __syncthreads();
        #pragma unroll
        for (int k = 0; k < 16; k++) {
            float4 a = *(const float4*)&As[k][ty * 4];
            float4 b = *(const float4*)&Bs[k][tx * 4];
            c[0][0] += a.x*b.x; c[0][1] += a.x*b.y; c[0][2] += a.x*b.z; c[0][3] += a.x*b.w;
            c[1][0] += a.y*b.x; c[1][1] += a.y*b.y; c[1][2] += a.y*b.z; c[1][3] += a.y*b.w;
            c[2][0] += a.z*b.x; c[2][1] += a.z*b.y; c[2][2] += a.z*b.z; c[2][3] += a.z*b.w;
            c[3][0] += a.w*b.x; c[3][1] += a.w*b.y; c[3][2] += a.w*b.z; c[3][3] += a.w*b.w;
        }
        __syncthreads();
    }

    #pragma unroll
    for (int i = 0; i < 4; i++)
        #pragma unroll
        for (int j = 0; j < 4; j++)
            out[(size_t)(m0 + ty*4 + i) * 1024 + n0 + tx*4 + j] = c[i][j];
}

// ---------------------------------------------------------------------------
// Postprocess per token: gate+ve add into V, RoPE + RMS-norm (*1.2) on Q and K.
// One block per token, 128 threads (4 warps).
// ---------------------------------------------------------------------------
__global__ __launch_bounds__(128) void postproc(
    const float* __restrict__ x, const float* __restrict__ ve,
    const float* __restrict__ cosb, const float* __restrict__ sinb,
    const float* __restrict__ Wgate)
{
    int tok = blockIdx.x;
    int s = tok & (SS - 1);
    int t = threadIdx.x;
    int w = t >> 5;
    int lane = t & 31;

    __shared__ float gate[4];
    __shared__ float x12[12];

    if (t < 12) x12[t] = x[(size_t)tok * EE + t];
    __syncthreads();
    if (t < 4) {
        float acc = 0.f;
        #pragma unroll
        for (int c = 0; c < 12; c++) acc += x12[c] * Wgate[t * 12 + c];
        gate[t] = 3.f / (1.f + __expf(-acc));
    }
    __syncthreads();

    // v += gate * ve
    for (int i = t; i < 256; i += 128) {
        int hh = i >> 6;
        g_V[(size_t)tok * 256 + i] += gate[hh] * ve[(size_t)tok * 256 + i];
    }

    const float EPS = 1.1920929e-7f;
    float cv = cosb[s * 32 + lane];
    float sv = sinb[s * 32 + lane];

    // Q: warp w handles heads w, w+4, w+8, w+12
    #pragma unroll
    for (int i = 0; i < 4; i++) {
        int h = w + 4 * i;
        float* qp = &g_Q[(size_t)tok * 1024 + h * 64];
        float x1 = qp[lane], x2 = qp[lane + 32];
        float r1 =  x1 * cv + x2 * sv;
        float r2 = -x1 * sv + x2 * cv;
        float ss = r1 * r1 + r2 * r2;
        #pragma unroll
        for (int o = 16; o; o >>= 1) ss += __shfl_xor_sync(0xFFFFFFFFu, ss, o);
        float scale = rsqrtf(ss * (1.f / 64.f) + EPS) * 1.2f;
        qp[lane] = r1 * scale;
        qp[lane + 32] = r2 * scale;
    }

    // K: warp w handles head w
    {
        float* kp = &g_K[(size_t)tok * 256 + w * 64];
        float x1 = kp[lane], x2 = kp[lane + 32];
        float r1 =  x1 * cv + x2 * sv;
        float r2 = -x1 * sv + x2 * cv;
        float ss = r1 * r1 + r2 * r2;
        #pragma unroll
        for (int o = 16; o; o >>= 1) ss += __shfl_xor_sync(0xFFFFFFFFu, ss, o);
        float scale = rsqrtf(ss * (1.f / 64.f) + EPS) * 1.2f;
        kp[lane] = r1 * scale;
        kp[lane + 32] = r2 * scale;
    }
}

// ---------------------------------------------------------------------------
// Causal flash attention, fp32. Grid: (S/128, NH, B), 128 threads.
// Each thread owns one q row: q[64], O[64], s[64] in registers.
// K/V 64x64 tiles in SMEM, read via broadcast (conflict-free).
// ---------------------------------------------------------------------------
__global__ __launch_bounds__(128, 1) void attn_kernel()
{
    __shared__ __align__(16) float Ks[64][64];
    __shared__ __align__(16) float Vs[64][64];

    int qb = blockIdx.x;       // 0..15
    int h  = blockIdx.y;       // 0..15
    int b  = blockIdx.z;       // 0..1
    int hkv = h >> 2;
    int t = threadIdx.x;       // 0..127
    int row = qb * 128 + t;    // q row within sequence
    size_t tok = (size_t)b * SS + row;

    float q[64];
    const float* qp = &g_Q[tok * 1024 + h * 64];
    #pragma unroll
    for (int d4 = 0; d4 < 16; d4++) {
        float4 v = *(const float4*)&qp[d4 * 4];
        q[d4*4+0] = v.x; q[d4*4+1] = v.y; q[d4*4+2] = v.z; q[d4*4+3] = v.w;
    }

    float O[64];
    #pragma unroll
    for (int d = 0; d < 64; d++) O[d] = 0.f;
    float m = -1e30f, l = 0.f;

    int ntiles = 2 * qb + 2;
    for (int kt = 0; kt < ntiles; kt++) {
        size_t base = (size_t)b * SS + kt * 64;
        for (int idx = t; idx < 64 * 16; idx += 128) {
            int c = idx >> 4, d4 = idx & 15;
            *(float4*)&Ks[c][d4*4] = *(const float4*)&g_K[(base + c) * 256 + hkv * 64 + d4 * 4];
            *(float4*)&Vs[c][d4*4] = *(const float4*)&g_V[(base + c) * 256 + hkv * 64 + d4 * 4];
        }
        __syncthreads();

        float s[64];
        #pragma unroll
        for (int c = 0; c < 64; c++) {
            float acc = 0.f;
            #pragma unroll
            for (int d4 = 0; d4 < 16; d4++) {
                float4 k4 = *(const float4*)&Ks[c][d4 * 4];
                acc += q[d4*4+0]*k4.x + q[d4*4+1]*k4.y + q[d4*4+2]*k4.z + q[d4*4+3]*k4.w;
            }
            int col = kt * 64 + c;
            s[c] = (col <= row) ? acc * 0.125f : -1e30f;
        }

        // online softmax update
        float mt = -1e30f;
        #pragma unroll
        for (int c = 0; c < 64; c++) mt = fmaxf(mt, s[c]);
        float mnew = fmaxf(m, mt);
        float corr = __expf(m - mnew);
        float ls = 0.f;
        #pragma unroll
        for (int c = 0; c < 64; c++) { float p = __expf(s[c] - mnew); s[c] = p; ls += p; }
        l = l * corr + ls;
        #pragma unroll
        for (int d = 0; d < 64; d++) O[d] *= corr;
        m = mnew;

        // O += P @ V
        #pragma unroll
        for (int c = 0; c < 64; c++) {
            float p = s[c];
            #pragma unroll
            for (int d4 = 0; d4 < 16; d4++) {
                float4 v4 = *(const float4*)&Vs[c][d4 * 4];
                O[d4*4+0] += p * v4.x; O[d4*4+1] += p * v4.y;
                O[d4*4+2] += p * v4.z; O[d4*4+3] += p * v4.w;
            }
        }
        __syncthreads();
    }

    float inv = 1.f / l;
    float* yp = &g_Y[tok * 1024 + h * 64];
    #pragma unroll
    for (int d4 = 0; d4 < 16; d4++) {
        float4 v;
        v.x = O[d4*4+0] * inv; v.y = O[d4*4+1] * inv;
        v.z = O[d4*4+2] * inv; v.w = O[d4*4+3] * inv;
        *(float4*)&yp[d4 * 4] = v;
    }
}

// ---------------------------------------------------------------------------
extern "C" void kernel_launch(void* const* d_in, const int* in_sizes, int n_in,
                              void* d_out, int out_size)
{
    const float* x     = (const float*)d_in[0];
    const float* ve    = (const float*)d_in[1];
    const float* cosb  = (const float*)d_in[2];
    const float* sinb  = (const float*)d_in[3];
    // d_in[4] = attn_mask (causal, reconstructed analytically)
    const float* Wq    = (const float*)d_in[5];
    const float* Wk    = (const float*)d_in[6];
    const float* Wv    = (const float*)d_in[7];
    const float* Wproj = (const float*)d_in[8];
    const float* Wgate = (const float*)d_in[9];
    float* out = (float*)d_out;

    dim3 g1(24, 64);
    qkv_gemm<<<g1, 256>>>(x, Wq, Wk, Wv);

    postproc<<<TOKENS, 128>>>(x, ve, cosb, sinb, Wgate);

    dim3 g3(SS / 128, NH, BB);
    attn_kernel<<<g3, 128>>>();

    dim3 g4(16, 64);
    proj_gemm<<<g4, 256>>>(Wproj, out);
}

// round 2
// speedup vs baseline: 1.8123x; 1.8123x over previous
#include <cuda_runtime.h>

#define BB 2
#define SS 2048
#define EE 1024
#define NH 16
#define NKV 4
#define HD 64
#define TOKENS (BB*SS)

typedef unsigned long long u64;

__device__ float g_Q[TOKENS * NH * HD];
__device__ float g_K[TOKENS * NKV * HD];
__device__ float g_V[TOKENS * NKV * HD];
__device__ float g_Y[TOKENS * NH * HD];

// ---- packed fp32x2 helpers (Blackwell FFMA2 path, PTX-only) ----
__device__ __forceinline__ u64 ffma2(u64 a, u64 b, u64 c) {
    u64 d; asm("fma.rn.f32x2 %0, %1, %2, %3;" : "=l"(d) : "l"(a), "l"(b), "l"(c)); return d;
}
__device__ __forceinline__ u64 fmul2(u64 a, u64 b) {
    u64 d; asm("mul.rn.f32x2 %0, %1, %2;" : "=l"(d) : "l"(a), "l"(b)); return d;
}
__device__ __forceinline__ u64 fadd2(u64 a, u64 b) {
    u64 d; asm("add.rn.f32x2 %0, %1, %2;" : "=l"(d) : "l"(a), "l"(b)); return d;
}
__device__ __forceinline__ u64 pack2(float x) {
    u64 d; asm("mov.b64 %0, {%1, %1};" : "=l"(d) : "f"(x)); return d;
}
__device__ __forceinline__ float2 unpack2(u64 v) {
    float2 f; asm("mov.b64 {%0, %1}, %2;" : "=f"(f.x), "=f"(f.y) : "l"(v)); return f;
}

// ---------------------------------------------------------------------------
// GEMM core: C[M,N] = A[M,1024] @ B[N,1024]^T  (both K-major)
// 128x128 tile, BK=16, 256 threads, 8x8 microtile as 2x2 blocks of 4x4,
// FFMA2 inner loop.
// ---------------------------------------------------------------------------
struct GemmOut { float* base; int ldc; };

template<bool QKV>
__device__ __forceinline__ void gemm_body(
    const float* __restrict__ A, const float* __restrict__ Bmat,
    float* __restrict__ Cb, int ldc, int m0)
{
    __shared__ __align__(16) float As[16][128];
    __shared__ __align__(16) float Bs[16][128];

    int t = threadIdx.x;
    int arow = t & 127;
    int khalf = (t >> 7) * 8;
    int ty = t >> 4;        // 0..15
    int tx = t & 15;        // 0..15

    u64 c2[8][4];
    #pragma unroll
    for (int i = 0; i < 8; i++)
        #pragma unroll
        for (int j = 0; j < 4; j++) c2[i][j] = 0ull;

    const float* arp = &A[(size_t)(m0 + arow) * 1024 + khalf];
    const float* brp = &Bmat[(size_t)arow * 1024 + khalf];

    for (int k0 = 0; k0 < 1024; k0 += 16) {
        float4 a0 = *(const float4*)&arp[k0];
        float4 a1 = *(const float4*)&arp[k0 + 4];
        float4 b0 = *(const float4*)&brp[k0];
        float4 b1 = *(const float4*)&brp[k0 + 4];
        As[khalf+0][arow] = a0.x; As[khalf+1][arow] = a0.y;
        As[khalf+2][arow] = a0.z; As[khalf+3][arow] = a0.w;
        As[khalf+4][arow] = a1.x; As[khalf+5][arow] = a1.y;
        As[khalf+6][arow] = a1.z; As[khalf+7][arow] = a1.w;
        Bs[khalf+0][arow] = b0.x; Bs[khalf+1][arow] = b0.y;
        Bs[khalf+2][arow] = b0.z; Bs[khalf+3][arow] = b0.w;
        Bs[khalf+4][arow] = b1.x; Bs[khalf+5][arow] = b1.y;
        Bs[khalf+6][arow] = b1.z; Bs[khalf+7][arow] = b1.w;
        __syncthreads();
        #pragma unroll
        for (int k = 0; k < 16; k++) {
            float4 av0 = *(const float4*)&As[k][ty * 4];
            float4 av1 = *(const float4*)&As[k][64 + ty * 4];
            ulonglong2 bv0 = *(const ulonglong2*)&Bs[k][tx * 4];
            ulonglong2 bv1 = *(const ulonglong2*)&Bs[k][64 + tx * 4];
            u64 pa[8];
            pa[0] = pack2(av0.x); pa[1] = pack2(av0.y);
            pa[2] = pack2(av0.z); pa[3] = pack2(av0.w);
            pa[4] = pack2(av1.x); pa[5] = pack2(av1.y);
            pa[6] = pack2(av1.z); pa[7] = pack2(av1.w);
            #pragma unroll
            for (int i = 0; i < 8; i++) {
                c2[i][0] = ffma2(pa[i], bv0.x, c2[i][0]);
                c2[i][1] = ffma2(pa[i], bv0.y, c2[i][1]);
                c2[i][2] = ffma2(pa[i], bv1.x, c2[i][2]);
                c2[i][3] = ffma2(pa[i], bv1.y, c2[i][3]);
            }
        }
        __syncthreads();
    }

    // Write back: rows {ty*4+i, 64+ty*4+i}, cols {tx*4.., 64+tx*4..}
    #pragma unroll
    for (int i = 0; i < 8; i++) {
        int r = (i < 4) ? (ty * 4 + i) : (64 + ty * 4 + (i - 4));
        float* rp = &Cb[(size_t)(m0 + r) * ldc];
        ulonglong2 w0; w0.x = c2[i][0]; w0.y = c2[i][1];
        ulonglong2 w1; w1.x = c2[i][2]; w1.y = c2[i][3];
        *(ulonglong2*)&rp[tx * 4]      = w0;
        *(ulonglong2*)&rp[64 + tx * 4] = w1;
    }
}

__global__ __launch_bounds__(256) void qkv_gemm(
    const float* __restrict__ X,
    const float* __restrict__ Wq,
    const float* __restrict__ Wk,
    const float* __restrict__ Wv)
{
    int n0 = blockIdx.x * 128;
    int m0 = blockIdx.y * 128;
    const float* Wb; float* Cb; int ldc;
    if (n0 < 1024)      { Wb = Wq + (size_t)n0 * 1024;          Cb = g_Q + n0;          ldc = 1024; }
    else if (n0 < 1280) { Wb = Wk + (size_t)(n0 - 1024) * 1024; Cb = g_K + (n0 - 1024); ldc = 256;  }
    else                { Wb = Wv + (size_t)(n0 - 1280) * 1024; Cb = g_V + (n0 - 1280); ldc = 256;  }
    gemm_body<true>(X, Wb, Cb, ldc, m0);
}

__global__ __launch_bounds__(256) void proj_gemm(
    const float* __restrict__ Wp, float* __restrict__ out)
{
    int n0 = blockIdx.x * 128;
    int m0 = blockIdx.y * 128;
    gemm_body<false>(g_Y, Wp + (size_t)n0 * 1024, out + n0, 1024, m0);
}

// ---------------------------------------------------------------------------
// Postprocess per token: gate+ve add into V, RoPE + RMS-norm (*1.2) on Q and K.
// ---------------------------------------------------------------------------
__global__ __launch_bounds__(128) void postproc(
    const float* __restrict__ x, const float* __restrict__ ve,
    const float* __restrict__ cosb, const float* __restrict__ sinb,
    const float* __restrict__ Wgate)
{
    int tok = blockIdx.x;
    int s = tok & (SS - 1);
    int t = threadIdx.x;
    int w = t >> 5;
    int lane = t & 31;

    __shared__ float gate[4];
    __shared__ float x12[12];

    if (t < 12) x12[t] = x[(size_t)tok * EE + t];
    __syncthreads();
    if (t < 4) {
        float acc = 0.f;
        #pragma unroll
        for (int c = 0; c < 12; c++) acc += x12[c] * Wgate[t * 12 + c];
        gate[t] = 3.f / (1.f + __expf(-acc));
    }
    __syncthreads();

    for (int i = t; i < 256; i += 128) {
        int hh = i >> 6;
        g_V[(size_t)tok * 256 + i] += gate[hh] * ve[(size_t)tok * 256 + i];
    }

    const float EPS = 1.1920929e-7f;
    float cv = cosb[s * 32 + lane];
    float sv = sinb[s * 32 + lane];

    #pragma unroll
    for (int i = 0; i < 4; i++) {
        int h = w + 4 * i;
        float* qp = &g_Q[(size_t)tok * 1024 + h * 64];
        float x1 = qp[lane], x2 = qp[lane + 32];
        float r1 =  x1 * cv + x2 * sv;
        float r2 = -x1 * sv + x2 * cv;
        float ss = r1 * r1 + r2 * r2;
        #pragma unroll
        for (int o = 16; o; o >>= 1) ss += __shfl_xor_sync(0xFFFFFFFFu, ss, o);
        float scale = rsqrtf(ss * (1.f / 64.f) + EPS) * 1.2f;
        qp[lane] = r1 * scale;
        qp[lane + 32] = r2 * scale;
    }
    {
        float* kp = &g_K[(size_t)tok * 256 + w * 64];
        float x1 = kp[lane], x2 = kp[lane + 32];
        float r1 =  x1 * cv + x2 * sv;
        float r2 = -x1 * sv + x2 * cv;
        float ss = r1 * r1 + r2 * r2;
        #pragma unroll
        for (int o = 16; o; o >>= 1) ss += __shfl_xor_sync(0xFFFFFFFFu, ss, o);
        float scale = rsqrtf(ss * (1.f / 64.f) + EPS) * 1.2f;
        kp[lane] = r1 * scale;
        kp[lane + 32] = r2 * scale;
    }
}

// ---------------------------------------------------------------------------
// Causal flash attention, fp32 + FFMA2. Grid: (S/128, NH, B), 128 threads.
// One q row per thread: q2[32], O2[32] packed u64, scores in 32-col chunks.
// ---------------------------------------------------------------------------
__global__ __launch_bounds__(128) void attn_kernel()
{
    __shared__ __align__(16) float Ks[64][64];
    __shared__ __align__(16) float Vs[64][64];

    int qb = gridDim.x - 1 - blockIdx.x;   // big tiles first
    int h  = blockIdx.y;
    int b  = blockIdx.z;
    int hkv = h >> 2;
    int t = threadIdx.x;
    int row = qb * 128 + t;
    size_t tok = (size_t)b * SS + row;

    u64 q2[32];
    {
        const ulonglong2* qr = (const ulonglong2*)&g_Q[tok * 1024 + h * 64];
        #pragma unroll
        for (int i = 0; i < 16; i++) {
            ulonglong2 v = qr[i];
            q2[2*i] = v.x; q2[2*i+1] = v.y;
        }
    }

    u64 O2[32];
    #pragma unroll
    for (int i = 0; i < 32; i++) O2[i] = 0ull;
    float m = -1e30f, l = 0.f;

    int ntiles = 2 * qb + 2;
    for (int kt = 0; kt < ntiles; kt++) {
        size_t base = (size_t)b * SS + kt * 64;
        for (int idx = t; idx < 64 * 16; idx += 128) {
            int c = idx >> 4, d4 = idx & 15;
            *(float4*)&Ks[c][d4*4] = *(const float4*)&g_K[(base + c) * 256 + hkv * 64 + d4 * 4];
            *(float4*)&Vs[c][d4*4] = *(const float4*)&g_V[(base + c) * 256 + hkv * 64 + d4 * 4];
        }
        __syncthreads();

        #pragma unroll
        for (int ch = 0; ch < 2; ch++) {
            int cbase = ch * 32;
            float s[32];
            #pragma unroll
            for (int j = 0; j < 32; j++) {
                int c = cbase + j;
                const ulonglong2* kr = (const ulonglong2*)&Ks[c][0];
                u64 acc0 = 0ull, acc1 = 0ull;
                #pragma unroll
                for (int i = 0; i < 16; i++) {
                    ulonglong2 kk = kr[i];
                    acc0 = ffma2(q2[2*i],   kk.x, acc0);
                    acc1 = ffma2(q2[2*i+1], kk.y, acc1);
                }
                float2 a = unpack2(fadd2(acc0, acc1));
                float acc = a.x + a.y;
                int col = kt * 64 + c;
                s[j] = (col <= row) ? acc * 0.125f : -1e30f;
            }

            float mt = -1e30f;
            #pragma unroll
            for (int j = 0; j < 32; j++) mt = fmaxf(mt, s[j]);
            float mnew = fmaxf(m, mt);
            float corr = __expf(m - mnew);
            float ls = 0.f;
            #pragma unroll
            for (int j = 0; j < 32; j++) {
                float p = __expf(s[j] - mnew);
                s[j] = p; ls += p;
            }
            l = l * corr + ls;
            u64 corr2 = pack2(corr);
            #pragma unroll
            for (int i = 0; i < 32; i++) O2[i] = fmul2(O2[i], corr2);
            m = mnew;

            #pragma unroll
            for (int j = 0; j < 32; j++) {
                int c = cbase + j;
                u64 p2 = pack2(s[j]);
                const ulonglong2* vr = (const ulonglong2*)&Vs[c][0];
                #pragma unroll
                for (int i = 0; i < 16; i++) {
                    ulonglong2 vv = vr[i];
                    O2[2*i]   = ffma2(p2, vv.x, O2[2*i]);
                    O2[2*i+1] = ffma2(p2, vv.y, O2[2*i+1]);
                }
            }
        }
        __syncthreads();
    }

    u64 inv2 = pack2(1.f / l);
    ulonglong2* yr = (ulonglong2*)&g_Y[tok * 1024 + h * 64];
    #pragma unroll
    for (int i = 0; i < 16; i++) {
        ulonglong2 w;
        w.x = fmul2(O2[2*i], inv2);
        w.y = fmul2(O2[2*i+1], inv2);
        yr[i] = w;
    }
}

// ---------------------------------------------------------------------------
extern "C" void kernel_launch(void* const* d_in, const int* in_sizes, int n_in,
                              void* d_out, int out_size)
{
    const float* x     = (const float*)d_in[0];
    const float* ve    = (const float*)d_in[1];
    const float* cosb  = (const float*)d_in[2];
    const float* sinb  = (const float*)d_in[3];
    const float* Wq    = (const float*)d_in[5];
    const float* Wk    = (const float*)d_in[6];
    const float* Wv    = (const float*)d_in[7];
    const float* Wproj = (const float*)d_in[8];
    const float* Wgate = (const float*)d_in[9];
    float* out = (float*)d_out;

    dim3 g1(12, 32);
    qkv_gemm<<<g1, 256>>>(x, Wq, Wk, Wv);

    postproc<<<TOKENS, 128>>>(x, ve, cosb, sinb, Wgate);

    dim3 g3(SS / 128, NH, BB);
    attn_kernel<<<g3, 128>>>();

    dim3 g4(8, 32);
    proj_gemm<<<g4, 256>>>(Wproj, out);
}

// round 4
// speedup vs baseline: 2.3410x; 1.2917x over previous
#include <cuda_runtime.h>
#include <cuda_bf16.h>
#include <cstdint>

#define BB 2
#define SS 2048
#define EE 1024
#define NH 16
#define NKV 4
#define HD 64
#define TOKENS (BB*SS)

typedef unsigned long long u64;

__device__ float g_Q[TOKENS * NH * HD];
__device__ float g_K[TOKENS * NKV * HD];
__device__ float g_V[TOKENS * NKV * HD];
__device__ float g_Y[TOKENS * NH * HD];

// bf16 hi/lo split copies (error-compensated HMMA inputs)
__device__ __nv_bfloat16 g_Xhi[TOKENS * EE],  g_Xlo[TOKENS * EE];
__device__ __nv_bfloat16 g_Whi[1536 * EE],    g_Wlo[1536 * EE];    // [Wq;Wk;Wv]
__device__ __nv_bfloat16 g_Phi[EE * EE],      g_Plo[EE * EE];      // Wproj
__device__ __nv_bfloat16 g_Yhi[TOKENS * EE],  g_Ylo[TOKENS * EE];

// ---- packed fp32x2 helpers (attention) ----
__device__ __forceinline__ u64 ffma2(u64 a, u64 b, u64 c) {
    u64 d; asm("fma.rn.f32x2 %0, %1, %2, %3;" : "=l"(d) : "l"(a), "l"(b), "l"(c)); return d;
}
__device__ __forceinline__ u64 fmul2(u64 a, u64 b) {
    u64 d; asm("mul.rn.f32x2 %0, %1, %2;" : "=l"(d) : "l"(a), "l"(b)); return d;
}
__device__ __forceinline__ u64 fadd2(u64 a, u64 b) {
    u64 d; asm("add.rn.f32x2 %0, %1, %2;" : "=l"(d) : "l"(a), "l"(b)); return d;
}
__device__ __forceinline__ u64 pack2(float x) {
    u64 d; asm("mov.b64 %0, {%1, %1};" : "=l"(d) : "f"(x)); return d;
}
__device__ __forceinline__ float2 unpack2(u64 v) {
    float2 f; asm("mov.b64 {%0, %1}, %2;" : "=f"(f.x), "=f"(f.y) : "l"(v)); return f;
}

// ---- HMMA helpers (baseline PTX; no 'a'-suffix features) ----
__device__ __forceinline__ uint32_t smem_u32(const void* p) {
    uint32_t a;
    asm("{ .reg .u64 t; cvta.to.shared.u64 t, %1; cvt.u32.u64 %0, t; }" : "=r"(a) : "l"(p));
    return a;
}
__device__ __forceinline__ void ldsm4(uint32_t r[4], uint32_t a) {
    asm volatile("ldmatrix.sync.aligned.m8n8.x4.shared.b16 {%0,%1,%2,%3}, [%4];"
        : "=r"(r[0]), "=r"(r[1]), "=r"(r[2]), "=r"(r[3]) : "r"(a));
}
__device__ __forceinline__ void ldsm2(uint32_t r[2], uint32_t a) {
    asm volatile("ldmatrix.sync.aligned.m8n8.x2.shared.b16 {%0,%1}, [%2];"
        : "=r"(r[0]), "=r"(r[1]) : "r"(a));
}
__device__ __forceinline__ void mma16816(float d[4], const uint32_t a[4], const uint32_t b[2]) {
    asm volatile("mma.sync.aligned.m16n8k16.row.col.f32.bf16.bf16.f32 "
        "{%0,%1,%2,%3}, {%4,%5,%6,%7}, {%8,%9}, {%0,%1,%2,%3};"
        : "+f"(d[0]), "+f"(d[1]), "+f"(d[2]), "+f"(d[3])
        : "r"(a[0]), "r"(a[1]), "r"(a[2]), "r"(a[3]), "r"(b[0]), "r"(b[1]));
}

// ---------------------------------------------------------------------------
// Split fp32 -> bf16 hi + lo (x = hi + lo to ~u^2 accuracy). n % 4 == 0.
// ---------------------------------------------------------------------------
__global__ __launch_bounds__(256) void split_bf16(
    const float* __restrict__ src, __nv_bfloat16* __restrict__ hi,
    __nv_bfloat16* __restrict__ lo, int n4)
{
    int i = blockIdx.x * 256 + threadIdx.x;
    if (i >= n4) return;
    float4 v = *(const float4*)(src + (size_t)i * 4);
    float f[4] = {v.x, v.y, v.z, v.w};
    __nv_bfloat16 h[4], l[4];
    #pragma unroll
    for (int e = 0; e < 4; e++) {
        h[e] = __float2bfloat16(f[e]);
        l[e] = __float2bfloat16(f[e] - __bfloat162float(h[e]));
    }
    *(uint2*)(hi + (size_t)i * 4) = *(uint2*)h;
    *(uint2*)(lo + (size_t)i * 4) = *(uint2*)l;
}

// ---------------------------------------------------------------------------
// HMMA GEMM: C[128,128] block of A[M,1024] @ B[N,1024]^T via bf16 split.
// 256 threads = 8 warps, each 64x32 (4x4 m16n8k16 tiles), BK=32.
// ---------------------------------------------------------------------------
__device__ __forceinline__ void mma_gemm(
    const __nv_bfloat16* __restrict__ Ahi, const __nv_bfloat16* __restrict__ Alo,
    const __nv_bfloat16* __restrict__ Bhi, const __nv_bfloat16* __restrict__ Blo,
    float* __restrict__ Cb, int ldc, int m0)
{
    __shared__ __align__(16) __nv_bfloat16 Ah_s[128][40];
    __shared__ __align__(16) __nv_bfloat16 Al_s[128][40];
    __shared__ __align__(16) __nv_bfloat16 Bh_s[128][40];
    __shared__ __align__(16) __nv_bfloat16 Bl_s[128][40];

    int t = threadIdx.x;
    int wid = t >> 5, lane = t & 31;
    int wr = wid >> 2;            // 0..1  -> m offset wr*64
    int wc = wid & 3;             // 0..3  -> n offset wc*32

    uint32_t aAh = smem_u32(Ah_s), aAl = smem_u32(Al_s);
    uint32_t aBh = smem_u32(Bh_s), aBl = smem_u32(Bl_s);

    float acc[4][4][4];
    #pragma unroll
    for (int mt = 0; mt < 4; mt++)
        #pragma unroll
        for (int nt = 0; nt < 4; nt++)
            #pragma unroll
            for (int e = 0; e < 4; e++) acc[mt][nt][e] = 0.f;

    for (int k0 = 0; k0 < 1024; k0 += 32) {
        if (k0) __syncthreads();
        #pragma unroll
        for (int i = 0; i < 2; i++) {
            int c = t + i * 256;          // 0..511
            int row = c >> 2, seg = (c & 3) * 8;
            size_t ga = (size_t)(m0 + row) * 1024 + k0 + seg;
            size_t gb = (size_t)row * 1024 + k0 + seg;
            *(uint4*)&Ah_s[row][seg] = *(const uint4*)&Ahi[ga];
            *(uint4*)&Al_s[row][seg] = *(const uint4*)&Alo[ga];
            *(uint4*)&Bh_s[row][seg] = *(const uint4*)&Bhi[gb];
            *(uint4*)&Bl_s[row][seg] = *(const uint4*)&Blo[gb];
        }
        __syncthreads();

        #pragma unroll
        for (int ks = 0; ks < 2; ks++) {
            int kk = ks * 16;
            uint32_t fAh[4][4], fAl[4][4], fBh[4][2], fBl[4][2];
            int arow = lane & 15;
            int acol = kk + (lane >> 4) * 8;
            #pragma unroll
            for (int mt = 0; mt < 4; mt++) {
                uint32_t off = ((wr * 64 + mt * 16 + arow) * 40 + acol) * 2;
                ldsm4(fAh[mt], aAh + off);
                ldsm4(fAl[mt], aAl + off);
            }
            int brow = lane & 7;
            int bcol = kk + (lane & 8);
            #pragma unroll
            for (int nt = 0; nt < 4; nt++) {
                uint32_t off = ((wc * 32 + nt * 8 + brow) * 40 + bcol) * 2;
                ldsm2(fBh[nt], aBh + off);
                ldsm2(fBl[nt], aBl + off);
            }
            #pragma unroll
            for (int mt = 0; mt < 4; mt++)
                #pragma unroll
                for (int nt = 0; nt < 4; nt++) {
                    mma16816(acc[mt][nt], fAh[mt], fBh[nt]);
                    mma16816(acc[mt][nt], fAl[mt], fBh[nt]);
                    mma16816(acc[mt][nt], fAh[mt], fBl[nt]);
                }
        }
    }

    // Epilogue: lane holds rows (lane>>2, +8), cols (lane&3)*2, +1
    #pragma unroll
    for (int mt = 0; mt < 4; mt++)
        #pragma unroll
        for (int nt = 0; nt < 4; nt++) {
            int r0 = m0 + wr * 64 + mt * 16 + (lane >> 2);
            int c0 = wc * 32 + nt * 8 + (lane & 3) * 2;
            float2 w0; w0.x = acc[mt][nt][0]; w0.y = acc[mt][nt][1];
            float2 w1; w1.x = acc[mt][nt][2]; w1.y = acc[mt][nt][3];
            *(float2*)&Cb[(size_t)r0 * ldc + c0]       = w0;
            *(float2*)&Cb[(size_t)(r0 + 8) * ldc + c0] = w1;
        }
}

__global__ __launch_bounds__(256) void qkv_gemm_mma()
{
    int n0 = blockIdx.x * 128;
    int m0 = blockIdx.y * 128;
    const __nv_bfloat16* Bh = g_Whi + (size_t)n0 * 1024;
    const __nv_bfloat16* Bl = g_Wlo + (size_t)n0 * 1024;
    float* Cb; int ldc;
    if (n0 < 1024)      { Cb = g_Q + n0;          ldc = 1024; }
    else if (n0 < 1280) { Cb = g_K + (n0 - 1024); ldc = 256;  }
    else                { Cb = g_V + (n0 - 1280); ldc = 256;  }
    mma_gemm(g_Xhi, g_Xlo, Bh, Bl, Cb, ldc, m0);
}

__global__ __launch_bounds__(256) void proj_gemm_mma(float* __restrict__ out)
{
    int n0 = blockIdx.x * 128;
    int m0 = blockIdx.y * 128;
    mma_gemm(g_Yhi, g_Ylo, g_Phi + (size_t)n0 * 1024, g_Plo + (size_t)n0 * 1024,
             out + n0, 1024, m0);
}

// ---------------------------------------------------------------------------
// Postprocess per token: gate+ve add into V, RoPE + RMS-norm (*1.2) on Q and K.
// ---------------------------------------------------------------------------
__global__ __launch_bounds__(128) void postproc(
    const float* __restrict__ x, const float* __restrict__ ve,
    const float* __restrict__ cosb, const float* __restrict__ sinb,
    const float* __restrict__ Wgate)
{
    int tok = blockIdx.x;
    int s = tok & (SS - 1);
    int t = threadIdx.x;
    int w = t >> 5;
    int lane = t & 31;

    __shared__ float gate[4];
    __shared__ float x12[12];

    if (t < 12) x12[t] = x[(size_t)tok * EE + t];
    __syncthreads();
    if (t < 4) {
        float acc = 0.f;
        #pragma unroll
        for (int c = 0; c < 12; c++) acc += x12[c] * Wgate[t * 12 + c];
        gate[t] = 3.f / (1.f + __expf(-acc));
    }
    __syncthreads();

    for (int i = t; i < 256; i += 128) {
        int hh = i >> 6;
        g_V[(size_t)tok * 256 + i] += gate[hh] * ve[(size_t)tok * 256 + i];
    }

    const float EPS = 1.1920929e-7f;
    float cv = cosb[s * 32 + lane];
    float sv = sinb[s * 32 + lane];

    #pragma unroll
    for (int i = 0; i < 4; i++) {
        int h = w + 4 * i;
        float* qp = &g_Q[(size_t)tok * 1024 + h * 64];
        float x1 = qp[lane], x2 = qp[lane + 32];
        float r1 =  x1 * cv + x2 * sv;
        float r2 = -x1 * sv + x2 * cv;
        float ss = r1 * r1 + r2 * r2;
        #pragma unroll
        for (int o = 16; o; o >>= 1) ss += __shfl_xor_sync(0xFFFFFFFFu, ss, o);
        float scale = rsqrtf(ss * (1.f / 64.f) + EPS) * 1.2f;
        qp[lane] = r1 * scale;
        qp[lane + 32] = r2 * scale;
    }
    {
        float* kp = &g_K[(size_t)tok * 256 + w * 64];
        float x1 = kp[lane], x2 = kp[lane + 32];
        float r1 =  x1 * cv + x2 * sv;
        float r2 = -x1 * sv + x2 * cv;
        float ss = r1 * r1 + r2 * r2;
        #pragma unroll
        for (int o = 16; o; o >>= 1) ss += __shfl_xor_sync(0xFFFFFFFFu, ss, o);
        float scale = rsqrtf(ss * (1.f / 64.f) + EPS) * 1.2f;
        kp[lane] = r1 * scale;
        kp[lane + 32] = r2 * scale;
    }
}

// ---------------------------------------------------------------------------
// Causal flash attention, fp32 + FFMA2. Grid: (S/128, NH, B), 128 threads.
// ---------------------------------------------------------------------------
__global__ __launch_bounds__(128) void attn_kernel()
{
    __shared__ __align__(16) float Ks[64][64];
    __shared__ __align__(16) float Vs[64][64];

    int qb = gridDim.x - 1 - blockIdx.x;
    int h  = blockIdx.y;
    int b  = blockIdx.z;
    int hkv = h >> 2;
    int t = threadIdx.x;
    int row = qb * 128 + t;
    size_t tok = (size_t)b * SS + row;

    u64 q2[32];
    {
        const ulonglong2* qr = (const ulonglong2*)&g_Q[tok * 1024 + h * 64];
        #pragma unroll
        for (int i = 0; i < 16; i++) {
            ulonglong2 v = qr[i];
            q2[2*i] = v.x; q2[2*i+1] = v.y;
        }
    }

    u64 O2[32];
    #pragma unroll
    for (int i = 0; i < 32; i++) O2[i] = 0ull;
    float m = -1e30f, l = 0.f;

    int ntiles = 2 * qb + 2;
    for (int kt = 0; kt < ntiles; kt++) {
        size_t base = (size_t)b * SS + kt * 64;
        for (int idx = t; idx < 64 * 16; idx += 128) {
            int c = idx >> 4, d4 = idx & 15;
            *(float4*)&Ks[c][d4*4] = *(const float4*)&g_K[(base + c) * 256 + hkv * 64 + d4 * 4];
            *(float4*)&Vs[c][d4*4] = *(const float4*)&g_V[(base + c) * 256 + hkv * 64 + d4 * 4];
        }
        __syncthreads();

        #pragma unroll
        for (int ch = 0; ch < 2; ch++) {
            int cbase = ch * 32;
            float s[32];
            #pragma unroll
            for (int j = 0; j < 32; j++) {
                int c = cbase + j;
                const ulonglong2* kr = (const ulonglong2*)&Ks[c][0];
                u64 acc0 = 0ull, acc1 = 0ull;
                #pragma unroll
                for (int i = 0; i < 16; i++) {
                    ulonglong2 kk = kr[i];
                    acc0 = ffma2(q2[2*i],   kk.x, acc0);
                    acc1 = ffma2(q2[2*i+1], kk.y, acc1);
                }
                float2 a = unpack2(fadd2(acc0, acc1));
                float acc = a.x + a.y;
                int col = kt * 64 + c;
                s[j] = (col <= row) ? acc * 0.125f : -1e30f;
            }

            float mt = -1e30f;
            #pragma unroll
            for (int j = 0; j < 32; j++) mt = fmaxf(mt, s[j]);
            float mnew = fmaxf(m, mt);
            float corr = __expf(m - mnew);
            float ls = 0.f;
            #pragma unroll
            for (int j = 0; j < 32; j++) {
                float p = __expf(s[j] - mnew);
                s[j] = p; ls += p;
            }
            l = l * corr + ls;
            u64 corr2 = pack2(corr);
            #pragma unroll
            for (int i = 0; i < 32; i++) O2[i] = fmul2(O2[i], corr2);
            m = mnew;

            #pragma unroll
            for (int j = 0; j < 32; j++) {
                int c = cbase + j;
                u64 p2 = pack2(s[j]);
                const ulonglong2* vr = (const ulonglong2*)&Vs[c][0];
                #pragma unroll
                for (int i = 0; i < 16; i++) {
                    ulonglong2 vv = vr[i];
                    O2[2*i]   = ffma2(p2, vv.x, O2[2*i]);
                    O2[2*i+1] = ffma2(p2, vv.y, O2[2*i+1]);
                }
            }
        }
        __syncthreads();
    }

    u64 inv2 = pack2(1.f / l);
    ulonglong2* yr = (ulonglong2*)&g_Y[tok * 1024 + h * 64];
    #pragma unroll
    for (int i = 0; i < 16; i++) {
        ulonglong2 w;
        w.x = fmul2(O2[2*i], inv2);
        w.y = fmul2(O2[2*i+1], inv2);
        yr[i] = w;
    }
}

// ---------------------------------------------------------------------------
extern "C" void kernel_launch(void* const* d_in, const int* in_sizes, int n_in,
                              void* d_out, int out_size)
{
    const float* x     = (const float*)d_in[0];
    const float* ve    = (const float*)d_in[1];
    const float* cosb  = (const float*)d_in[2];
    const float* sinb  = (const float*)d_in[3];
    const float* Wq    = (const float*)d_in[5];
    const float* Wk    = (const float*)d_in[6];
    const float* Wv    = (const float*)d_in[7];
    const float* Wproj = (const float*)d_in[8];
    const float* Wgate = (const float*)d_in[9];
    float* out = (float*)d_out;

    __nv_bfloat16 *Xhi, *Xlo, *Whi, *Wlo, *Phi, *Plo, *Yhi, *Ylo;
    float *Yf;
    cudaGetSymbolAddress((void**)&Xhi, g_Xhi); cudaGetSymbolAddress((void**)&Xlo, g_Xlo);
    cudaGetSymbolAddress((void**)&Whi, g_Whi); cudaGetSymbolAddress((void**)&Wlo, g_Wlo);
    cudaGetSymbolAddress((void**)&Phi, g_Phi); cudaGetSymbolAddress((void**)&Plo, g_Plo);
    cudaGetSymbolAddress((void**)&Yhi, g_Yhi); cudaGetSymbolAddress((void**)&Ylo, g_Ylo);
    cudaGetSymbolAddress((void**)&Yf, g_Y);

    // Split inputs to bf16 hi/lo
    split_bf16<<<(TOKENS*EE/4 + 255)/256, 256>>>(x, Xhi, Xlo, TOKENS*EE/4);
    split_bf16<<<(1024*EE/4 + 255)/256, 256>>>(Wq, Whi, Wlo, 1024*EE/4);
    split_bf16<<<(256*EE/4 + 255)/256, 256>>>(Wk, Whi + (size_t)1024*EE, Wlo + (size_t)1024*EE, 256*EE/4);
    split_bf16<<<(256*EE/4 + 255)/256, 256>>>(Wv, Whi + (size_t)1280*EE, Wlo + (size_t)1280*EE, 256*EE/4);
    split_bf16<<<(EE*EE/4 + 255)/256, 256>>>(Wproj, Phi, Plo, EE*EE/4);

    dim3 g1(12, 32);
    qkv_gemm_mma<<<g1, 256>>>();

    postproc<<<TOKENS, 128>>>(x, ve, cosb, sinb, Wgate);

    dim3 g3(SS / 128, NH, BB);
    attn_kernel<<<g3, 128>>>();

    split_bf16<<<(TOKENS*EE/4 + 255)/256, 256>>>(Yf, Yhi, Ylo, TOKENS*EE/4);

    dim3 g4(8, 32);
    proj_gemm_mma<<<g4, 256>>>(out);
}

// round 5
// speedup vs baseline: 5.4991x; 2.3490x over previous
#include <cuda_runtime.h>
#include <cuda_bf16.h>
#include <cstdint>

#define BB 2
#define SS 2048
#define EE 1024
#define NH 16
#define NKV 4
#define HD 64
#define TOKENS (BB*SS)

__device__ float g_Q[TOKENS * NH * HD];
__device__ float g_K[TOKENS * NKV * HD];
__device__ float g_V[TOKENS * NKV * HD];
__device__ float g_Y[TOKENS * NH * HD];

// bf16 hi/lo split copies
__device__ __nv_bfloat16 g_Xhi[TOKENS * EE],  g_Xlo[TOKENS * EE];
__device__ __nv_bfloat16 g_Whi[1536 * EE],    g_Wlo[1536 * EE];
__device__ __nv_bfloat16 g_Phi[EE * EE],      g_Plo[EE * EE];
__device__ __nv_bfloat16 g_Yhi[TOKENS * EE],  g_Ylo[TOKENS * EE];
__device__ __nv_bfloat16 g_Qhi[TOKENS * NH * HD],  g_Qlo[TOKENS * NH * HD];
__device__ __nv_bfloat16 g_Khi[TOKENS * NKV * HD], g_Klo[TOKENS * NKV * HD];
__device__ __nv_bfloat16 g_Vhi[TOKENS * NKV * HD], g_Vlo[TOKENS * NKV * HD];

// ---- MMA helpers (baseline PTX only) ----
__device__ __forceinline__ uint32_t smem_u32(const void* p) {
    uint32_t a;
    asm("{ .reg .u64 t; cvta.to.shared.u64 t, %1; cvt.u32.u64 %0, t; }" : "=r"(a) : "l"(p));
    return a;
}
__device__ __forceinline__ void ldsm4(uint32_t r[4], uint32_t a) {
    asm volatile("ldmatrix.sync.aligned.m8n8.x4.shared.b16 {%0,%1,%2,%3}, [%4];"
        : "=r"(r[0]), "=r"(r[1]), "=r"(r[2]), "=r"(r[3]) : "r"(a));
}
__device__ __forceinline__ void ldsm2(uint32_t r[2], uint32_t a) {
    asm volatile("ldmatrix.sync.aligned.m8n8.x2.shared.b16 {%0,%1}, [%2];"
        : "=r"(r[0]), "=r"(r[1]) : "r"(a));
}
__device__ __forceinline__ void ldsm2t(uint32_t r[2], uint32_t a) {
    asm volatile("ldmatrix.sync.aligned.m8n8.x2.trans.shared.b16 {%0,%1}, [%2];"
        : "=r"(r[0]), "=r"(r[1]) : "r"(a));
}
__device__ __forceinline__ void mma16816(float d[4], const uint32_t a[4], const uint32_t b[2]) {
    asm volatile("mma.sync.aligned.m16n8k16.row.col.f32.bf16.bf16.f32 "
        "{%0,%1,%2,%3}, {%4,%5,%6,%7}, {%8,%9}, {%0,%1,%2,%3};"
        : "+f"(d[0]), "+f"(d[1]), "+f"(d[2]), "+f"(d[3])
        : "r"(a[0]), "r"(a[1]), "r"(a[2]), "r"(a[3]), "r"(b[0]), "r"(b[1]));
}
// pack {lo=e, hi=o} bf16x2
__device__ __forceinline__ uint32_t packbf(float e, float o) {
    uint32_t r; asm("cvt.rn.bf16x2.f32 %0, %1, %2;" : "=r"(r) : "f"(o), "f"(e)); return r;
}

// ---------------------------------------------------------------------------
__global__ __launch_bounds__(256) void split_bf16(
    const float* __restrict__ src, __nv_bfloat16* __restrict__ hi,
    __nv_bfloat16* __restrict__ lo, int n4)
{
    int i = blockIdx.x * 256 + threadIdx.x;
    if (i >= n4) return;
    float4 v = *(const float4*)(src + (size_t)i * 4);
    float f[4] = {v.x, v.y, v.z, v.w};
    __nv_bfloat16 h[4], l[4];
    #pragma unroll
    for (int e = 0; e < 4; e++) {
        h[e] = __float2bfloat16(f[e]);
        l[e] = __float2bfloat16(f[e] - __bfloat162float(h[e]));
    }
    *(uint2*)(hi + (size_t)i * 4) = *(uint2*)h;
    *(uint2*)(lo + (size_t)i * 4) = *(uint2*)l;
}

// ---------------------------------------------------------------------------
// HMMA GEMM: C[128,128] block of A[M,1024] @ B[N,1024]^T via bf16 split.
// ---------------------------------------------------------------------------
__device__ __forceinline__ void mma_gemm(
    const __nv_bfloat16* __restrict__ Ahi, const __nv_bfloat16* __restrict__ Alo,
    const __nv_bfloat16* __restrict__ Bhi, const __nv_bfloat16* __restrict__ Blo,
    float* __restrict__ Cb, int ldc, int m0)
{
    __shared__ __align__(16) __nv_bfloat16 Ah_s[128][40];
    __shared__ __align__(16) __nv_bfloat16 Al_s[128][40];
    __shared__ __align__(16) __nv_bfloat16 Bh_s[128][40];
    __shared__ __align__(16) __nv_bfloat16 Bl_s[128][40];

    int t = threadIdx.x;
    int wid = t >> 5, lane = t & 31;
    int wr = wid >> 2, wc = wid & 3;

    uint32_t aAh = smem_u32(Ah_s), aAl = smem_u32(Al_s);
    uint32_t aBh = smem_u32(Bh_s), aBl = smem_u32(Bl_s);

    float acc[4][4][4];
    #pragma unroll
    for (int mt = 0; mt < 4; mt++)
        #pragma unroll
        for (int nt = 0; nt < 4; nt++)
            #pragma unroll
            for (int e = 0; e < 4; e++) acc[mt][nt][e] = 0.f;

    for (int k0 = 0; k0 < 1024; k0 += 32) {
        if (k0) __syncthreads();
        #pragma unroll
        for (int i = 0; i < 2; i++) {
            int c = t + i * 256;
            int row = c >> 2, seg = (c & 3) * 8;
            size_t ga = (size_t)(m0 + row) * 1024 + k0 + seg;
            size_t gb = (size_t)row * 1024 + k0 + seg;
            *(uint4*)&Ah_s[row][seg] = *(const uint4*)&Ahi[ga];
            *(uint4*)&Al_s[row][seg] = *(const uint4*)&Alo[ga];
            *(uint4*)&Bh_s[row][seg] = *(const uint4*)&Bhi[gb];
            *(uint4*)&Bl_s[row][seg] = *(const uint4*)&Blo[gb];
        }
        __syncthreads();

        #pragma unroll
        for (int ks = 0; ks < 2; ks++) {
            int kk = ks * 16;
            uint32_t fAh[4][4], fAl[4][4], fBh[4][2], fBl[4][2];
            int arow = lane & 15;
            int acol = kk + (lane >> 4) * 8;
            #pragma unroll
            for (int mt = 0; mt < 4; mt++) {
                uint32_t off = ((wr * 64 + mt * 16 + arow) * 40 + acol) * 2;
                ldsm4(fAh[mt], aAh + off);
                ldsm4(fAl[mt], aAl + off);
            }
            int brow = lane & 7;
            int bcol = kk + (lane & 8);
            #pragma unroll
            for (int nt = 0; nt < 4; nt++) {
                uint32_t off = ((wc * 32 + nt * 8 + brow) * 40 + bcol) * 2;
                ldsm2(fBh[nt], aBh + off);
                ldsm2(fBl[nt], aBl + off);
            }
            #pragma unroll
            for (int mt = 0; mt < 4; mt++)
                #pragma unroll
                for (int nt = 0; nt < 4; nt++) {
                    mma16816(acc[mt][nt], fAh[mt], fBh[nt]);
                    mma16816(acc[mt][nt], fAl[mt], fBh[nt]);
                    mma16816(acc[mt][nt], fAh[mt], fBl[nt]);
                }
        }
    }

    #pragma unroll
    for (int mt = 0; mt < 4; mt++)
        #pragma unroll
        for (int nt = 0; nt < 4; nt++) {
            int r0 = m0 + wr * 64 + mt * 16 + (lane >> 2);
            int c0 = wc * 32 + nt * 8 + (lane & 3) * 2;
            float2 w0; w0.x = acc[mt][nt][0]; w0.y = acc[mt][nt][1];
            float2 w1; w1.x = acc[mt][nt][2]; w1.y = acc[mt][nt][3];
            *(float2*)&Cb[(size_t)r0 * ldc + c0]       = w0;
            *(float2*)&Cb[(size_t)(r0 + 8) * ldc + c0] = w1;
        }
}

__global__ __launch_bounds__(256) void qkv_gemm_mma()
{
    int n0 = blockIdx.x * 128;
    int m0 = blockIdx.y * 128;
    const __nv_bfloat16* Bh = g_Whi + (size_t)n0 * 1024;
    const __nv_bfloat16* Bl = g_Wlo + (size_t)n0 * 1024;
    float* Cb; int ldc;
    if (n0 < 1024)      { Cb = g_Q + n0;          ldc = 1024; }
    else if (n0 < 1280) { Cb = g_K + (n0 - 1024); ldc = 256;  }
    else                { Cb = g_V + (n0 - 1280); ldc = 256;  }
    mma_gemm(g_Xhi, g_Xlo, Bh, Bl, Cb, ldc, m0);
}

__global__ __launch_bounds__(256) void proj_gemm_mma(float* __restrict__ out)
{
    int n0 = blockIdx.x * 128;
    int m0 = blockIdx.y * 128;
    mma_gemm(g_Yhi, g_Ylo, g_Phi + (size_t)n0 * 1024, g_Plo + (size_t)n0 * 1024,
             out + n0, 1024, m0);
}

// ---------------------------------------------------------------------------
// Postprocess: gate+ve into V, RoPE + RMS-norm on Q/K; emit bf16 hi/lo.
// ---------------------------------------------------------------------------
__device__ __forceinline__ void split_store(__nv_bfloat16* hi, __nv_bfloat16* lo,
                                            size_t idx, float v) {
    __nv_bfloat16 h = __float2bfloat16(v);
    hi[idx] = h;
    lo[idx] = __float2bfloat16(v - __bfloat162float(h));
}

__global__ __launch_bounds__(128) void postproc(
    const float* __restrict__ x, const float* __restrict__ ve,
    const float* __restrict__ cosb, const float* __restrict__ sinb,
    const float* __restrict__ Wgate)
{
    int tok = blockIdx.x;
    int s = tok & (SS - 1);
    int t = threadIdx.x;
    int w = t >> 5;
    int lane = t & 31;

    __shared__ float gate[4];
    __shared__ float x12[12];

    if (t < 12) x12[t] = x[(size_t)tok * EE + t];
    __syncthreads();
    if (t < 4) {
        float acc = 0.f;
        #pragma unroll
        for (int c = 0; c < 12; c++) acc += x12[c] * Wgate[t * 12 + c];
        gate[t] = 3.f / (1.f + __expf(-acc));
    }
    __syncthreads();

    for (int i = t; i < 256; i += 128) {
        int hh = i >> 6;
        float v = g_V[(size_t)tok * 256 + i] + gate[hh] * ve[(size_t)tok * 256 + i];
        split_store(g_Vhi, g_Vlo, (size_t)tok * 256 + i, v);
    }

    const float EPS = 1.1920929e-7f;
    float cv = cosb[s * 32 + lane];
    float sv = sinb[s * 32 + lane];

    #pragma unroll
    for (int i = 0; i < 4; i++) {
        int h = w + 4 * i;
        const float* qp = &g_Q[(size_t)tok * 1024 + h * 64];
        float x1 = qp[lane], x2 = qp[lane + 32];
        float r1 =  x1 * cv + x2 * sv;
        float r2 = -x1 * sv + x2 * cv;
        float ss = r1 * r1 + r2 * r2;
        #pragma unroll
        for (int o = 16; o; o >>= 1) ss += __shfl_xor_sync(0xFFFFFFFFu, ss, o);
        float scale = rsqrtf(ss * (1.f / 64.f) + EPS) * 1.2f;
        size_t base = (size_t)tok * 1024 + h * 64;
        split_store(g_Qhi, g_Qlo, base + lane,      r1 * scale);
        split_store(g_Qhi, g_Qlo, base + lane + 32, r2 * scale);
    }
    {
        const float* kp = &g_K[(size_t)tok * 256 + w * 64];
        float x1 = kp[lane], x2 = kp[lane + 32];
        float r1 =  x1 * cv + x2 * sv;
        float r2 = -x1 * sv + x2 * cv;
        float ss = r1 * r1 + r2 * r2;
        #pragma unroll
        for (int o = 16; o; o >>= 1) ss += __shfl_xor_sync(0xFFFFFFFFu, ss, o);
        float scale = rsqrtf(ss * (1.f / 64.f) + EPS) * 1.2f;
        size_t base = (size_t)tok * 256 + w * 64;
        split_store(g_Khi, g_Klo, base + lane,      r1 * scale);
        split_store(g_Khi, g_Klo, base + lane + 32, r2 * scale);
    }
}

// ---------------------------------------------------------------------------
// Flash attention on HMMA. Grid (32, NH, BB), 128 threads = 4 warps.
// CTA: 64 q-rows; warp: 16 q-rows x 64 kv cols per tile. bf16 hi/lo 3-pass
// on both QK^T and PV; fp32 accumulators; online softmax in fragments.
// ---------------------------------------------------------------------------
__global__ __launch_bounds__(128) void attn_mma()
{
    __shared__ __align__(16) __nv_bfloat16 Kh_s[64][72];
    __shared__ __align__(16) __nv_bfloat16 Kl_s[64][72];
    __shared__ __align__(16) __nv_bfloat16 Vh_s[64][72];
    __shared__ __align__(16) __nv_bfloat16 Vl_s[64][72];

    int qb = (int)gridDim.x - 1 - (int)blockIdx.x;   // big blocks first
    int h  = blockIdx.y;
    int b  = blockIdx.z;
    int hkv = h >> 2;
    int t = threadIdx.x;
    int wid = t >> 5, lane = t & 31;
    size_t tok0 = (size_t)b * SS + qb * 64;

    uint32_t aKh = smem_u32(Kh_s), aKl = smem_u32(Kl_s);
    uint32_t aVh = smem_u32(Vh_s), aVl = smem_u32(Vl_s);

    // ---- stage Q tile (hi/lo) into K buffers, build persistent fragments ----
    for (int idx = t; idx < 512; idx += 128) {
        int row = idx >> 3, ch = (idx & 7) * 8;
        size_t g = (tok0 + row) * 1024 + h * 64 + ch;
        *(uint4*)&Kh_s[row][ch] = *(const uint4*)&g_Qhi[g];
        *(uint4*)&Kl_s[row][ch] = *(const uint4*)&g_Qlo[g];
    }
    __syncthreads();

    uint32_t qh[4][4], ql[4][4];
    {
        int arow = wid * 16 + (lane & 15);
        int acol = (lane >> 4) * 8;
        #pragma unroll
        for (int kc = 0; kc < 4; kc++) {
            uint32_t off = (arow * 72 + kc * 16 + acol) * 2;
            ldsm4(qh[kc], aKh + off);
            ldsm4(ql[kc], aKl + off);
        }
    }
    __syncthreads();

    float accO[8][4];
    #pragma unroll
    for (int nt = 0; nt < 8; nt++)
        #pragma unroll
        for (int e = 0; e < 4; e++) accO[nt][e] = 0.f;
    float m0 = -1e30f, m1 = -1e30f, l0 = 0.f, l1 = 0.f;

    for (int kt = 0; kt <= qb; kt++) {
        size_t base = (size_t)b * SS + kt * 64;
        for (int idx = t; idx < 512; idx += 128) {
            int row = idx >> 3, ch = (idx & 7) * 8;
            size_t g = (base + row) * 256 + hkv * 64 + ch;
            *(uint4*)&Kh_s[row][ch] = *(const uint4*)&g_Khi[g];
            *(uint4*)&Kl_s[row][ch] = *(const uint4*)&g_Klo[g];
            *(uint4*)&Vh_s[row][ch] = *(const uint4*)&g_Vhi[g];
            *(uint4*)&Vl_s[row][ch] = *(const uint4*)&g_Vlo[g];
        }
        __syncthreads();

        // ---- scores S = Q K^T (3-pass) ----
        float sacc[8][4];
        #pragma unroll
        for (int nt = 0; nt < 8; nt++)
            #pragma unroll
            for (int e = 0; e < 4; e++) sacc[nt][e] = 0.f;

        #pragma unroll
        for (int kc = 0; kc < 4; kc++) {
            int bcol = kc * 16 + (lane & 8);
            #pragma unroll
            for (int nt = 0; nt < 8; nt++) {
                uint32_t bh[2], bl[2];
                uint32_t off = ((nt * 8 + (lane & 7)) * 72 + bcol) * 2;
                ldsm2(bh, aKh + off);
                ldsm2(bl, aKl + off);
                mma16816(sacc[nt], qh[kc], bh);
                mma16816(sacc[nt], ql[kc], bh);
                mma16816(sacc[nt], qh[kc], bl);
            }
        }

        // scale + causal mask (diagonal tile only)
        #pragma unroll
        for (int nt = 0; nt < 8; nt++)
            #pragma unroll
            for (int e = 0; e < 4; e++) sacc[nt][e] *= 0.125f;
        if (kt == qb) {
            int rloc = wid * 16 + (lane >> 2);
            #pragma unroll
            for (int nt = 0; nt < 8; nt++) {
                int cl = nt * 8 + (lane & 3) * 2;
                if (cl     > rloc)     sacc[nt][0] = -1e30f;
                if (cl + 1 > rloc)     sacc[nt][1] = -1e30f;
                if (cl     > rloc + 8) sacc[nt][2] = -1e30f;
                if (cl + 1 > rloc + 8) sacc[nt][3] = -1e30f;
            }
        }

        // ---- online softmax ----
        float mx0 = -1e30f, mx1 = -1e30f;
        #pragma unroll
        for (int nt = 0; nt < 8; nt++) {
            mx0 = fmaxf(mx0, fmaxf(sacc[nt][0], sacc[nt][1]));
            mx1 = fmaxf(mx1, fmaxf(sacc[nt][2], sacc[nt][3]));
        }
        mx0 = fmaxf(mx0, __shfl_xor_sync(0xFFFFFFFFu, mx0, 1));
        mx0 = fmaxf(mx0, __shfl_xor_sync(0xFFFFFFFFu, mx0, 2));
        mx1 = fmaxf(mx1, __shfl_xor_sync(0xFFFFFFFFu, mx1, 1));
        mx1 = fmaxf(mx1, __shfl_xor_sync(0xFFFFFFFFu, mx1, 2));

        float mn0 = fmaxf(m0, mx0), mn1 = fmaxf(m1, mx1);
        float cr0 = __expf(m0 - mn0), cr1 = __expf(m1 - mn1);
        float rs0 = 0.f, rs1 = 0.f;
        #pragma unroll
        for (int nt = 0; nt < 8; nt++) {
            float p0 = __expf(sacc[nt][0] - mn0);
            float p1 = __expf(sacc[nt][1] - mn0);
            float p2 = __expf(sacc[nt][2] - mn1);
            float p3 = __expf(sacc[nt][3] - mn1);
            sacc[nt][0] = p0; sacc[nt][1] = p1; sacc[nt][2] = p2; sacc[nt][3] = p3;
            rs0 += p0 + p1; rs1 += p2 + p3;
        }
        rs0 += __shfl_xor_sync(0xFFFFFFFFu, rs0, 1);
        rs0 += __shfl_xor_sync(0xFFFFFFFFu, rs0, 2);
        rs1 += __shfl_xor_sync(0xFFFFFFFFu, rs1, 1);
        rs1 += __shfl_xor_sync(0xFFFFFFFFu, rs1, 2);
        l0 = l0 * cr0 + rs0; l1 = l1 * cr1 + rs1;
        m0 = mn0; m1 = mn1;
        #pragma unroll
        for (int nt = 0; nt < 8; nt++) {
            accO[nt][0] *= cr0; accO[nt][1] *= cr0;
            accO[nt][2] *= cr1; accO[nt][3] *= cr1;
        }

        // ---- O += P V (3-pass) ----
        #pragma unroll
        for (int kc = 0; kc < 4; kc++) {
            // P fragments (hi/lo) from S accumulator tiles 2kc, 2kc+1
            uint32_t ph[4], pl[4];
            {
                float p00 = sacc[2*kc][0],   p01 = sacc[2*kc][1];
                float p10 = sacc[2*kc][2],   p11 = sacc[2*kc][3];
                float p20 = sacc[2*kc+1][0], p21 = sacc[2*kc+1][1];
                float p30 = sacc[2*kc+1][2], p31 = sacc[2*kc+1][3];
                ph[0] = packbf(p00, p01); ph[1] = packbf(p10, p11);
                ph[2] = packbf(p20, p21); ph[3] = packbf(p30, p31);
                float h00 = __bfloat162float(__float2bfloat16(p00));
                float h01 = __bfloat162float(__float2bfloat16(p01));
                float h10 = __bfloat162float(__float2bfloat16(p10));
                float h11 = __bfloat162float(__float2bfloat16(p11));
                float h20 = __bfloat162float(__float2bfloat16(p20));
                float h21 = __bfloat162float(__float2bfloat16(p21));
                float h30 = __bfloat162float(__float2bfloat16(p30));
                float h31 = __bfloat162float(__float2bfloat16(p31));
                pl[0] = packbf(p00 - h00, p01 - h01);
                pl[1] = packbf(p10 - h10, p11 - h11);
                pl[2] = packbf(p20 - h20, p21 - h21);
                pl[3] = packbf(p30 - h30, p31 - h31);
            }
            int vrow = kc * 16 + (lane & 15);
            #pragma unroll
            for (int nt = 0; nt < 8; nt++) {
                uint32_t vh[2], vl[2];
                uint32_t off = (vrow * 72 + nt * 8) * 2;
                ldsm2t(vh, aVh + off);
                ldsm2t(vl, aVl + off);
                mma16816(accO[nt], ph, vh);
                mma16816(accO[nt], pl, vh);
                mma16816(accO[nt], ph, vl);
            }
        }
        __syncthreads();
    }

    // ---- epilogue ----
    float inv0 = 1.f / l0, inv1 = 1.f / l1;
    int r0 = wid * 16 + (lane >> 2);
    #pragma unroll
    for (int nt = 0; nt < 8; nt++) {
        int col = h * 64 + nt * 8 + (lane & 3) * 2;
        float2 w0; w0.x = accO[nt][0] * inv0; w0.y = accO[nt][1] * inv0;
        float2 w1; w1.x = accO[nt][2] * inv1; w1.y = accO[nt][3] * inv1;
        *(float2*)&g_Y[(tok0 + r0) * 1024 + col]     = w0;
        *(float2*)&g_Y[(tok0 + r0 + 8) * 1024 + col] = w1;
    }
}

// ---------------------------------------------------------------------------
extern "C" void kernel_launch(void* const* d_in, const int* in_sizes, int n_in,
                              void* d_out, int out_size)
{
    const float* x     = (const float*)d_in[0];
    const float* ve    = (const float*)d_in[1];
    const float* cosb  = (const float*)d_in[2];
    const float* sinb  = (const float*)d_in[3];
    const float* Wq    = (const float*)d_in[5];
    const float* Wk    = (const float*)d_in[6];
    const float* Wv    = (const float*)d_in[7];
    const float* Wproj = (const float*)d_in[8];
    const float* Wgate = (const float*)d_in[9];
    float* out = (float*)d_out;

    __nv_bfloat16 *Xhi, *Xlo, *Whi, *Wlo, *Phi, *Plo, *Yhi, *Ylo;
    float* Yf;
    cudaGetSymbolAddress((void**)&Xhi, g_Xhi); cudaGetSymbolAddress((void**)&Xlo, g_Xlo);
    cudaGetSymbolAddress((void**)&Whi, g_Whi); cudaGetSymbolAddress((void**)&Wlo, g_Wlo);
    cudaGetSymbolAddress((void**)&Phi, g_Phi); cudaGetSymbolAddress((void**)&Plo, g_Plo);
    cudaGetSymbolAddress((void**)&Yhi, g_Yhi); cudaGetSymbolAddress((void**)&Ylo, g_Ylo);
    cudaGetSymbolAddress((void**)&Yf, g_Y);

    split_bf16<<<(TOKENS*EE/4 + 255)/256, 256>>>(x, Xhi, Xlo, TOKENS*EE/4);
    split_bf16<<<(1024*EE/4 + 255)/256, 256>>>(Wq, Whi, Wlo, 1024*EE/4);
    split_bf16<<<(256*EE/4 + 255)/256, 256>>>(Wk, Whi + (size_t)1024*EE, Wlo + (size_t)1024*EE, 256*EE/4);
    split_bf16<<<(256*EE/4 + 255)/256, 256>>>(Wv, Whi + (size_t)1280*EE, Wlo + (size_t)1280*EE, 256*EE/4);
    split_bf16<<<(EE*EE/4 + 255)/256, 256>>>(Wproj, Phi, Plo, EE*EE/4);

    dim3 g1(12, 32);
    qkv_gemm_mma<<<g1, 256>>>();

    postproc<<<TOKENS, 128>>>(x, ve, cosb, sinb, Wgate);

    dim3 g3(32, NH, BB);
    attn_mma<<<g3, 128>>>();

    split_bf16<<<(TOKENS*EE/4 + 255)/256, 256>>>(Yf, Yhi, Ylo, TOKENS*EE/4);

    dim3 g4(8, 32);
    proj_gemm_mma<<<g4, 256>>>(out);
}

// round 6
// speedup vs baseline: 5.6011x; 1.0185x over previous
#include <cuda_runtime.h>
#include <cuda_bf16.h>
#include <cstdint>

#define BB 2
#define SS 2048
#define EE 1024
#define NH 16
#define NKV 4
#define HD 64
#define TOKENS (BB*SS)

__device__ float g_Q[TOKENS * NH * HD];
__device__ float g_K[TOKENS * NKV * HD];
__device__ float g_V[TOKENS * NKV * HD];

__device__ __nv_bfloat16 g_Xhi[TOKENS * EE],  g_Xlo[TOKENS * EE];
__device__ __nv_bfloat16 g_Whi[1536 * EE],    g_Wlo[1536 * EE];
__device__ __nv_bfloat16 g_Phi[EE * EE],      g_Plo[EE * EE];
__device__ __nv_bfloat16 g_Yhi[TOKENS * EE],  g_Ylo[TOKENS * EE];
__device__ __nv_bfloat16 g_Qhi[TOKENS * NH * HD],  g_Qlo[TOKENS * NH * HD];
__device__ __nv_bfloat16 g_Khi[TOKENS * NKV * HD], g_Klo[TOKENS * NKV * HD];
__device__ __nv_bfloat16 g_Vhi[TOKENS * NKV * HD], g_Vlo[TOKENS * NKV * HD];

// ---- PTX helpers (baseline features only) ----
__device__ __forceinline__ uint32_t smem_u32(const void* p) {
    uint32_t a;
    asm("{ .reg .u64 t; cvta.to.shared.u64 t, %1; cvt.u32.u64 %0, t; }" : "=r"(a) : "l"(p));
    return a;
}
__device__ __forceinline__ void ldsm4(uint32_t r[4], uint32_t a) {
    asm volatile("ldmatrix.sync.aligned.m8n8.x4.shared.b16 {%0,%1,%2,%3}, [%4];"
        : "=r"(r[0]), "=r"(r[1]), "=r"(r[2]), "=r"(r[3]) : "r"(a));
}
__device__ __forceinline__ void ldsm2(uint32_t r[2], uint32_t a) {
    asm volatile("ldmatrix.sync.aligned.m8n8.x2.shared.b16 {%0,%1}, [%2];"
        : "=r"(r[0]), "=r"(r[1]) : "r"(a));
}
__device__ __forceinline__ void ldsm2t(uint32_t r[2], uint32_t a) {
    asm volatile("ldmatrix.sync.aligned.m8n8.x2.trans.shared.b16 {%0,%1}, [%2];"
        : "=r"(r[0]), "=r"(r[1]) : "r"(a));
}
__device__ __forceinline__ void mma16816(float d[4], const uint32_t a[4], const uint32_t b[2]) {
    asm volatile("mma.sync.aligned.m16n8k16.row.col.f32.bf16.bf16.f32 "
        "{%0,%1,%2,%3}, {%4,%5,%6,%7}, {%8,%9}, {%0,%1,%2,%3};"
        : "+f"(d[0]), "+f"(d[1]), "+f"(d[2]), "+f"(d[3])
        : "r"(a[0]), "r"(a[1]), "r"(a[2]), "r"(a[3]), "r"(b[0]), "r"(b[1]));
}
__device__ __forceinline__ uint32_t packbf(float e, float o) {
    uint32_t r; asm("cvt.rn.bf16x2.f32 %0, %1, %2;" : "=r"(r) : "f"(o), "f"(e)); return r;
}
__device__ __forceinline__ void cpa16(uint32_t dst, const void* src) {
    asm volatile("cp.async.cg.shared.global [%0], [%1], 16;" :: "r"(dst), "l"(src));
}
#define CP_COMMIT() asm volatile("cp.async.commit_group;" ::: "memory")
#define CP_WAIT(n)  asm volatile("cp.async.wait_group %0;" :: "n"(n) : "memory")

// ---------------------------------------------------------------------------
__global__ __launch_bounds__(256) void split_bf16(
    const float* __restrict__ src, __nv_bfloat16* __restrict__ hi,
    __nv_bfloat16* __restrict__ lo, int n4)
{
    int i = blockIdx.x * 256 + threadIdx.x;
    if (i >= n4) return;
    float4 v = *(const float4*)(src + (size_t)i * 4);
    float f[4] = {v.x, v.y, v.z, v.w};
    __nv_bfloat16 h[4], l[4];
    #pragma unroll
    for (int e = 0; e < 4; e++) {
        h[e] = __float2bfloat16(f[e]);
        l[e] = __float2bfloat16(f[e] - __bfloat162float(h[e]));
    }
    *(uint2*)(hi + (size_t)i * 4) = *(uint2*)h;
    *(uint2*)(lo + (size_t)i * 4) = *(uint2*)l;
}

// One launch for all weight splits: Wq, Wk, Wv -> g_Whi/Wlo; Wproj -> g_Phi/Plo
__global__ __launch_bounds__(256) void split_weights(
    const float* __restrict__ Wq, const float* __restrict__ Wk,
    const float* __restrict__ Wv, const float* __restrict__ Wp)
{
    int i = blockIdx.x * 256 + threadIdx.x;   // 4-element chunks
    const float* src; __nv_bfloat16 *hi, *lo; size_t off;
    if (i < 262144)      { src = Wq; hi = g_Whi; lo = g_Wlo; off = (size_t)i; }
    else if (i < 327680) { src = Wk; hi = g_Whi; lo = g_Wlo; off = (size_t)(i - 262144) + 262144; src = Wk; }
    else if (i < 393216) { src = Wv; hi = g_Whi; lo = g_Wlo; off = (size_t)(i - 327680) + 327680; }
    else if (i < 655360) { src = Wp; hi = g_Phi; lo = g_Plo; off = (size_t)(i - 393216); }
    else return;
    size_t s4;
    if (i < 262144)      s4 = (size_t)i;
    else if (i < 327680) s4 = (size_t)(i - 262144);
    else if (i < 393216) s4 = (size_t)(i - 327680);
    else                 s4 = (size_t)(i - 393216);
    float4 v = *(const float4*)(src + s4 * 4);
    float f[4] = {v.x, v.y, v.z, v.w};
    __nv_bfloat16 h[4], l[4];
    #pragma unroll
    for (int e = 0; e < 4; e++) {
        h[e] = __float2bfloat16(f[e]);
        l[e] = __float2bfloat16(f[e] - __bfloat162float(h[e]));
    }
    *(uint2*)(hi + off * 4) = *(uint2*)h;
    *(uint2*)(lo + off * 4) = *(uint2*)l;
}

// ---------------------------------------------------------------------------
// HMMA GEMM, cp.async 2-stage pipeline. C[128,128] of A[M,1024] @ B[N,1024]^T.
// Dyn smem: 2 stages x 4 arrays (Ah,Al,Bh,Bl) x [128][40] bf16 = 80 KB.
// ---------------------------------------------------------------------------
#define G_AR   10240                 // 128*40*2 bytes per array
#define G_STG  (4 * G_AR)            // per stage
#define G_SMEM (2 * G_STG)

__device__ __forceinline__ void mma_gemm(
    const __nv_bfloat16* __restrict__ Ahi, const __nv_bfloat16* __restrict__ Alo,
    const __nv_bfloat16* __restrict__ Bhi, const __nv_bfloat16* __restrict__ Blo,
    float* __restrict__ Cb, int ldc, int m0)
{
    extern __shared__ char smdyn[];
    uint32_t sb0 = smem_u32(smdyn);

    int t = threadIdx.x;
    int wid = t >> 5, lane = t & 31;
    int wr = wid >> 2, wc = wid & 3;

    const __nv_bfloat16* srcs[4] = {
        Ahi + (size_t)m0 * 1024, Alo + (size_t)m0 * 1024, Bhi, Blo };

    float acc[4][4][4];
    #pragma unroll
    for (int mt = 0; mt < 4; mt++)
        #pragma unroll
        for (int nt = 0; nt < 4; nt++)
            #pragma unroll
            for (int e = 0; e < 4; e++) acc[mt][nt][e] = 0.f;

    // prologue load, stage 0
    {
        uint32_t base = sb0;
        #pragma unroll
        for (int i = 0; i < 8; i++) {
            int c = t + i * 256;
            int arr = c >> 9, cc = c & 511, row = cc >> 2, seg = (cc & 3) * 8;
            cpa16(base + (uint32_t)(arr * G_AR + row * 80 + seg * 2),
                  srcs[arr] + (size_t)row * 1024 + seg);
        }
        CP_COMMIT();
    }

    for (int it = 0; it < 32; it++) {
        if (it + 1 < 32) {
            uint32_t base = sb0 + ((it + 1) & 1) * G_STG;
            int k0 = (it + 1) * 32;
            #pragma unroll
            for (int i = 0; i < 8; i++) {
                int c = t + i * 256;
                int arr = c >> 9, cc = c & 511, row = cc >> 2, seg = (cc & 3) * 8;
                cpa16(base + (uint32_t)(arr * G_AR + row * 80 + seg * 2),
                      srcs[arr] + (size_t)row * 1024 + k0 + seg);
            }
            CP_COMMIT();
            CP_WAIT(1);
        } else {
            CP_WAIT(0);
        }
        __syncthreads();

        uint32_t sb = sb0 + (it & 1) * G_STG;
        uint32_t aAh = sb, aAl = sb + G_AR, aBh = sb + 2 * G_AR, aBl = sb + 3 * G_AR;

        #pragma unroll
        for (int ks = 0; ks < 2; ks++) {
            int kk = ks * 16;
            uint32_t fAh[4][4], fAl[4][4], fBh[4][2], fBl[4][2];
            int arow = lane & 15;
            int acol = kk + (lane >> 4) * 8;
            #pragma unroll
            for (int mt = 0; mt < 4; mt++) {
                uint32_t off = (uint32_t)((wr * 64 + mt * 16 + arow) * 80 + acol * 2);
                ldsm4(fAh[mt], aAh + off);
                ldsm4(fAl[mt], aAl + off);
            }
            int brow = lane & 7;
            int bcol = kk + (lane & 8);
            #pragma unroll
            for (int nt = 0; nt < 4; nt++) {
                uint32_t off = (uint32_t)((wc * 32 + nt * 8 + brow) * 80 + bcol * 2);
                ldsm2(fBh[nt], aBh + off);
                ldsm2(fBl[nt], aBl + off);
            }
            #pragma unroll
            for (int mt = 0; mt < 4; mt++)
                #pragma unroll
                for (int nt = 0; nt < 4; nt++) {
                    mma16816(acc[mt][nt], fAh[mt], fBh[nt]);
                    mma16816(acc[mt][nt], fAl[mt], fBh[nt]);
                    mma16816(acc[mt][nt], fAh[mt], fBl[nt]);
                }
        }
        __syncthreads();
    }

    #pragma unroll
    for (int mt = 0; mt < 4; mt++)
        #pragma unroll
        for (int nt = 0; nt < 4; nt++) {
            int r0 = m0 + wr * 64 + mt * 16 + (lane >> 2);
            int c0 = wc * 32 + nt * 8 + (lane & 3) * 2;
            float2 w0; w0.x = acc[mt][nt][0]; w0.y = acc[mt][nt][1];
            float2 w1; w1.x = acc[mt][nt][2]; w1.y = acc[mt][nt][3];
            *(float2*)&Cb[(size_t)r0 * ldc + c0]       = w0;
            *(float2*)&Cb[(size_t)(r0 + 8) * ldc + c0] = w1;
        }
}

__global__ __launch_bounds__(256) void qkv_gemm_mma()
{
    int n0 = blockIdx.x * 128;
    int m0 = blockIdx.y * 128;
    const __nv_bfloat16* Bh = g_Whi + (size_t)n0 * 1024;
    const __nv_bfloat16* Bl = g_Wlo + (size_t)n0 * 1024;
    float* Cb; int ldc;
    if (n0 < 1024)      { Cb = g_Q + n0;          ldc = 1024; }
    else if (n0 < 1280) { Cb = g_K + (n0 - 1024); ldc = 256;  }
    else                { Cb = g_V + (n0 - 1280); ldc = 256;  }
    mma_gemm(g_Xhi, g_Xlo, Bh, Bl, Cb, ldc, m0);
}

__global__ __launch_bounds__(256) void proj_gemm_mma(float* __restrict__ out)
{
    int n0 = blockIdx.x * 128;
    int m0 = blockIdx.y * 128;
    mma_gemm(g_Yhi, g_Ylo, g_Phi + (size_t)n0 * 1024, g_Plo + (size_t)n0 * 1024,
             out + n0, 1024, m0);
}

// ---------------------------------------------------------------------------
__device__ __forceinline__ void split_store(__nv_bfloat16* hi, __nv_bfloat16* lo,
                                            size_t idx, float v) {
    __nv_bfloat16 h = __float2bfloat16(v);
    hi[idx] = h;
    lo[idx] = __float2bfloat16(v - __bfloat162float(h));
}

__global__ __launch_bounds__(128) void postproc(
    const float* __restrict__ x, const float* __restrict__ ve,
    const float* __restrict__ cosb, const float* __restrict__ sinb,
    const float* __restrict__ Wgate)
{
    int tok = blockIdx.x;
    int s = tok & (SS - 1);
    int t = threadIdx.x;
    int w = t >> 5;
    int lane = t & 31;

    __shared__ float gate[4];
    __shared__ float x12[12];

    if (t < 12) x12[t] = x[(size_t)tok * EE + t];
    __syncthreads();
    if (t < 4) {
        float acc = 0.f;
        #pragma unroll
        for (int c = 0; c < 12; c++) acc += x12[c] * Wgate[t * 12 + c];
        gate[t] = 3.f / (1.f + __expf(-acc));
    }
    __syncthreads();

    for (int i = t; i < 256; i += 128) {
        int hh = i >> 6;
        float v = g_V[(size_t)tok * 256 + i] + gate[hh] * ve[(size_t)tok * 256 + i];
        split_store(g_Vhi, g_Vlo, (size_t)tok * 256 + i, v);
    }

    const float EPS = 1.1920929e-7f;
    float cv = cosb[s * 32 + lane];
    float sv = sinb[s * 32 + lane];

    #pragma unroll
    for (int i = 0; i < 4; i++) {
        int h = w + 4 * i;
        const float* qp = &g_Q[(size_t)tok * 1024 + h * 64];
        float x1 = qp[lane], x2 = qp[lane + 32];
        float r1 =  x1 * cv + x2 * sv;
        float r2 = -x1 * sv + x2 * cv;
        float ss = r1 * r1 + r2 * r2;
        #pragma unroll
        for (int o = 16; o; o >>= 1) ss += __shfl_xor_sync(0xFFFFFFFFu, ss, o);
        float scale = rsqrtf(ss * (1.f / 64.f) + EPS) * 1.2f;
        size_t base = (size_t)tok * 1024 + h * 64;
        split_store(g_Qhi, g_Qlo, base + lane,      r1 * scale);
        split_store(g_Qhi, g_Qlo, base + lane + 32, r2 * scale);
    }
    {
        const float* kp = &g_K[(size_t)tok * 256 + w * 64];
        float x1 = kp[lane], x2 = kp[lane + 32];
        float r1 =  x1 * cv + x2 * sv;
        float r2 = -x1 * sv + x2 * cv;
        float ss = r1 * r1 + r2 * r2;
        #pragma unroll
        for (int o = 16; o; o >>= 1) ss += __shfl_xor_sync(0xFFFFFFFFu, ss, o);
        float scale = rsqrtf(ss * (1.f / 64.f) + EPS) * 1.2f;
        size_t base = (size_t)tok * 256 + w * 64;
        split_store(g_Khi, g_Klo, base + lane,      r1 * scale);
        split_store(g_Khi, g_Klo, base + lane + 32, r2 * scale);
    }
}

// ---------------------------------------------------------------------------
// Flash attention on HMMA, cp.async 2-stage K/V pipeline.
// Grid (32, NH, BB), 128 threads. Dyn smem: 2 x 4 x [64][72] bf16 = 72 KB.
// Epilogue writes bf16 hi/lo Y directly.
// ---------------------------------------------------------------------------
#define A_AR   9216                  // 64*72*2 bytes per array
#define A_STG  (4 * A_AR)
#define A_SMEM (2 * A_STG)

__global__ __launch_bounds__(128) void attn_mma()
{
    extern __shared__ char smdyn[];
    uint32_t sb0 = smem_u32(smdyn);

    int qb = (int)gridDim.x - 1 - (int)blockIdx.x;
    int h  = blockIdx.y;
    int b  = blockIdx.z;
    int hkv = h >> 2;
    int t = threadIdx.x;
    int wid = t >> 5, lane = t & 31;
    size_t tok0 = (size_t)b * SS + qb * 64;

    // ---- stage Q tile into stage-0 Kh/Kl arrays, build persistent fragments ----
    for (int idx = t; idx < 512; idx += 128) {
        int row = idx >> 3, ch = (idx & 7) * 8;
        size_t g = (tok0 + row) * 1024 + h * 64 + ch;
        *(uint4*)(smdyn + row * 144 + ch * 2)        = *(const uint4*)&g_Qhi[g];
        *(uint4*)(smdyn + A_AR + row * 144 + ch * 2) = *(const uint4*)&g_Qlo[g];
    }
    __syncthreads();

    uint32_t qh[4][4], ql[4][4];
    {
        int arow = wid * 16 + (lane & 15);
        int acol = (lane >> 4) * 8;
        #pragma unroll
        for (int kc = 0; kc < 4; kc++) {
            uint32_t off = (uint32_t)(arow * 144 + (kc * 16 + acol) * 2);
            ldsm4(qh[kc], sb0 + off);
            ldsm4(ql[kc], sb0 + A_AR + off);
        }
    }
    __syncthreads();

    const __nv_bfloat16* srcs[4] = { g_Khi, g_Klo, g_Vhi, g_Vlo };

    float accO[8][4];
    #pragma unroll
    for (int nt = 0; nt < 8; nt++)
        #pragma unroll
        for (int e = 0; e < 4; e++) accO[nt][e] = 0.f;
    float m0 = -1e30f, m1 = -1e30f, l0 = 0.f, l1 = 0.f;

    // prologue: load kt=0 into stage 0
    {
        size_t base = (size_t)b * SS;
        #pragma unroll
        for (int i = 0; i < 16; i++) {
            int c = t + i * 128;
            int arr = c >> 9, cc = c & 511, row = cc >> 3, seg = (cc & 7) * 8;
            cpa16(sb0 + (uint32_t)(arr * A_AR + row * 144 + seg * 2),
                  srcs[arr] + (base + row) * 256 + hkv * 64 + seg);
        }
        CP_COMMIT();
    }

    for (int kt = 0; kt <= qb; kt++) {
        if (kt + 1 <= qb) {
            uint32_t sbl = sb0 + ((kt + 1) & 1) * A_STG;
            size_t base = (size_t)b * SS + (kt + 1) * 64;
            #pragma unroll
            for (int i = 0; i < 16; i++) {
                int c = t + i * 128;
                int arr = c >> 9, cc = c & 511, row = cc >> 3, seg = (cc & 7) * 8;
                cpa16(sbl + (uint32_t)(arr * A_AR + row * 144 + seg * 2),
                      srcs[arr] + (base + row) * 256 + hkv * 64 + seg);
            }
            CP_COMMIT();
            CP_WAIT(1);
        } else {
            CP_WAIT(0);
        }
        __syncthreads();

        uint32_t sb = sb0 + (kt & 1) * A_STG;
        uint32_t aKh = sb, aKl = sb + A_AR, aVh = sb + 2 * A_AR, aVl = sb + 3 * A_AR;

        // ---- S = Q K^T (3-pass) ----
        float sacc[8][4];
        #pragma unroll
        for (int nt = 0; nt < 8; nt++)
            #pragma unroll
            for (int e = 0; e < 4; e++) sacc[nt][e] = 0.f;

        #pragma unroll
        for (int kc = 0; kc < 4; kc++) {
            int bcol = kc * 16 + (lane & 8);
            #pragma unroll
            for (int nt = 0; nt < 8; nt++) {
                uint32_t bh[2], bl[2];
                uint32_t off = (uint32_t)((nt * 8 + (lane & 7)) * 144 + bcol * 2);
                ldsm2(bh, aKh + off);
                ldsm2(bl, aKl + off);
                mma16816(sacc[nt], qh[kc], bh);
                mma16816(sacc[nt], ql[kc], bh);
                mma16816(sacc[nt], qh[kc], bl);
            }
        }

        #pragma unroll
        for (int nt = 0; nt < 8; nt++)
            #pragma unroll
            for (int e = 0; e < 4; e++) sacc[nt][e] *= 0.125f;
        if (kt == qb) {
            int rloc = wid * 16 + (lane >> 2);
            #pragma unroll
            for (int nt = 0; nt < 8; nt++) {
                int cl = nt * 8 + (lane & 3) * 2;
                if (cl     > rloc)     sacc[nt][0] = -1e30f;
                if (cl + 1 > rloc)     sacc[nt][1] = -1e30f;
                if (cl     > rloc + 8) sacc[nt][2] = -1e30f;
                if (cl + 1 > rloc + 8) sacc[nt][3] = -1e30f;
            }
        }

        // ---- online softmax ----
        float mx0 = -1e30f, mx1 = -1e30f;
        #pragma unroll
        for (int nt = 0; nt < 8; nt++) {
            mx0 = fmaxf(mx0, fmaxf(sacc[nt][0], sacc[nt][1]));
            mx1 = fmaxf(mx1, fmaxf(sacc[nt][2], sacc[nt][3]));
        }
        mx0 = fmaxf(mx0, __shfl_xor_sync(0xFFFFFFFFu, mx0, 1));
        mx0 = fmaxf(mx0, __shfl_xor_sync(0xFFFFFFFFu, mx0, 2));
        mx1 = fmaxf(mx1, __shfl_xor_sync(0xFFFFFFFFu, mx1, 1));
        mx1 = fmaxf(mx1, __shfl_xor_sync(0xFFFFFFFFu, mx1, 2));

        float mn0 = fmaxf(m0, mx0), mn1 = fmaxf(m1, mx1);
        float cr0 = __expf(m0 - mn0), cr1 = __expf(m1 - mn1);
        float rs0 = 0.f, rs1 = 0.f;
        #pragma unroll
        for (int nt = 0; nt < 8; nt++) {
            float p0 = __expf(sacc[nt][0] - mn0);
            float p1 = __expf(sacc[nt][1] - mn0);
            float p2 = __expf(sacc[nt][2] - mn1);
            float p3 = __expf(sacc[nt][3] - mn1);
            sacc[nt][0] = p0; sacc[nt][1] = p1; sacc[nt][2] = p2; sacc[nt][3] = p3;
            rs0 += p0 + p1; rs1 += p2 + p3;
        }
        rs0 += __shfl_xor_sync(0xFFFFFFFFu, rs0, 1);
        rs0 += __shfl_xor_sync(0xFFFFFFFFu, rs0, 2);
        rs1 += __shfl_xor_sync(0xFFFFFFFFu, rs1, 1);
        rs1 += __shfl_xor_sync(0xFFFFFFFFu, rs1, 2);
        l0 = l0 * cr0 + rs0; l1 = l1 * cr1 + rs1;
        m0 = mn0; m1 = mn1;
        #pragma unroll
        for (int nt = 0; nt < 8; nt++) {
            accO[nt][0] *= cr0; accO[nt][1] *= cr0;
            accO[nt][2] *= cr1; accO[nt][3] *= cr1;
        }

        // ---- O += P V (3-pass) ----
        #pragma unroll
        for (int kc = 0; kc < 4; kc++) {
            uint32_t ph[4], pl[4];
            {
                float p00 = sacc[2*kc][0],   p01 = sacc[2*kc][1];
                float p10 = sacc[2*kc][2],   p11 = sacc[2*kc][3];
                float p20 = sacc[2*kc+1][0], p21 = sacc[2*kc+1][1];
                float p30 = sacc[2*kc+1][2], p31 = sacc[2*kc+1][3];
                ph[0] = packbf(p00, p01); ph[1] = packbf(p10, p11);
                ph[2] = packbf(p20, p21); ph[3] = packbf(p30, p31);
                float h00 = __bfloat162float(__float2bfloat16(p00));
                float h01 = __bfloat162float(__float2bfloat16(p01));
                float h10 = __bfloat162float(__float2bfloat16(p10));
                float h11 = __bfloat162float(__float2bfloat16(p11));
                float h20 = __bfloat162float(__float2bfloat16(p20));
                float h21 = __bfloat162float(__float2bfloat16(p21));
                float h30 = __bfloat162float(__float2bfloat16(p30));
                float h31 = __bfloat162float(__float2bfloat16(p31));
                pl[0] = packbf(p00 - h00, p01 - h01);
                pl[1] = packbf(p10 - h10, p11 - h11);
                pl[2] = packbf(p20 - h20, p21 - h21);
                pl[3] = packbf(p30 - h30, p31 - h31);
            }
            int vrow = kc * 16 + (lane & 15);
            #pragma unroll
            for (int nt = 0; nt < 8; nt++) {
                uint32_t vh[2], vl[2];
                uint32_t off = (uint32_t)(vrow * 144 + nt * 16);
                ldsm2t(vh, aVh + off);
                ldsm2t(vl, aVl + off);
                mma16816(accO[nt], ph, vh);
                mma16816(accO[nt], pl, vh);
                mma16816(accO[nt], ph, vl);
            }
        }
        __syncthreads();
    }

    // ---- epilogue: write Yhi/Ylo directly (fused split) ----
    float inv0 = 1.f / l0, inv1 = 1.f / l1;
    int r0 = wid * 16 + (lane >> 2);
    #pragma unroll
    for (int nt = 0; nt < 8; nt++) {
        int col = h * 64 + nt * 8 + (lane & 3) * 2;
        float v00 = accO[nt][0] * inv0, v01 = accO[nt][1] * inv0;
        float v10 = accO[nt][2] * inv1, v11 = accO[nt][3] * inv1;
        float h00 = __bfloat162float(__float2bfloat16(v00));
        float h01 = __bfloat162float(__float2bfloat16(v01));
        float h10 = __bfloat162float(__float2bfloat16(v10));
        float h11 = __bfloat162float(__float2bfloat16(v11));
        size_t i0 = (tok0 + r0) * 1024 + col;
        size_t i1 = (tok0 + r0 + 8) * 1024 + col;
        *(uint32_t*)&g_Yhi[i0] = packbf(v00, v01);
        *(uint32_t*)&g_Ylo[i0] = packbf(v00 - h00, v01 - h01);
        *(uint32_t*)&g_Yhi[i1] = packbf(v10, v11);
        *(uint32_t*)&g_Ylo[i1] = packbf(v10 - h10, v11 - h11);
    }
}

// ---------------------------------------------------------------------------
extern "C" void kernel_launch(void* const* d_in, const int* in_sizes, int n_in,
                              void* d_out, int out_size)
{
    const float* x     = (const float*)d_in[0];
    const float* ve    = (const float*)d_in[1];
    const float* cosb  = (const float*)d_in[2];
    const float* sinb  = (const float*)d_in[3];
    const float* Wq    = (const float*)d_in[5];
    const float* Wk    = (const float*)d_in[6];
    const float* Wv    = (const float*)d_in[7];
    const float* Wproj = (const float*)d_in[8];
    const float* Wgate = (const float*)d_in[9];
    float* out = (float*)d_out;

    __nv_bfloat16 *Xhi, *Xlo;
    cudaGetSymbolAddress((void**)&Xhi, g_Xhi);
    cudaGetSymbolAddress((void**)&Xlo, g_Xlo);

    static bool attr_set = false;
    if (!attr_set) {
        cudaFuncSetAttribute(qkv_gemm_mma, cudaFuncAttributeMaxDynamicSharedMemorySize, G_SMEM);
        cudaFuncSetAttribute(proj_gemm_mma, cudaFuncAttributeMaxDynamicSharedMemorySize, G_SMEM);
        cudaFuncSetAttribute(attn_mma, cudaFuncAttributeMaxDynamicSharedMemorySize, A_SMEM);
        attr_set = true;
    }

    split_bf16<<<(TOKENS*EE/4 + 255)/256, 256>>>(x, Xhi, Xlo, TOKENS*EE/4);
    split_weights<<<(655360 + 255)/256, 256>>>(Wq, Wk, Wv, Wproj);

    dim3 g1(12, 32);
    qkv_gemm_mma<<<g1, 256, G_SMEM>>>();

    postproc<<<TOKENS, 128>>>(x, ve, cosb, sinb, Wgate);

    dim3 g3(32, NH, BB);
    attn_mma<<<g3, 128, A_SMEM>>>();

    dim3 g4(8, 32);
    proj_gemm_mma<<<g4, 256, G_SMEM>>>(out);
}

// round 7
// speedup vs baseline: 5.6586x; 1.0103x over previous
#include <cuda_runtime.h>
#include <cuda_bf16.h>
#include <cstdint>

#define BB 2
#define SS 2048
#define EE 1024
#define NH 16
#define NKV 4
#define HD 64
#define TOKENS (BB*SS)

__device__ float g_Q[TOKENS * NH * HD];
__device__ float g_K[TOKENS * NKV * HD];
__device__ float g_V[TOKENS * NKV * HD];

__device__ __nv_bfloat16 g_Xhi[TOKENS * EE],  g_Xlo[TOKENS * EE];
__device__ __nv_bfloat16 g_Whi[1536 * EE],    g_Wlo[1536 * EE];
__device__ __nv_bfloat16 g_Phi[EE * EE],      g_Plo[EE * EE];
__device__ __nv_bfloat16 g_Yhi[TOKENS * EE],  g_Ylo[TOKENS * EE];
__device__ __nv_bfloat16 g_Qhi[TOKENS * NH * HD],  g_Qlo[TOKENS * NH * HD];
__device__ __nv_bfloat16 g_Khi[TOKENS * NKV * HD], g_Klo[TOKENS * NKV * HD];
__device__ __nv_bfloat16 g_Vhi[TOKENS * NKV * HD], g_Vlo[TOKENS * NKV * HD];

// ---- PTX helpers (baseline features only) ----
__device__ __forceinline__ uint32_t smem_u32(const void* p) {
    uint32_t a;
    asm("{ .reg .u64 t; cvta.to.shared.u64 t, %1; cvt.u32.u64 %0, t; }" : "=r"(a) : "l"(p));
    return a;
}
__device__ __forceinline__ void ldsm4(uint32_t r[4], uint32_t a) {
    asm volatile("ldmatrix.sync.aligned.m8n8.x4.shared.b16 {%0,%1,%2,%3}, [%4];"
        : "=r"(r[0]), "=r"(r[1]), "=r"(r[2]), "=r"(r[3]) : "r"(a));
}
__device__ __forceinline__ void ldsm2(uint32_t r[2], uint32_t a) {
    asm volatile("ldmatrix.sync.aligned.m8n8.x2.shared.b16 {%0,%1}, [%2];"
        : "=r"(r[0]), "=r"(r[1]) : "r"(a));
}
__device__ __forceinline__ void ldsm2t(uint32_t r[2], uint32_t a) {
    asm volatile("ldmatrix.sync.aligned.m8n8.x2.trans.shared.b16 {%0,%1}, [%2];"
        : "=r"(r[0]), "=r"(r[1]) : "r"(a));
}
__device__ __forceinline__ void mma16816(float d[4], const uint32_t a[4], const uint32_t b[2]) {
    asm volatile("mma.sync.aligned.m16n8k16.row.col.f32.bf16.bf16.f32 "
        "{%0,%1,%2,%3}, {%4,%5,%6,%7}, {%8,%9}, {%0,%1,%2,%3};"
        : "+f"(d[0]), "+f"(d[1]), "+f"(d[2]), "+f"(d[3])
        : "r"(a[0]), "r"(a[1]), "r"(a[2]), "r"(a[3]), "r"(b[0]), "r"(b[1]));
}
__device__ __forceinline__ uint32_t packbf(float e, float o) {
    uint32_t r; asm("cvt.rn.bf16x2.f32 %0, %1, %2;" : "=r"(r) : "f"(o), "f"(e)); return r;
}
__device__ __forceinline__ void cpa16(uint32_t dst, const void* src) {
    asm volatile("cp.async.cg.shared.global [%0], [%1], 16;" :: "r"(dst), "l"(src));
}
#define CP_COMMIT() asm volatile("cp.async.commit_group;" ::: "memory")
#define CP_WAIT(n)  asm volatile("cp.async.wait_group %0;" :: "n"(n) : "memory")

// ---------------------------------------------------------------------------
__global__ __launch_bounds__(256) void split_bf16(
    const float* __restrict__ src, __nv_bfloat16* __restrict__ hi,
    __nv_bfloat16* __restrict__ lo, int n4)
{
    int i = blockIdx.x * 256 + threadIdx.x;
    if (i >= n4) return;
    float4 v = *(const float4*)(src + (size_t)i * 4);
    float f[4] = {v.x, v.y, v.z, v.w};
    __nv_bfloat16 h[4], l[4];
    #pragma unroll
    for (int e = 0; e < 4; e++) {
        h[e] = __float2bfloat16(f[e]);
        l[e] = __float2bfloat16(f[e] - __bfloat162float(h[e]));
    }
    *(uint2*)(hi + (size_t)i * 4) = *(uint2*)h;
    *(uint2*)(lo + (size_t)i * 4) = *(uint2*)l;
}

__global__ __launch_bounds__(256) void split_weights(
    const float* __restrict__ Wq, const float* __restrict__ Wk,
    const float* __restrict__ Wv, const float* __restrict__ Wp)
{
    int i = blockIdx.x * 256 + threadIdx.x;
    const float* src; __nv_bfloat16 *hi, *lo; size_t off, s4;
    if (i < 262144)      { src = Wq; hi = g_Whi; lo = g_Wlo; off = (size_t)i;            s4 = (size_t)i; }
    else if (i < 327680) { src = Wk; hi = g_Whi; lo = g_Wlo; off = (size_t)i;            s4 = (size_t)(i - 262144); }
    else if (i < 393216) { src = Wv; hi = g_Whi; lo = g_Wlo; off = (size_t)i;            s4 = (size_t)(i - 327680); }
    else if (i < 655360) { src = Wp; hi = g_Phi; lo = g_Plo; off = (size_t)(i - 393216); s4 = (size_t)(i - 393216); }
    else return;
    float4 v = *(const float4*)(src + s4 * 4);
    float f[4] = {v.x, v.y, v.z, v.w};
    __nv_bfloat16 h[4], l[4];
    #pragma unroll
    for (int e = 0; e < 4; e++) {
        h[e] = __float2bfloat16(f[e]);
        l[e] = __float2bfloat16(f[e] - __bfloat162float(h[e]));
    }
    *(uint2*)(hi + off * 4) = *(uint2*)h;
    *(uint2*)(lo + off * 4) = *(uint2*)l;
}

// ---------------------------------------------------------------------------
// HMMA GEMM, cp.async 2-stage pipeline. C[128,128] of A[M,1024] @ B[N,1024]^T.
// ---------------------------------------------------------------------------
#define G_AR   10240
#define G_STG  (4 * G_AR)
#define G_SMEM (2 * G_STG)

__device__ __forceinline__ void mma_gemm(
    const __nv_bfloat16* __restrict__ Ahi, const __nv_bfloat16* __restrict__ Alo,
    const __nv_bfloat16* __restrict__ Bhi, const __nv_bfloat16* __restrict__ Blo,
    float* __restrict__ Cb, int ldc, int m0)
{
    extern __shared__ char smdyn[];
    uint32_t sb0 = smem_u32(smdyn);

    int t = threadIdx.x;
    int wid = t >> 5, lane = t & 31;
    int wr = wid >> 2, wc = wid & 3;

    const __nv_bfloat16* srcs[4] = {
        Ahi + (size_t)m0 * 1024, Alo + (size_t)m0 * 1024, Bhi, Blo };

    float acc[4][4][4];
    #pragma unroll
    for (int mt = 0; mt < 4; mt++)
        #pragma unroll
        for (int nt = 0; nt < 4; nt++)
            #pragma unroll
            for (int e = 0; e < 4; e++) acc[mt][nt][e] = 0.f;

    {
        #pragma unroll
        for (int i = 0; i < 8; i++) {
            int c = t + i * 256;
            int arr = c >> 9, cc = c & 511, row = cc >> 2, seg = (cc & 3) * 8;
            cpa16(sb0 + (uint32_t)(arr * G_AR + row * 80 + seg * 2),
                  srcs[arr] + (size_t)row * 1024 + seg);
        }
        CP_COMMIT();
    }

    for (int it = 0; it < 32; it++) {
        if (it + 1 < 32) {
            uint32_t base = sb0 + ((it + 1) & 1) * G_STG;
            int k0 = (it + 1) * 32;
            #pragma unroll
            for (int i = 0; i < 8; i++) {
                int c = t + i * 256;
                int arr = c >> 9, cc = c & 511, row = cc >> 2, seg = (cc & 3) * 8;
                cpa16(base + (uint32_t)(arr * G_AR + row * 80 + seg * 2),
                      srcs[arr] + (size_t)row * 1024 + k0 + seg);
            }
            CP_COMMIT();
            CP_WAIT(1);
        } else {
            CP_WAIT(0);
        }
        __syncthreads();

        uint32_t sb = sb0 + (it & 1) * G_STG;
        uint32_t aAh = sb, aAl = sb + G_AR, aBh = sb + 2 * G_AR, aBl = sb + 3 * G_AR;

        #pragma unroll
        for (int ks = 0; ks < 2; ks++) {
            int kk = ks * 16;
            uint32_t fAh[4][4], fAl[4][4], fBh[4][2], fBl[4][2];
            int arow = lane & 15;
            int acol = kk + (lane >> 4) * 8;
            #pragma unroll
            for (int mt = 0; mt < 4; mt++) {
                uint32_t off = (uint32_t)((wr * 64 + mt * 16 + arow) * 80 + acol * 2);
                ldsm4(fAh[mt], aAh + off);
                ldsm4(fAl[mt], aAl + off);
            }
            int brow = lane & 7;
            int bcol = kk + (lane & 8);
            #pragma unroll
            for (int nt = 0; nt < 4; nt++) {
                uint32_t off = (uint32_t)((wc * 32 + nt * 8 + brow) * 80 + bcol * 2);
                ldsm2(fBh[nt], aBh + off);
                ldsm2(fBl[nt], aBl + off);
            }
            #pragma unroll
            for (int mt = 0; mt < 4; mt++)
                #pragma unroll
                for (int nt = 0; nt < 4; nt++) {
                    mma16816(acc[mt][nt], fAh[mt], fBh[nt]);
                    mma16816(acc[mt][nt], fAl[mt], fBh[nt]);
                    mma16816(acc[mt][nt], fAh[mt], fBl[nt]);
                }
        }
        __syncthreads();
    }

    #pragma unroll
    for (int mt = 0; mt < 4; mt++)
        #pragma unroll
        for (int nt = 0; nt < 4; nt++) {
            int r0 = m0 + wr * 64 + mt * 16 + (lane >> 2);
            int c0 = wc * 32 + nt * 8 + (lane & 3) * 2;
            float2 w0; w0.x = acc[mt][nt][0]; w0.y = acc[mt][nt][1];
            float2 w1; w1.x = acc[mt][nt][2]; w1.y = acc[mt][nt][3];
            *(float2*)&Cb[(size_t)r0 * ldc + c0]       = w0;
            *(float2*)&Cb[(size_t)(r0 + 8) * ldc + c0] = w1;
        }
}

__global__ __launch_bounds__(256) void qkv_gemm_mma()
{
    int n0 = blockIdx.x * 128;
    int m0 = blockIdx.y * 128;
    const __nv_bfloat16* Bh = g_Whi + (size_t)n0 * 1024;
    const __nv_bfloat16* Bl = g_Wlo + (size_t)n0 * 1024;
    float* Cb; int ldc;
    if (n0 < 1024)      { Cb = g_Q + n0;          ldc = 1024; }
    else if (n0 < 1280) { Cb = g_K + (n0 - 1024); ldc = 256;  }
    else                { Cb = g_V + (n0 - 1280); ldc = 256;  }
    mma_gemm(g_Xhi, g_Xlo, Bh, Bl, Cb, ldc, m0);
}

__global__ __launch_bounds__(256) void proj_gemm_mma(float* __restrict__ out)
{
    int n0 = blockIdx.x * 128;
    int m0 = blockIdx.y * 128;
    mma_gemm(g_Yhi, g_Ylo, g_Phi + (size_t)n0 * 1024, g_Plo + (size_t)n0 * 1024,
             out + n0, 1024, m0);
}

// ---------------------------------------------------------------------------
__device__ __forceinline__ void split_store(__nv_bfloat16* hi, __nv_bfloat16* lo,
                                            size_t idx, float v) {
    __nv_bfloat16 h = __float2bfloat16(v);
    hi[idx] = h;
    lo[idx] = __float2bfloat16(v - __bfloat162float(h));
}

__global__ __launch_bounds__(128) void postproc(
    const float* __restrict__ x, const float* __restrict__ ve,
    const float* __restrict__ cosb, const float* __restrict__ sinb,
    const float* __restrict__ Wgate)
{
    int tok = blockIdx.x;
    int s = tok & (SS - 1);
    int t = threadIdx.x;
    int w = t >> 5;
    int lane = t & 31;

    __shared__ float gate[4];
    __shared__ float x12[12];

    if (t < 12) x12[t] = x[(size_t)tok * EE + t];
    __syncthreads();
    if (t < 4) {
        float acc = 0.f;
        #pragma unroll
        for (int c = 0; c < 12; c++) acc += x12[c] * Wgate[t * 12 + c];
        gate[t] = 3.f / (1.f + __expf(-acc));
    }
    __syncthreads();

    for (int i = t; i < 256; i += 128) {
        int hh = i >> 6;
        float v = g_V[(size_t)tok * 256 + i] + gate[hh] * ve[(size_t)tok * 256 + i];
        split_store(g_Vhi, g_Vlo, (size_t)tok * 256 + i, v);
    }

    const float EPS = 1.1920929e-7f;
    float cv = cosb[s * 32 + lane];
    float sv = sinb[s * 32 + lane];

    #pragma unroll
    for (int i = 0; i < 4; i++) {
        int h = w + 4 * i;
        const float* qp = &g_Q[(size_t)tok * 1024 + h * 64];
        float x1 = qp[lane], x2 = qp[lane + 32];
        float r1 =  x1 * cv + x2 * sv;
        float r2 = -x1 * sv + x2 * cv;
        float ss = r1 * r1 + r2 * r2;
        #pragma unroll
        for (int o = 16; o; o >>= 1) ss += __shfl_xor_sync(0xFFFFFFFFu, ss, o);
        float scale = rsqrtf(ss * (1.f / 64.f) + EPS) * 1.2f;
        size_t base = (size_t)tok * 1024 + h * 64;
        split_store(g_Qhi, g_Qlo, base + lane,      r1 * scale);
        split_store(g_Qhi, g_Qlo, base + lane + 32, r2 * scale);
    }
    {
        const float* kp = &g_K[(size_t)tok * 256 + w * 64];
        float x1 = kp[lane], x2 = kp[lane + 32];
        float r1 =  x1 * cv + x2 * sv;
        float r2 = -x1 * sv + x2 * cv;
        float ss = r1 * r1 + r2 * r2;
        #pragma unroll
        for (int o = 16; o; o >>= 1) ss += __shfl_xor_sync(0xFFFFFFFFu, ss, o);
        float scale = rsqrtf(ss * (1.f / 64.f) + EPS) * 1.2f;
        size_t base = (size_t)tok * 256 + w * 64;
        split_store(g_Khi, g_Klo, base + lane,      r1 * scale);
        split_store(g_Khi, g_Klo, base + lane + 32, r2 * scale);
    }
}

// ---------------------------------------------------------------------------
// Flash attention on HMMA, balanced pairing. Grid (8, NH, BB), 256 threads.
// CTA processes q-blocks {15-p, p} (128 rows each) => uniform 34 KV tiles.
// 2-stage cp.async K/V pipeline; epilogue writes Yhi/Ylo (fused split).
// ---------------------------------------------------------------------------
#define A_AR   9216
#define A_STG  (4 * A_AR)
#define A_SMEM (2 * A_STG)

__global__ __launch_bounds__(256) void attn_mma()
{
    extern __shared__ char smdyn[];
    uint32_t sb0 = smem_u32(smdyn);

    int p  = blockIdx.x;           // 0..7
    int h  = blockIdx.y;
    int b  = blockIdx.z;
    int hkv = h >> 2;
    int t = threadIdx.x;
    int wid = t >> 5, lane = t & 31;

    const __nv_bfloat16* srcs[4] = { g_Khi, g_Klo, g_Vhi, g_Vlo };

    #pragma unroll 1
    for (int bi = 0; bi < 2; bi++) {
        int jblk = bi ? p : (15 - p);       // big block first
        size_t tok0 = (size_t)b * SS + jblk * 128;
        int ntiles = 2 * jblk + 2;

        // ---- stage Q (hi at sb0, lo at sb0+18432), build fragments ----
        for (int idx = t; idx < 1024; idx += 256) {
            int row = idx >> 3, ch = (idx & 7) * 8;
            size_t g = (tok0 + row) * 1024 + h * 64 + ch;
            *(uint4*)(smdyn + row * 144 + ch * 2)         = *(const uint4*)&g_Qhi[g];
            *(uint4*)(smdyn + 18432 + row * 144 + ch * 2) = *(const uint4*)&g_Qlo[g];
        }
        __syncthreads();

        uint32_t qh[4][4], ql[4][4];
        {
            int arow = wid * 16 + (lane & 15);
            int acol = (lane >> 4) * 8;
            #pragma unroll
            for (int kc = 0; kc < 4; kc++) {
                uint32_t off = (uint32_t)(arow * 144 + (kc * 16 + acol) * 2);
                ldsm4(qh[kc], sb0 + off);
                ldsm4(ql[kc], sb0 + 18432 + off);
            }
        }
        __syncthreads();

        float accO[8][4];
        #pragma unroll
        for (int nt = 0; nt < 8; nt++)
            #pragma unroll
            for (int e = 0; e < 4; e++) accO[nt][e] = 0.f;
        float m0 = -1e30f, m1 = -1e30f, l0 = 0.f, l1 = 0.f;

        // prologue: tile 0 into stage 0
        {
            size_t base = (size_t)b * SS;
            #pragma unroll
            for (int i = 0; i < 8; i++) {
                int c = t + i * 256;
                int arr = c >> 9, cc = c & 511, row = cc >> 3, seg = (cc & 7) * 8;
                cpa16(sb0 + (uint32_t)(arr * A_AR + row * 144 + seg * 2),
                      srcs[arr] + (base + row) * 256 + hkv * 64 + seg);
            }
            CP_COMMIT();
        }

        for (int kt = 0; kt < ntiles; kt++) {
            if (kt + 1 < ntiles) {
                uint32_t sbl = sb0 + ((kt + 1) & 1) * A_STG;
                size_t base = (size_t)b * SS + (kt + 1) * 64;
                #pragma unroll
                for (int i = 0; i < 8; i++) {
                    int c = t + i * 256;
                    int arr = c >> 9, cc = c & 511, row = cc >> 3, seg = (cc & 7) * 8;
                    cpa16(sbl + (uint32_t)(arr * A_AR + row * 144 + seg * 2),
                          srcs[arr] + (base + row) * 256 + hkv * 64 + seg);
                }
                CP_COMMIT();
                CP_WAIT(1);
            } else {
                CP_WAIT(0);
            }
            __syncthreads();

            uint32_t sb = sb0 + (kt & 1) * A_STG;
            uint32_t aKh = sb, aKl = sb + A_AR, aVh = sb + 2 * A_AR, aVl = sb + 3 * A_AR;

            // ---- S = Q K^T (3-pass) ----
            float sacc[8][4];
            #pragma unroll
            for (int nt = 0; nt < 8; nt++)
                #pragma unroll
                for (int e = 0; e < 4; e++) sacc[nt][e] = 0.f;

            #pragma unroll
            for (int kc = 0; kc < 4; kc++) {
                int bcol = kc * 16 + (lane & 8);
                #pragma unroll
                for (int nt = 0; nt < 8; nt++) {
                    uint32_t bh[2], bl[2];
                    uint32_t off = (uint32_t)((nt * 8 + (lane & 7)) * 144 + bcol * 2);
                    ldsm2(bh, aKh + off);
                    ldsm2(bl, aKl + off);
                    mma16816(sacc[nt], qh[kc], bh);
                    mma16816(sacc[nt], ql[kc], bh);
                    mma16816(sacc[nt], qh[kc], bl);
                }
            }

            #pragma unroll
            for (int nt = 0; nt < 8; nt++)
                #pragma unroll
                for (int e = 0; e < 4; e++) sacc[nt][e] *= 0.125f;

            if (kt >= 2 * jblk) {
                int cb2 = (kt - 2 * jblk) * 64;
                int rloc = wid * 16 + (lane >> 2);
                #pragma unroll
                for (int nt = 0; nt < 8; nt++) {
                    int cl = cb2 + nt * 8 + (lane & 3) * 2;
                    if (cl     > rloc)     sacc[nt][0] = -1e30f;
                    if (cl + 1 > rloc)     sacc[nt][1] = -1e30f;
                    if (cl     > rloc + 8) sacc[nt][2] = -1e30f;
                    if (cl + 1 > rloc + 8) sacc[nt][3] = -1e30f;
                }
            }

            // ---- online softmax ----
            float mx0 = -1e30f, mx1 = -1e30f;
            #pragma unroll
            for (int nt = 0; nt < 8; nt++) {
                mx0 = fmaxf(mx0, fmaxf(sacc[nt][0], sacc[nt][1]));
                mx1 = fmaxf(mx1, fmaxf(sacc[nt][2], sacc[nt][3]));
            }
            mx0 = fmaxf(mx0, __shfl_xor_sync(0xFFFFFFFFu, mx0, 1));
            mx0 = fmaxf(mx0, __shfl_xor_sync(0xFFFFFFFFu, mx0, 2));
            mx1 = fmaxf(mx1, __shfl_xor_sync(0xFFFFFFFFu, mx1, 1));
            mx1 = fmaxf(mx1, __shfl_xor_sync(0xFFFFFFFFu, mx1, 2));

            float mn0 = fmaxf(m0, mx0), mn1 = fmaxf(m1, mx1);
            float cr0 = __expf(m0 - mn0), cr1 = __expf(m1 - mn1);
            float rs0 = 0.f, rs1 = 0.f;
            #pragma unroll
            for (int nt = 0; nt < 8; nt++) {
                float p0 = __expf(sacc[nt][0] - mn0);
                float p1 = __expf(sacc[nt][1] - mn0);
                float p2 = __expf(sacc[nt][2] - mn1);
                float p3 = __expf(sacc[nt][3] - mn1);
                sacc[nt][0] = p0; sacc[nt][1] = p1; sacc[nt][2] = p2; sacc[nt][3] = p3;
                rs0 += p0 + p1; rs1 += p2 + p3;
            }
            rs0 += __shfl_xor_sync(0xFFFFFFFFu, rs0, 1);
            rs0 += __shfl_xor_sync(0xFFFFFFFFu, rs0, 2);
            rs1 += __shfl_xor_sync(0xFFFFFFFFu, rs1, 1);
            rs1 += __shfl_xor_sync(0xFFFFFFFFu, rs1, 2);
            l0 = l0 * cr0 + rs0; l1 = l1 * cr1 + rs1;
            m0 = mn0; m1 = mn1;
            #pragma unroll
            for (int nt = 0; nt < 8; nt++) {
                accO[nt][0] *= cr0; accO[nt][1] *= cr0;
                accO[nt][2] *= cr1; accO[nt][3] *= cr1;
            }

            // ---- O += P V (3-pass) ----
            #pragma unroll
            for (int kc = 0; kc < 4; kc++) {
                uint32_t ph[4], pl[4];
                {
                    float p00 = sacc[2*kc][0],   p01 = sacc[2*kc][1];
                    float p10 = sacc[2*kc][2],   p11 = sacc[2*kc][3];
                    float p20 = sacc[2*kc+1][0], p21 = sacc[2*kc+1][1];
                    float p30 = sacc[2*kc+1][2], p31 = sacc[2*kc+1][3];
                    ph[0] = packbf(p00, p01); ph[1] = packbf(p10, p11);
                    ph[2] = packbf(p20, p21); ph[3] = packbf(p30, p31);
                    float h00 = __bfloat162float(__float2bfloat16(p00));
                    float h01 = __bfloat162float(__float2bfloat16(p01));
                    float h10 = __bfloat162float(__float2bfloat16(p10));
                    float h11 = __bfloat162float(__float2bfloat16(p11));
                    float h20 = __bfloat162float(__float2bfloat16(p20));
                    float h21 = __bfloat162float(__float2bfloat16(p21));
                    float h30 = __bfloat162float(__float2bfloat16(p30));
                    float h31 = __bfloat162float(__float2bfloat16(p31));
                    pl[0] = packbf(p00 - h00, p01 - h01);
                    pl[1] = packbf(p10 - h10, p11 - h11);
                    pl[2] = packbf(p20 - h20, p21 - h21);
                    pl[3] = packbf(p30 - h30, p31 - h31);
                }
                int vrow = kc * 16 + (lane & 15);
                #pragma unroll
                for (int nt = 0; nt < 8; nt++) {
                    uint32_t vh[2], vl[2];
                    uint32_t off = (uint32_t)(vrow * 144 + nt * 16);
                    ldsm2t(vh, aVh + off);
                    ldsm2t(vl, aVl + off);
                    mma16816(accO[nt], ph, vh);
                    mma16816(accO[nt], pl, vh);
                    mma16816(accO[nt], ph, vl);
                }
            }
            __syncthreads();
        }

        // ---- epilogue: write Yhi/Ylo (fused split) ----
        float inv0 = 1.f / l0, inv1 = 1.f / l1;
        int r0 = wid * 16 + (lane >> 2);
        #pragma unroll
        for (int nt = 0; nt < 8; nt++) {
            int col = h * 64 + nt * 8 + (lane & 3) * 2;
            float v00 = accO[nt][0] * inv0, v01 = accO[nt][1] * inv0;
            float v10 = accO[nt][2] * inv1, v11 = accO[nt][3] * inv1;
            float h00 = __bfloat162float(__float2bfloat16(v00));
            float h01 = __bfloat162float(__float2bfloat16(v01));
            float h10 = __bfloat162float(__float2bfloat16(v10));
            float h11 = __bfloat162float(__float2bfloat16(v11));
            size_t i0 = (tok0 + r0) * 1024 + col;
            size_t i1 = (tok0 + r0 + 8) * 1024 + col;
            *(uint32_t*)&g_Yhi[i0] = packbf(v00, v01);
            *(uint32_t*)&g_Ylo[i0] = packbf(v00 - h00, v01 - h01);
            *(uint32_t*)&g_Yhi[i1] = packbf(v10, v11);
            *(uint32_t*)&g_Ylo[i1] = packbf(v10 - h10, v11 - h11);
        }
        __syncthreads();
    }
}

// ---------------------------------------------------------------------------
extern "C" void kernel_launch(void* const* d_in, const int* in_sizes, int n_in,
                              void* d_out, int out_size)
{
    const float* x     = (const float*)d_in[0];
    const float* ve    = (const float*)d_in[1];
    const float* cosb  = (const float*)d_in[2];
    const float* sinb  = (const float*)d_in[3];
    const float* Wq    = (const float*)d_in[5];
    const float* Wk    = (const float*)d_in[6];
    const float* Wv    = (const float*)d_in[7];
    const float* Wproj = (const float*)d_in[8];
    const float* Wgate = (const float*)d_in[9];
    float* out = (float*)d_out;

    __nv_bfloat16 *Xhi, *Xlo;
    cudaGetSymbolAddress((void**)&Xhi, g_Xhi);
    cudaGetSymbolAddress((void**)&Xlo, g_Xlo);

    static bool attr_set = false;
    if (!attr_set) {
        cudaFuncSetAttribute(qkv_gemm_mma, cudaFuncAttributeMaxDynamicSharedMemorySize, G_SMEM);
        cudaFuncSetAttribute(proj_gemm_mma, cudaFuncAttributeMaxDynamicSharedMemorySize, G_SMEM);
        cudaFuncSetAttribute(attn_mma, cudaFuncAttributeMaxDynamicSharedMemorySize, A_SMEM);
        attr_set = true;
    }

    split_bf16<<<(TOKENS*EE/4 + 255)/256, 256>>>(x, Xhi, Xlo, TOKENS*EE/4);
    split_weights<<<(655360 + 255)/256, 256>>>(Wq, Wk, Wv, Wproj);

    dim3 g1(12, 32);
    qkv_gemm_mma<<<g1, 256, G_SMEM>>>();

    postproc<<<TOKENS, 128>>>(x, ve, cosb, sinb, Wgate);

    dim3 g3(8, NH, BB);
    attn_mma<<<g3, 256, A_SMEM>>>();

    dim3 g4(8, 32);
    proj_gemm_mma<<<g4, 256, G_SMEM>>>(out);
}

// round 8
// speedup vs baseline: 8.0550x; 1.4235x over previous
#include <cuda_runtime.h>
#include <cuda_fp16.h>
#include <cstdint>

#define BB 2
#define SS 2048
#define EE 1024
#define NH 16
#define NKV 4
#define HD 64
#define TOKENS (BB*SS)

__device__ float g_Q[TOKENS * NH * HD];
__device__ float g_K[TOKENS * NKV * HD];
__device__ float g_V[TOKENS * NKV * HD];

// fp16 operands: activations split exactly (hi+lo), weights rounded once
__device__ __half g_Xhi[TOKENS * EE], g_Xlo[TOKENS * EE];
__device__ __half g_Wh[1536 * EE];                    // [Wq;Wk;Wv] rounded
__device__ __half g_Ph[EE * EE];                      // Wproj rounded
__device__ __half g_Yhi[TOKENS * EE], g_Ylo[TOKENS * EE];
__device__ __half g_Qhi[TOKENS * NH * HD], g_Qlo[TOKENS * NH * HD];
__device__ __half g_Kh[TOKENS * NKV * HD];            // rounded
__device__ __half g_Vh[TOKENS * NKV * HD];            // rounded

// ---- PTX helpers (baseline features only) ----
__device__ __forceinline__ uint32_t smem_u32(const void* p) {
    uint32_t a;
    asm("{ .reg .u64 t; cvta.to.shared.u64 t, %1; cvt.u32.u64 %0, t; }" : "=r"(a) : "l"(p));
    return a;
}
__device__ __forceinline__ void ldsm4(uint32_t r[4], uint32_t a) {
    asm volatile("ldmatrix.sync.aligned.m8n8.x4.shared.b16 {%0,%1,%2,%3}, [%4];"
        : "=r"(r[0]), "=r"(r[1]), "=r"(r[2]), "=r"(r[3]) : "r"(a));
}
__device__ __forceinline__ void ldsm2(uint32_t r[2], uint32_t a) {
    asm volatile("ldmatrix.sync.aligned.m8n8.x2.shared.b16 {%0,%1}, [%2];"
        : "=r"(r[0]), "=r"(r[1]) : "r"(a));
}
__device__ __forceinline__ void ldsm2t(uint32_t r[2], uint32_t a) {
    asm volatile("ldmatrix.sync.aligned.m8n8.x2.trans.shared.b16 {%0,%1}, [%2];"
        : "=r"(r[0]), "=r"(r[1]) : "r"(a));
}
__device__ __forceinline__ void mmah(float d[4], const uint32_t a[4], const uint32_t b[2]) {
    asm volatile("mma.sync.aligned.m16n8k16.row.col.f32.f16.f16.f32 "
        "{%0,%1,%2,%3}, {%4,%5,%6,%7}, {%8,%9}, {%0,%1,%2,%3};"
        : "+f"(d[0]), "+f"(d[1]), "+f"(d[2]), "+f"(d[3])
        : "r"(a[0]), "r"(a[1]), "r"(a[2]), "r"(a[3]), "r"(b[0]), "r"(b[1]));
}
// pack {lo=e, hi=o} f16x2
__device__ __forceinline__ uint32_t packh(float e, float o) {
    uint32_t r; asm("cvt.rn.f16x2.f32 %0, %1, %2;" : "=r"(r) : "f"(o), "f"(e)); return r;
}
__device__ __forceinline__ void cpa16(uint32_t dst, const void* src) {
    asm volatile("cp.async.cg.shared.global [%0], [%1], 16;" :: "r"(dst), "l"(src));
}
#define CP_COMMIT() asm volatile("cp.async.commit_group;" ::: "memory")
#define CP_WAIT(n)  asm volatile("cp.async.wait_group %0;" :: "n"(n) : "memory")

// ---------------------------------------------------------------------------
// X -> exact fp16 hi/lo split
__global__ __launch_bounds__(256) void split_x(
    const float* __restrict__ src, __half* __restrict__ hi,
    __half* __restrict__ lo, int n4)
{
    int i = blockIdx.x * 256 + threadIdx.x;
    if (i >= n4) return;
    float4 v = *(const float4*)(src + (size_t)i * 4);
    float f[4] = {v.x, v.y, v.z, v.w};
    __half h[4], l[4];
    #pragma unroll
    for (int e = 0; e < 4; e++) {
        h[e] = __float2half(f[e]);
        l[e] = __float2half(f[e] - __half2float(h[e]));
    }
    *(uint2*)(hi + (size_t)i * 4) = *(uint2*)h;
    *(uint2*)(lo + (size_t)i * 4) = *(uint2*)l;
}

// All weights -> single-rounded fp16, one launch
__global__ __launch_bounds__(256) void round_weights(
    const float* __restrict__ Wq, const float* __restrict__ Wk,
    const float* __restrict__ Wv, const float* __restrict__ Wp)
{
    int i = blockIdx.x * 256 + threadIdx.x;
    const float* src; __half* dst; size_t off, s4;
    if (i < 262144)      { src = Wq; dst = g_Wh; off = (size_t)i;            s4 = (size_t)i; }
    else if (i < 327680) { src = Wk; dst = g_Wh; off = (size_t)i;            s4 = (size_t)(i - 262144); }
    else if (i < 393216) { src = Wv; dst = g_Wh; off = (size_t)i;            s4 = (size_t)(i - 327680); }
    else if (i < 655360) { src = Wp; dst = g_Ph; off = (size_t)(i - 393216); s4 = (size_t)(i - 393216); }
    else return;
    float4 v = *(const float4*)(src + s4 * 4);
    __half h[4] = { __float2half(v.x), __float2half(v.y),
                    __float2half(v.z), __float2half(v.w) };
    *(uint2*)(dst + off * 4) = *(uint2*)h;
}

// ---------------------------------------------------------------------------
// fp16 2-pass HMMA GEMM: C = (Ah+Al) @ Bh^T.  128x128 tile, cp.async 2-stage.
// smem/stage: 3 arrays (Ah, Al, B) x [128][40] halves = 30720 B.
// ---------------------------------------------------------------------------
#define G_AR   10240
#define G_STG  (3 * G_AR)
#define G_SMEM (2 * G_STG)

__device__ __forceinline__ void mma_gemm(
    const __half* __restrict__ Ahi, const __half* __restrict__ Alo,
    const __half* __restrict__ Bh,
    float* __restrict__ Cb, int ldc, int m0)
{
    extern __shared__ char smdyn[];
    uint32_t sb0 = smem_u32(smdyn);

    int t = threadIdx.x;
    int wid = t >> 5, lane = t & 31;
    int wr = wid >> 2, wc = wid & 3;

    const __half* srcs[3] = { Ahi + (size_t)m0 * 1024, Alo + (size_t)m0 * 1024, Bh };

    float acc[4][4][4];
    #pragma unroll
    for (int mt = 0; mt < 4; mt++)
        #pragma unroll
        for (int nt = 0; nt < 4; nt++)
            #pragma unroll
            for (int e = 0; e < 4; e++) acc[mt][nt][e] = 0.f;

    {
        #pragma unroll
        for (int i = 0; i < 6; i++) {
            int c = t + i * 256;
            int arr = c >> 9, cc = c & 511, row = cc >> 2, seg = (cc & 3) * 8;
            cpa16(sb0 + (uint32_t)(arr * G_AR + row * 80 + seg * 2),
                  srcs[arr] + (size_t)row * 1024 + seg);
        }
        CP_COMMIT();
    }

    for (int it = 0; it < 32; it++) {
        if (it + 1 < 32) {
            uint32_t base = sb0 + ((it + 1) & 1) * G_STG;
            int k0 = (it + 1) * 32;
            #pragma unroll
            for (int i = 0; i < 6; i++) {
                int c = t + i * 256;
                int arr = c >> 9, cc = c & 511, row = cc >> 2, seg = (cc & 3) * 8;
                cpa16(base + (uint32_t)(arr * G_AR + row * 80 + seg * 2),
                      srcs[arr] + (size_t)row * 1024 + k0 + seg);
            }
            CP_COMMIT();
            CP_WAIT(1);
        } else {
            CP_WAIT(0);
        }
        __syncthreads();

        uint32_t sb = sb0 + (it & 1) * G_STG;
        uint32_t aAh = sb, aAl = sb + G_AR, aB = sb + 2 * G_AR;

        #pragma unroll
        for (int ks = 0; ks < 2; ks++) {
            int kk = ks * 16;
            uint32_t fAh[4][4], fAl[4][4], fB[4][2];
            int arow = lane & 15;
            int acol = kk + (lane >> 4) * 8;
            #pragma unroll
            for (int mt = 0; mt < 4; mt++) {
                uint32_t off = (uint32_t)((wr * 64 + mt * 16 + arow) * 80 + acol * 2);
                ldsm4(fAh[mt], aAh + off);
                ldsm4(fAl[mt], aAl + off);
            }
            int brow = lane & 7;
            int bcol = kk + (lane & 8);
            #pragma unroll
            for (int nt = 0; nt < 4; nt++) {
                uint32_t off = (uint32_t)((wc * 32 + nt * 8 + brow) * 80 + bcol * 2);
                ldsm2(fB[nt], aB + off);
            }
            #pragma unroll
            for (int mt = 0; mt < 4; mt++)
                #pragma unroll
                for (int nt = 0; nt < 4; nt++) {
                    mmah(acc[mt][nt], fAh[mt], fB[nt]);
                    mmah(acc[mt][nt], fAl[mt], fB[nt]);
                }
        }
        __syncthreads();
    }

    #pragma unroll
    for (int mt = 0; mt < 4; mt++)
        #pragma unroll
        for (int nt = 0; nt < 4; nt++) {
            int r0 = m0 + wr * 64 + mt * 16 + (lane >> 2);
            int c0 = wc * 32 + nt * 8 + (lane & 3) * 2;
            float2 w0; w0.x = acc[mt][nt][0]; w0.y = acc[mt][nt][1];
            float2 w1; w1.x = acc[mt][nt][2]; w1.y = acc[mt][nt][3];
            *(float2*)&Cb[(size_t)r0 * ldc + c0]       = w0;
            *(float2*)&Cb[(size_t)(r0 + 8) * ldc + c0] = w1;
        }
}

__global__ __launch_bounds__(256) void qkv_gemm_mma()
{
    int n0 = blockIdx.x * 128;
    int m0 = blockIdx.y * 128;
    float* Cb; int ldc;
    if (n0 < 1024)      { Cb = g_Q + n0;          ldc = 1024; }
    else if (n0 < 1280) { Cb = g_K + (n0 - 1024); ldc = 256;  }
    else                { Cb = g_V + (n0 - 1280); ldc = 256;  }
    mma_gemm(g_Xhi, g_Xlo, g_Wh + (size_t)n0 * 1024, Cb, ldc, m0);
}

__global__ __launch_bounds__(256) void proj_gemm_mma(float* __restrict__ out)
{
    int n0 = blockIdx.x * 128;
    int m0 = blockIdx.y * 128;
    mma_gemm(g_Yhi, g_Ylo, g_Ph + (size_t)n0 * 1024, out + n0, 1024, m0);
}

// ---------------------------------------------------------------------------
__global__ __launch_bounds__(128) void postproc(
    const float* __restrict__ x, const float* __restrict__ ve,
    const float* __restrict__ cosb, const float* __restrict__ sinb,
    const float* __restrict__ Wgate)
{
    int tok = blockIdx.x;
    int s = tok & (SS - 1);
    int t = threadIdx.x;
    int w = t >> 5;
    int lane = t & 31;

    __shared__ float gate[4];
    __shared__ float x12[12];

    if (t < 12) x12[t] = x[(size_t)tok * EE + t];
    __syncthreads();
    if (t < 4) {
        float acc = 0.f;
        #pragma unroll
        for (int c = 0; c < 12; c++) acc += x12[c] * Wgate[t * 12 + c];
        gate[t] = 3.f / (1.f + __expf(-acc));
    }
    __syncthreads();

    for (int i = t; i < 256; i += 128) {
        int hh = i >> 6;
        float v = g_V[(size_t)tok * 256 + i] + gate[hh] * ve[(size_t)tok * 256 + i];
        g_Vh[(size_t)tok * 256 + i] = __float2half(v);
    }

    const float EPS = 1.1920929e-7f;
    float cv = cosb[s * 32 + lane];
    float sv = sinb[s * 32 + lane];

    #pragma unroll
    for (int i = 0; i < 4; i++) {
        int h = w + 4 * i;
        const float* qp = &g_Q[(size_t)tok * 1024 + h * 64];
        float x1 = qp[lane], x2 = qp[lane + 32];
        float r1 =  x1 * cv + x2 * sv;
        float r2 = -x1 * sv + x2 * cv;
        float ss = r1 * r1 + r2 * r2;
        #pragma unroll
        for (int o = 16; o; o >>= 1) ss += __shfl_xor_sync(0xFFFFFFFFu, ss, o);
        float scale = rsqrtf(ss * (1.f / 64.f) + EPS) * 1.2f;
        size_t base = (size_t)tok * 1024 + h * 64;
        float v1 = r1 * scale, v2 = r2 * scale;
        __half h1 = __float2half(v1), h2 = __float2half(v2);
        g_Qhi[base + lane]      = h1;
        g_Qlo[base + lane]      = __float2half(v1 - __half2float(h1));
        g_Qhi[base + lane + 32] = h2;
        g_Qlo[base + lane + 32] = __float2half(v2 - __half2float(h2));
    }
    {
        const float* kp = &g_K[(size_t)tok * 256 + w * 64];
        float x1 = kp[lane], x2 = kp[lane + 32];
        float r1 =  x1 * cv + x2 * sv;
        float r2 = -x1 * sv + x2 * cv;
        float ss = r1 * r1 + r2 * r2;
        #pragma unroll
        for (int o = 16; o; o >>= 1) ss += __shfl_xor_sync(0xFFFFFFFFu, ss, o);
        float scale = rsqrtf(ss * (1.f / 64.f) + EPS) * 1.2f;
        size_t base = (size_t)tok * 256 + w * 64;
        g_Kh[base + lane]      = __float2half(r1 * scale);
        g_Kh[base + lane + 32] = __float2half(r2 * scale);
    }
}

// ---------------------------------------------------------------------------
// Flash attention, fp16 2-pass. Grid (8, NH, BB), 256 threads; CTA does
// q-blocks {15-p, p} (uniform 34 tiles). K/V single fp16, Q split hi/lo.
// smem: 2 stages x (K + V) x [64][72] halves = 36864 B (Q staging reuses it).
// ---------------------------------------------------------------------------
#define A_AR   9216
#define A_STG  (2 * A_AR)
#define A_SMEM (2 * A_STG)

__global__ __launch_bounds__(256) void attn_mma()
{
    extern __shared__ char smdyn[];
    uint32_t sb0 = smem_u32(smdyn);

    int p  = blockIdx.x;
    int h  = blockIdx.y;
    int b  = blockIdx.z;
    int hkv = h >> 2;
    int t = threadIdx.x;
    int wid = t >> 5, lane = t & 31;

    const __half* srcs[2] = { g_Kh, g_Vh };

    #pragma unroll 1
    for (int bi = 0; bi < 2; bi++) {
        int jblk = bi ? p : (15 - p);
        size_t tok0 = (size_t)b * SS + jblk * 128;
        int ntiles = 2 * jblk + 2;

        // ---- stage Q (hi [0,18432), lo [18432,36864)), build fragments ----
        for (int idx = t; idx < 1024; idx += 256) {
            int row = idx >> 3, ch = (idx & 7) * 8;
            size_t g = (tok0 + row) * 1024 + h * 64 + ch;
            *(uint4*)(smdyn + row * 144 + ch * 2)         = *(const uint4*)&g_Qhi[g];
            *(uint4*)(smdyn + 18432 + row * 144 + ch * 2) = *(const uint4*)&g_Qlo[g];
        }
        __syncthreads();

        uint32_t qh[4][4], ql[4][4];
        {
            int arow = wid * 16 + (lane & 15);
            int acol = (lane >> 4) * 8;
            #pragma unroll
            for (int kc = 0; kc < 4; kc++) {
                uint32_t off = (uint32_t)(arow * 144 + (kc * 16 + acol) * 2);
                ldsm4(qh[kc], sb0 + off);
                ldsm4(ql[kc], sb0 + 18432 + off);
            }
        }
        __syncthreads();

        float accO[8][4];
        #pragma unroll
        for (int nt = 0; nt < 8; nt++)
            #pragma unroll
            for (int e = 0; e < 4; e++) accO[nt][e] = 0.f;
        float m0 = -1e30f, m1 = -1e30f, l0 = 0.f, l1 = 0.f;

        {
            size_t base = (size_t)b * SS;
            #pragma unroll
            for (int i = 0; i < 4; i++) {
                int c = t + i * 256;
                int arr = c >> 9, cc = c & 511, row = cc >> 3, seg = (cc & 7) * 8;
                cpa16(sb0 + (uint32_t)(arr * A_AR + row * 144 + seg * 2),
                      srcs[arr] + (base + row) * 256 + hkv * 64 + seg);
            }
            CP_COMMIT();
        }

        for (int kt = 0; kt < ntiles; kt++) {
            if (kt + 1 < ntiles) {
                uint32_t sbl = sb0 + ((kt + 1) & 1) * A_STG;
                size_t base = (size_t)b * SS + (kt + 1) * 64;
                #pragma unroll
                for (int i = 0; i < 4; i++) {
                    int c = t + i * 256;
                    int arr = c >> 9, cc = c & 511, row = cc >> 3, seg = (cc & 7) * 8;
                    cpa16(sbl + (uint32_t)(arr * A_AR + row * 144 + seg * 2),
                          srcs[arr] + (base + row) * 256 + hkv * 64 + seg);
                }
                CP_COMMIT();
                CP_WAIT(1);
            } else {
                CP_WAIT(0);
            }
            __syncthreads();

            uint32_t sb = sb0 + (kt & 1) * A_STG;
            uint32_t aK = sb, aV = sb + A_AR;

            // ---- S = (Qh+Ql) K^T  (2-pass) ----
            float sacc[8][4];
            #pragma unroll
            for (int nt = 0; nt < 8; nt++)
                #pragma unroll
                for (int e = 0; e < 4; e++) sacc[nt][e] = 0.f;

            #pragma unroll
            for (int kc = 0; kc < 4; kc++) {
                int bcol = kc * 16 + (lane & 8);
                #pragma unroll
                for (int nt = 0; nt < 8; nt++) {
                    uint32_t bk[2];
                    uint32_t off = (uint32_t)((nt * 8 + (lane & 7)) * 144 + bcol * 2);
                    ldsm2(bk, aK + off);
                    mmah(sacc[nt], qh[kc], bk);
                    mmah(sacc[nt], ql[kc], bk);
                }
            }

            #pragma unroll
            for (int nt = 0; nt < 8; nt++)
                #pragma unroll
                for (int e = 0; e < 4; e++) sacc[nt][e] *= 0.125f;

            if (kt >= 2 * jblk) {
                int cb2 = (kt - 2 * jblk) * 64;
                int rloc = wid * 16 + (lane >> 2);
                #pragma unroll
                for (int nt = 0; nt < 8; nt++) {
                    int cl = cb2 + nt * 8 + (lane & 3) * 2;
                    if (cl     > rloc)     sacc[nt][0] = -1e30f;
                    if (cl + 1 > rloc)     sacc[nt][1] = -1e30f;
                    if (cl     > rloc + 8) sacc[nt][2] = -1e30f;
                    if (cl + 1 > rloc + 8) sacc[nt][3] = -1e30f;
                }
            }

            // ---- online softmax ----
            float mx0 = -1e30f, mx1 = -1e30f;
            #pragma unroll
            for (int nt = 0; nt < 8; nt++) {
                mx0 = fmaxf(mx0, fmaxf(sacc[nt][0], sacc[nt][1]));
                mx1 = fmaxf(mx1, fmaxf(sacc[nt][2], sacc[nt][3]));
            }
            mx0 = fmaxf(mx0, __shfl_xor_sync(0xFFFFFFFFu, mx0, 1));
            mx0 = fmaxf(mx0, __shfl_xor_sync(0xFFFFFFFFu, mx0, 2));
            mx1 = fmaxf(mx1, __shfl_xor_sync(0xFFFFFFFFu, mx1, 1));
            mx1 = fmaxf(mx1, __shfl_xor_sync(0xFFFFFFFFu, mx1, 2));

            float mn0 = fmaxf(m0, mx0), mn1 = fmaxf(m1, mx1);
            float cr0 = __expf(m0 - mn0), cr1 = __expf(m1 - mn1);
            float rs0 = 0.f, rs1 = 0.f;
            #pragma unroll
            for (int nt = 0; nt < 8; nt++) {
                float p0 = __expf(sacc[nt][0] - mn0);
                float p1 = __expf(sacc[nt][1] - mn0);
                float p2 = __expf(sacc[nt][2] - mn1);
                float p3 = __expf(sacc[nt][3] - mn1);
                sacc[nt][0] = p0; sacc[nt][1] = p1; sacc[nt][2] = p2; sacc[nt][3] = p3;
                rs0 += p0 + p1; rs1 += p2 + p3;
            }
            rs0 += __shfl_xor_sync(0xFFFFFFFFu, rs0, 1);
            rs0 += __shfl_xor_sync(0xFFFFFFFFu, rs0, 2);
            rs1 += __shfl_xor_sync(0xFFFFFFFFu, rs1, 1);
            rs1 += __shfl_xor_sync(0xFFFFFFFFu, rs1, 2);
            l0 = l0 * cr0 + rs0; l1 = l1 * cr1 + rs1;
            m0 = mn0; m1 = mn1;
            #pragma unroll
            for (int nt = 0; nt < 8; nt++) {
                accO[nt][0] *= cr0; accO[nt][1] *= cr0;
                accO[nt][2] *= cr1; accO[nt][3] *= cr1;
            }

            // ---- O += (Ph+Pl) V  (2-pass) ----
            #pragma unroll
            for (int kc = 0; kc < 4; kc++) {
                uint32_t ph[4], pl[4];
                {
                    float p00 = sacc[2*kc][0],   p01 = sacc[2*kc][1];
                    float p10 = sacc[2*kc][2],   p11 = sacc[2*kc][3];
                    float p20 = sacc[2*kc+1][0], p21 = sacc[2*kc+1][1];
                    float p30 = sacc[2*kc+1][2], p31 = sacc[2*kc+1][3];
                    ph[0] = packh(p00, p01); ph[1] = packh(p10, p11);
                    ph[2] = packh(p20, p21); ph[3] = packh(p30, p31);
                    float h00 = __half2float(__float2half(p00));
                    float h01 = __half2float(__float2half(p01));
                    float h10 = __half2float(__float2half(p10));
                    float h11 = __half2float(__float2half(p11));
                    float h20 = __half2float(__float2half(p20));
                    float h21 = __half2float(__float2half(p21));
                    float h30 = __half2float(__float2half(p30));
                    float h31 = __half2float(__float2half(p31));
                    pl[0] = packh(p00 - h00, p01 - h01);
                    pl[1] = packh(p10 - h10, p11 - h11);
                    pl[2] = packh(p20 - h20, p21 - h21);
                    pl[3] = packh(p30 - h30, p31 - h31);
                }
                int vrow = kc * 16 + (lane & 15);
                #pragma unroll
                for (int nt = 0; nt < 8; nt++) {
                    uint32_t vv[2];
                    uint32_t off = (uint32_t)(vrow * 144 + nt * 16);
                    ldsm2t(vv, aV + off);
                    mmah(accO[nt], ph, vv);
                    mmah(accO[nt], pl, vv);
                }
            }
            __syncthreads();
        }

        // ---- epilogue: exact fp16 hi/lo split of Y ----
        float inv0 = 1.f / l0, inv1 = 1.f / l1;
        int r0 = wid * 16 + (lane >> 2);
        #pragma unroll
        for (int nt = 0; nt < 8; nt++) {
            int col = h * 64 + nt * 8 + (lane & 3) * 2;
            float v00 = accO[nt][0] * inv0, v01 = accO[nt][1] * inv0;
            float v10 = accO[nt][2] * inv1, v11 = accO[nt][3] * inv1;
            float h00 = __half2float(__float2half(v00));
            float h01 = __half2float(__float2half(v01));
            float h10 = __half2float(__float2half(v10));
            float h11 = __half2float(__float2half(v11));
            size_t i0 = (tok0 + r0) * 1024 + col;
            size_t i1 = (tok0 + r0 + 8) * 1024 + col;
            *(uint32_t*)&g_Yhi[i0] = packh(v00, v01);
            *(uint32_t*)&g_Ylo[i0] = packh(v00 - h00, v01 - h01);
            *(uint32_t*)&g_Yhi[i1] = packh(v10, v11);
            *(uint32_t*)&g_Ylo[i1] = packh(v10 - h10, v11 - h11);
        }
        __syncthreads();
    }
}

// ---------------------------------------------------------------------------
extern "C" void kernel_launch(void* const* d_in, const int* in_sizes, int n_in,
                              void* d_out, int out_size)
{
    const float* x     = (const float*)d_in[0];
    const float* ve    = (const float*)d_in[1];
    const float* cosb  = (const float*)d_in[2];
    const float* sinb  = (const float*)d_in[3];
    const float* Wq    = (const float*)d_in[5];
    const float* Wk    = (const float*)d_in[6];
    const float* Wv    = (const float*)d_in[7];
    const float* Wproj = (const float*)d_in[8];
    const float* Wgate = (const float*)d_in[9];
    float* out = (float*)d_out;

    __half *Xhi, *Xlo;
    cudaGetSymbolAddress((void**)&Xhi, g_Xhi);
    cudaGetSymbolAddress((void**)&Xlo, g_Xlo);

    static bool attr_set = false;
    if (!attr_set) {
        cudaFuncSetAttribute(qkv_gemm_mma, cudaFuncAttributeMaxDynamicSharedMemorySize, G_SMEM);
        cudaFuncSetAttribute(proj_gemm_mma, cudaFuncAttributeMaxDynamicSharedMemorySize, G_SMEM);
        cudaFuncSetAttribute(attn_mma, cudaFuncAttributeMaxDynamicSharedMemorySize, A_SMEM);
        attr_set = true;
    }

    split_x<<<(TOKENS*EE/4 + 255)/256, 256>>>(x, Xhi, Xlo, TOKENS*EE/4);
    round_weights<<<(655360 + 255)/256, 256>>>(Wq, Wk, Wv, Wproj);

    dim3 g1(12, 32);
    qkv_gemm_mma<<<g1, 256, G_SMEM>>>();

    postproc<<<TOKENS, 128>>>(x, ve, cosb, sinb, Wgate);

    dim3 g3(8, NH, BB);
    attn_mma<<<g3, 256, A_SMEM>>>();

    dim3 g4(8, 32);
    proj_gemm_mma<<<g4, 256, G_SMEM>>>(out);
}

// round 9
// speedup vs baseline: 10.7940x; 1.3400x over previous
#include <cuda_runtime.h>
#include <cuda_fp16.h>
#include <cstdint>

#define BB 2
#define SS 2048
#define EE 1024
#define NH 16
#define NKV 4
#define HD 64
#define TOKENS (BB*SS)

__device__ float g_Q[TOKENS * NH * HD];
__device__ float g_K[TOKENS * NKV * HD];
__device__ float g_V[TOKENS * NKV * HD];

// fp16 operands: X split exactly (hi+lo); everything else rounded once
__device__ __half g_Xhi[TOKENS * EE], g_Xlo[TOKENS * EE];
__device__ __half g_Wh[1536 * EE];                    // [Wq;Wk;Wv] rounded
__device__ __half g_Ph[EE * EE];                      // Wproj rounded
__device__ __half g_Yh[TOKENS * EE];                  // attention out, rounded
__device__ __half g_Qh[TOKENS * NH * HD];             // rounded
__device__ __half g_Kh[TOKENS * NKV * HD];            // rounded
__device__ __half g_Vh[TOKENS * NKV * HD];            // rounded

// ---- PTX helpers (baseline features only) ----
__device__ __forceinline__ uint32_t smem_u32(const void* p) {
    uint32_t a;
    asm("{ .reg .u64 t; cvta.to.shared.u64 t, %1; cvt.u32.u64 %0, t; }" : "=r"(a) : "l"(p));
    return a;
}
__device__ __forceinline__ void ldsm4(uint32_t r[4], uint32_t a) {
    asm volatile("ldmatrix.sync.aligned.m8n8.x4.shared.b16 {%0,%1,%2,%3}, [%4];"
        : "=r"(r[0]), "=r"(r[1]), "=r"(r[2]), "=r"(r[3]) : "r"(a));
}
__device__ __forceinline__ void ldsm2(uint32_t r[2], uint32_t a) {
    asm volatile("ldmatrix.sync.aligned.m8n8.x2.shared.b16 {%0,%1}, [%2];"
        : "=r"(r[0]), "=r"(r[1]) : "r"(a));
}
__device__ __forceinline__ void ldsm2t(uint32_t r[2], uint32_t a) {
    asm volatile("ldmatrix.sync.aligned.m8n8.x2.trans.shared.b16 {%0,%1}, [%2];"
        : "=r"(r[0]), "=r"(r[1]) : "r"(a));
}
__device__ __forceinline__ void mmah(float d[4], const uint32_t a[4], const uint32_t b[2]) {
    asm volatile("mma.sync.aligned.m16n8k16.row.col.f32.f16.f16.f32 "
        "{%0,%1,%2,%3}, {%4,%5,%6,%7}, {%8,%9}, {%0,%1,%2,%3};"
        : "+f"(d[0]), "+f"(d[1]), "+f"(d[2]), "+f"(d[3])
        : "r"(a[0]), "r"(a[1]), "r"(a[2]), "r"(a[3]), "r"(b[0]), "r"(b[1]));
}
__device__ __forceinline__ uint32_t packh(float e, float o) {
    uint32_t r; asm("cvt.rn.f16x2.f32 %0, %1, %2;" : "=r"(r) : "f"(o), "f"(e)); return r;
}
__device__ __forceinline__ void cpa16(uint32_t dst, const void* src) {
    asm volatile("cp.async.cg.shared.global [%0], [%1], 16;" :: "r"(dst), "l"(src));
}
#define CP_COMMIT() asm volatile("cp.async.commit_group;" ::: "memory")
#define CP_WAIT(n)  asm volatile("cp.async.wait_group %0;" :: "n"(n) : "memory")

// ---------------------------------------------------------------------------
__global__ __launch_bounds__(256) void split_x(
    const float* __restrict__ src, __half* __restrict__ hi,
    __half* __restrict__ lo, int n4)
{
    int i = blockIdx.x * 256 + threadIdx.x;
    if (i >= n4) return;
    float4 v = *(const float4*)(src + (size_t)i * 4);
    float f[4] = {v.x, v.y, v.z, v.w};
    __half h[4], l[4];
    #pragma unroll
    for (int e = 0; e < 4; e++) {
        h[e] = __float2half(f[e]);
        l[e] = __float2half(f[e] - __half2float(h[e]));
    }
    *(uint2*)(hi + (size_t)i * 4) = *(uint2*)h;
    *(uint2*)(lo + (size_t)i * 4) = *(uint2*)l;
}

__global__ __launch_bounds__(256) void round_weights(
    const float* __restrict__ Wq, const float* __restrict__ Wk,
    const float* __restrict__ Wv, const float* __restrict__ Wp)
{
    int i = blockIdx.x * 256 + threadIdx.x;
    const float* src; __half* dst; size_t off, s4;
    if (i < 262144)      { src = Wq; dst = g_Wh; off = (size_t)i;            s4 = (size_t)i; }
    else if (i < 327680) { src = Wk; dst = g_Wh; off = (size_t)i;            s4 = (size_t)(i - 262144); }
    else if (i < 393216) { src = Wv; dst = g_Wh; off = (size_t)i;            s4 = (size_t)(i - 327680); }
    else if (i < 655360) { src = Wp; dst = g_Ph; off = (size_t)(i - 393216); s4 = (size_t)(i - 393216); }
    else return;
    float4 v = *(const float4*)(src + s4 * 4);
    __half h[4] = { __float2half(v.x), __float2half(v.y),
                    __float2half(v.z), __float2half(v.w) };
    *(uint2*)(dst + off * 4) = *(uint2*)h;
}

// ---------------------------------------------------------------------------
// fp16 HMMA GEMM, 128x128 tile, cp.async 2-stage.
// TWOA=true: C = (Ah+Al) @ B^T (2-pass); false: C = Ah @ B^T (1-pass).
// ---------------------------------------------------------------------------
#define G_AR 10240

template<bool TWOA>
__device__ __forceinline__ void mma_gemm(
    const __half* __restrict__ Ahi, const __half* __restrict__ Alo,
    const __half* __restrict__ Bh,
    float* __restrict__ Cb, int ldc, int m0)
{
    constexpr int NARR = TWOA ? 3 : 2;
    constexpr int STG  = NARR * G_AR;
    extern __shared__ char smdyn[];
    uint32_t sb0 = smem_u32(smdyn);

    int t = threadIdx.x;
    int wid = t >> 5, lane = t & 31;
    int wr = wid >> 2, wc = wid & 3;

    const __half* srcs[NARR];
    srcs[0] = Ahi + (size_t)m0 * 1024;
    if (TWOA) { srcs[1] = Alo + (size_t)m0 * 1024; srcs[NARR - 1] = Bh; }
    else      { srcs[1] = Bh; }

    float acc[4][4][4];
    #pragma unroll
    for (int mt = 0; mt < 4; mt++)
        #pragma unroll
        for (int nt = 0; nt < 4; nt++)
            #pragma unroll
            for (int e = 0; e < 4; e++) acc[mt][nt][e] = 0.f;

    {
        #pragma unroll
        for (int i = 0; i < NARR * 2; i++) {
            int c = t + i * 256;
            int arr = c >> 9, cc = c & 511, row = cc >> 2, seg = (cc & 3) * 8;
            cpa16(sb0 + (uint32_t)(arr * G_AR + row * 80 + seg * 2),
                  srcs[arr] + (size_t)row * 1024 + seg);
        }
        CP_COMMIT();
    }

    for (int it = 0; it < 32; it++) {
        if (it + 1 < 32) {
            uint32_t base = sb0 + ((it + 1) & 1) * STG;
            int k0 = (it + 1) * 32;
            #pragma unroll
            for (int i = 0; i < NARR * 2; i++) {
                int c = t + i * 256;
                int arr = c >> 9, cc = c & 511, row = cc >> 2, seg = (cc & 3) * 8;
                cpa16(base + (uint32_t)(arr * G_AR + row * 80 + seg * 2),
                      srcs[arr] + (size_t)row * 1024 + k0 + seg);
            }
            CP_COMMIT();
            CP_WAIT(1);
        } else {
            CP_WAIT(0);
        }
        __syncthreads();

        uint32_t sb = sb0 + (it & 1) * STG;
        uint32_t aAh = sb, aAl = sb + G_AR, aB = sb + (NARR - 1) * G_AR;

        #pragma unroll
        for (int ks = 0; ks < 2; ks++) {
            int kk = ks * 16;
            uint32_t fAh[4][4], fAl[4][4], fB[4][2];
            int arow = lane & 15;
            int acol = kk + (lane >> 4) * 8;
            #pragma unroll
            for (int mt = 0; mt < 4; mt++) {
                uint32_t off = (uint32_t)((wr * 64 + mt * 16 + arow) * 80 + acol * 2);
                ldsm4(fAh[mt], aAh + off);
                if (TWOA) ldsm4(fAl[mt], aAl + off);
            }
            int brow = lane & 7;
            int bcol = kk + (lane & 8);
            #pragma unroll
            for (int nt = 0; nt < 4; nt++) {
                uint32_t off = (uint32_t)((wc * 32 + nt * 8 + brow) * 80 + bcol * 2);
                ldsm2(fB[nt], aB + off);
            }
            #pragma unroll
            for (int mt = 0; mt < 4; mt++)
                #pragma unroll
                for (int nt = 0; nt < 4; nt++) {
                    mmah(acc[mt][nt], fAh[mt], fB[nt]);
                    if (TWOA) mmah(acc[mt][nt], fAl[mt], fB[nt]);
                }
        }
        __syncthreads();
    }

    #pragma unroll
    for (int mt = 0; mt < 4; mt++)
        #pragma unroll
        for (int nt = 0; nt < 4; nt++) {
            int r0 = m0 + wr * 64 + mt * 16 + (lane >> 2);
            int c0 = wc * 32 + nt * 8 + (lane & 3) * 2;
            float2 w0; w0.x = acc[mt][nt][0]; w0.y = acc[mt][nt][1];
            float2 w1; w1.x = acc[mt][nt][2]; w1.y = acc[mt][nt][3];
            *(float2*)&Cb[(size_t)r0 * ldc + c0]       = w0;
            *(float2*)&Cb[(size_t)(r0 + 8) * ldc + c0] = w1;
        }
}

#define G_SMEM3 (2 * 3 * G_AR)
#define G_SMEM2 (2 * 2 * G_AR)

__global__ __launch_bounds__(256) void qkv_gemm_mma()
{
    int n0 = blockIdx.x * 128;
    int m0 = blockIdx.y * 128;
    float* Cb; int ldc;
    if (n0 < 1024)      { Cb = g_Q + n0;          ldc = 1024; }
    else if (n0 < 1280) { Cb = g_K + (n0 - 1024); ldc = 256;  }
    else                { Cb = g_V + (n0 - 1280); ldc = 256;  }
    mma_gemm<true>(g_Xhi, g_Xlo, g_Wh + (size_t)n0 * 1024, Cb, ldc, m0);
}

__global__ __launch_bounds__(256) void proj_gemm_mma(float* __restrict__ out)
{
    int n0 = blockIdx.x * 128;
    int m0 = blockIdx.y * 128;
    mma_gemm<false>(g_Yh, nullptr, g_Ph + (size_t)n0 * 1024, out + n0, 1024, m0);
}

// ---------------------------------------------------------------------------
__global__ __launch_bounds__(128) void postproc(
    const float* __restrict__ x, const float* __restrict__ ve,
    const float* __restrict__ cosb, const float* __restrict__ sinb,
    const float* __restrict__ Wgate)
{
    int tok = blockIdx.x;
    int s = tok & (SS - 1);
    int t = threadIdx.x;
    int w = t >> 5;
    int lane = t & 31;

    __shared__ float gate[4];
    __shared__ float x12[12];

    if (t < 12) x12[t] = x[(size_t)tok * EE + t];
    __syncthreads();
    if (t < 4) {
        float acc = 0.f;
        #pragma unroll
        for (int c = 0; c < 12; c++) acc += x12[c] * Wgate[t * 12 + c];
        gate[t] = 3.f / (1.f + __expf(-acc));
    }
    __syncthreads();

    for (int i = t; i < 256; i += 128) {
        int hh = i >> 6;
        float v = g_V[(size_t)tok * 256 + i] + gate[hh] * ve[(size_t)tok * 256 + i];
        g_Vh[(size_t)tok * 256 + i] = __float2half(v);
    }

    const float EPS = 1.1920929e-7f;
    float cv = cosb[s * 32 + lane];
    float sv = sinb[s * 32 + lane];

    #pragma unroll
    for (int i = 0; i < 4; i++) {
        int h = w + 4 * i;
        const float* qp = &g_Q[(size_t)tok * 1024 + h * 64];
        float x1 = qp[lane], x2 = qp[lane + 32];
        float r1 =  x1 * cv + x2 * sv;
        float r2 = -x1 * sv + x2 * cv;
        float ss = r1 * r1 + r2 * r2;
        #pragma unroll
        for (int o = 16; o; o >>= 1) ss += __shfl_xor_sync(0xFFFFFFFFu, ss, o);
        float scale = rsqrtf(ss * (1.f / 64.f) + EPS) * 1.2f;
        size_t base = (size_t)tok * 1024 + h * 64;
        g_Qh[base + lane]      = __float2half(r1 * scale);
        g_Qh[base + lane + 32] = __float2half(r2 * scale);
    }
    {
        const float* kp = &g_K[(size_t)tok * 256 + w * 64];
        float x1 = kp[lane], x2 = kp[lane + 32];
        float r1 =  x1 * cv + x2 * sv;
        float r2 = -x1 * sv + x2 * cv;
        float ss = r1 * r1 + r2 * r2;
        #pragma unroll
        for (int o = 16; o; o >>= 1) ss += __shfl_xor_sync(0xFFFFFFFFu, ss, o);
        float scale = rsqrtf(ss * (1.f / 64.f) + EPS) * 1.2f;
        size_t base = (size_t)tok * 256 + w * 64;
        g_Kh[base + lane]      = __float2half(r1 * scale);
        g_Kh[base + lane + 32] = __float2half(r2 * scale);
    }
}

// ---------------------------------------------------------------------------
// Flash attention, fp16 single-pass QK and PV. Grid (8, NH, BB), 256 threads.
// CTA does q-blocks {15-p, p} (uniform 34 tiles). 2-stage cp.async K/V.
// ---------------------------------------------------------------------------
#define A_AR   9216
#define A_STG  (2 * A_AR)
#define A_SMEM (2 * A_STG)

__global__ __launch_bounds__(256) void attn_mma()
{
    extern __shared__ char smdyn[];
    uint32_t sb0 = smem_u32(smdyn);

    int p  = blockIdx.x;
    int h  = blockIdx.y;
    int b  = blockIdx.z;
    int hkv = h >> 2;
    int t = threadIdx.x;
    int wid = t >> 5, lane = t & 31;

    const __half* srcs[2] = { g_Kh, g_Vh };

    #pragma unroll 1
    for (int bi = 0; bi < 2; bi++) {
        int jblk = bi ? p : (15 - p);
        size_t tok0 = (size_t)b * SS + jblk * 128;
        int ntiles = 2 * jblk + 2;

        // ---- stage Q, build persistent fragments ----
        for (int idx = t; idx < 1024; idx += 256) {
            int row = idx >> 3, ch = (idx & 7) * 8;
            size_t g = (tok0 + row) * 1024 + h * 64 + ch;
            *(uint4*)(smdyn + row * 144 + ch * 2) = *(const uint4*)&g_Qh[g];
        }
        __syncthreads();

        uint32_t qh[4][4];
        {
            int arow = wid * 16 + (lane & 15);
            int acol = (lane >> 4) * 8;
            #pragma unroll
            for (int kc = 0; kc < 4; kc++) {
                uint32_t off = (uint32_t)(arow * 144 + (kc * 16 + acol) * 2);
                ldsm4(qh[kc], sb0 + off);
            }
        }
        __syncthreads();

        float accO[8][4];
        #pragma unroll
        for (int nt = 0; nt < 8; nt++)
            #pragma unroll
            for (int e = 0; e < 4; e++) accO[nt][e] = 0.f;
        float m0 = -1e30f, m1 = -1e30f, l0 = 0.f, l1 = 0.f;

        {
            size_t base = (size_t)b * SS;
            #pragma unroll
            for (int i = 0; i < 4; i++) {
                int c = t + i * 256;
                int arr = c >> 9, cc = c & 511, row = cc >> 3, seg = (cc & 7) * 8;
                cpa16(sb0 + (uint32_t)(arr * A_AR + row * 144 + seg * 2),
                      srcs[arr] + (base + row) * 256 + hkv * 64 + seg);
            }
            CP_COMMIT();
        }

        for (int kt = 0; kt < ntiles; kt++) {
            if (kt + 1 < ntiles) {
                uint32_t sbl = sb0 + ((kt + 1) & 1) * A_STG;
                size_t base = (size_t)b * SS + (kt + 1) * 64;
                #pragma unroll
                for (int i = 0; i < 4; i++) {
                    int c = t + i * 256;
                    int arr = c >> 9, cc = c & 511, row = cc >> 3, seg = (cc & 7) * 8;
                    cpa16(sbl + (uint32_t)(arr * A_AR + row * 144 + seg * 2),
                          srcs[arr] + (base + row) * 256 + hkv * 64 + seg);
                }
                CP_COMMIT();
                CP_WAIT(1);
            } else {
                CP_WAIT(0);
            }
            __syncthreads();

            uint32_t sb = sb0 + (kt & 1) * A_STG;
            uint32_t aK = sb, aV = sb + A_AR;

            // ---- S = Q K^T (single pass) ----
            float sacc[8][4];
            #pragma unroll
            for (int nt = 0; nt < 8; nt++)
                #pragma unroll
                for (int e = 0; e < 4; e++) sacc[nt][e] = 0.f;

            #pragma unroll
            for (int kc = 0; kc < 4; kc++) {
                int bcol = kc * 16 + (lane & 8);
                #pragma unroll
                for (int nt = 0; nt < 8; nt++) {
                    uint32_t bk[2];
                    uint32_t off = (uint32_t)((nt * 8 + (lane & 7)) * 144 + bcol * 2);
                    ldsm2(bk, aK + off);
                    mmah(sacc[nt], qh[kc], bk);
                }
            }

            #pragma unroll
            for (int nt = 0; nt < 8; nt++)
                #pragma unroll
                for (int e = 0; e < 4; e++) sacc[nt][e] *= 0.125f;

            if (kt >= 2 * jblk) {
                int cb2 = (kt - 2 * jblk) * 64;
                int rloc = wid * 16 + (lane >> 2);
                #pragma unroll
                for (int nt = 0; nt < 8; nt++) {
                    int cl = cb2 + nt * 8 + (lane & 3) * 2;
                    if (cl     > rloc)     sacc[nt][0] = -1e30f;
                    if (cl + 1 > rloc)     sacc[nt][1] = -1e30f;
                    if (cl     > rloc + 8) sacc[nt][2] = -1e30f;
                    if (cl + 1 > rloc + 8) sacc[nt][3] = -1e30f;
                }
            }

            // ---- online softmax ----
            float mx0 = -1e30f, mx1 = -1e30f;
            #pragma unroll
            for (int nt = 0; nt < 8; nt++) {
                mx0 = fmaxf(mx0, fmaxf(sacc[nt][0], sacc[nt][1]));
                mx1 = fmaxf(mx1, fmaxf(sacc[nt][2], sacc[nt][3]));
            }
            mx0 = fmaxf(mx0, __shfl_xor_sync(0xFFFFFFFFu, mx0, 1));
            mx0 = fmaxf(mx0, __shfl_xor_sync(0xFFFFFFFFu, mx0, 2));
            mx1 = fmaxf(mx1, __shfl_xor_sync(0xFFFFFFFFu, mx1, 1));
            mx1 = fmaxf(mx1, __shfl_xor_sync(0xFFFFFFFFu, mx1, 2));

            float mn0 = fmaxf(m0, mx0), mn1 = fmaxf(m1, mx1);
            float cr0 = __expf(m0 - mn0), cr1 = __expf(m1 - mn1);
            float rs0 = 0.f, rs1 = 0.f;
            #pragma unroll
            for (int nt = 0; nt < 8; nt++) {
                float p0 = __expf(sacc[nt][0] - mn0);
                float p1 = __expf(sacc[nt][1] - mn0);
                float p2 = __expf(sacc[nt][2] - mn1);
                float p3 = __expf(sacc[nt][3] - mn1);
                sacc[nt][0] = p0; sacc[nt][1] = p1; sacc[nt][2] = p2; sacc[nt][3] = p3;
                rs0 += p0 + p1; rs1 += p2 + p3;
            }
            rs0 += __shfl_xor_sync(0xFFFFFFFFu, rs0, 1);
            rs0 += __shfl_xor_sync(0xFFFFFFFFu, rs0, 2);
            rs1 += __shfl_xor_sync(0xFFFFFFFFu, rs1, 1);
            rs1 += __shfl_xor_sync(0xFFFFFFFFu, rs1, 2);
            l0 = l0 * cr0 + rs0; l1 = l1 * cr1 + rs1;
            m0 = mn0; m1 = mn1;
            #pragma unroll
            for (int nt = 0; nt < 8; nt++) {
                accO[nt][0] *= cr0; accO[nt][1] *= cr0;
                accO[nt][2] *= cr1; accO[nt][3] *= cr1;
            }

            // ---- O += P V (single pass, P rounded) ----
            #pragma unroll
            for (int kc = 0; kc < 4; kc++) {
                uint32_t ph[4];
                ph[0] = packh(sacc[2*kc][0],   sacc[2*kc][1]);
                ph[1] = packh(sacc[2*kc][2],   sacc[2*kc][3]);
                ph[2] = packh(sacc[2*kc+1][0], sacc[2*kc+1][1]);
                ph[3] = packh(sacc[2*kc+1][2], sacc[2*kc+1][3]);
                int vrow = kc * 16 + (lane & 15);
                #pragma unroll
                for (int nt = 0; nt < 8; nt++) {
                    uint32_t vv[2];
                    uint32_t off = (uint32_t)(vrow * 144 + nt * 16);
                    ldsm2t(vv, aV + off);
                    mmah(accO[nt], ph, vv);
                }
            }
            __syncthreads();
        }

        // ---- epilogue: write rounded fp16 Y ----
        float inv0 = 1.f / l0, inv1 = 1.f / l1;
        int r0 = wid * 16 + (lane >> 2);
        #pragma unroll
        for (int nt = 0; nt < 8; nt++) {
            int col = h * 64 + nt * 8 + (lane & 3) * 2;
            size_t i0 = (tok0 + r0) * 1024 + col;
            size_t i1 = (tok0 + r0 + 8) * 1024 + col;
            *(uint32_t*)&g_Yh[i0] = packh(accO[nt][0] * inv0, accO[nt][1] * inv0);
            *(uint32_t*)&g_Yh[i1] = packh(accO[nt][2] * inv1, accO[nt][3] * inv1);
        }
        __syncthreads();
    }
}

// ---------------------------------------------------------------------------
extern "C" void kernel_launch(void* const* d_in, const int* in_sizes, int n_in,
                              void* d_out, int out_size)
{
    const float* x     = (const float*)d_in[0];
    const float* ve    = (const float*)d_in[1];
    const float* cosb  = (const float*)d_in[2];
    const float* sinb  = (const float*)d_in[3];
    const float* Wq    = (const float*)d_in[5];
    const float* Wk    = (const float*)d_in[6];
    const float* Wv    = (const float*)d_in[7];
    const float* Wproj = (const float*)d_in[8];
    const float* Wgate = (const float*)d_in[9];
    float* out = (float*)d_out;

    __half *Xhi, *Xlo;
    cudaGetSymbolAddress((void**)&Xhi, g_Xhi);
    cudaGetSymbolAddress((void**)&Xlo, g_Xlo);

    static bool attr_set = false;
    if (!attr_set) {
        cudaFuncSetAttribute(qkv_gemm_mma, cudaFuncAttributeMaxDynamicSharedMemorySize, G_SMEM3);
        cudaFuncSetAttribute(proj_gemm_mma, cudaFuncAttributeMaxDynamicSharedMemorySize, G_SMEM2);
        cudaFuncSetAttribute(attn_mma, cudaFuncAttributeMaxDynamicSharedMemorySize, A_SMEM);
        attr_set = true;
    }

    split_x<<<(TOKENS*EE/4 + 255)/256, 256>>>(x, Xhi, Xlo, TOKENS*EE/4);
    round_weights<<<(655360 + 255)/256, 256>>>(Wq, Wk, Wv, Wproj);

    dim3 g1(12, 32);
    qkv_gemm_mma<<<g1, 256, G_SMEM3>>>();

    postproc<<<TOKENS, 128>>>(x, ve, cosb, sinb, Wgate);

    dim3 g3(8, NH, BB);
    attn_mma<<<g3, 256, A_SMEM>>>();

    dim3 g4(8, 32);
    proj_gemm_mma<<<g4, 256, G_SMEM2>>>(out);
}

// round 10
// speedup vs baseline: 13.2356x; 1.2262x over previous
#include <cuda_runtime.h>
#include <cuda_fp16.h>
#include <cstdint>

#define BB 2
#define SS 2048
#define EE 1024
#define NH 16
#define NKV 4
#define HD 64
#define TOKENS (BB*SS)

__device__ float g_Q[TOKENS * NH * HD];
__device__ float g_K[TOKENS * NKV * HD];
__device__ float g_V[TOKENS * NKV * HD];

// fp16 operands, each rounded exactly once from fp32
__device__ __half g_Xh[TOKENS * EE];
__device__ __half g_Wh[1536 * EE];                    // [Wq;Wk;Wv]
__device__ __half g_Ph[EE * EE];                      // Wproj
__device__ __half g_Yh[TOKENS * EE];                  // attention out
__device__ __half g_Qh[TOKENS * NH * HD];
__device__ __half g_Kh[TOKENS * NKV * HD];
__device__ __half g_Vh[TOKENS * NKV * HD];

// ---- PTX helpers (baseline features only) ----
__device__ __forceinline__ uint32_t smem_u32(const void* p) {
    uint32_t a;
    asm("{ .reg .u64 t; cvta.to.shared.u64 t, %1; cvt.u32.u64 %0, t; }" : "=r"(a) : "l"(p));
    return a;
}
__device__ __forceinline__ void ldsm4(uint32_t r[4], uint32_t a) {
    asm volatile("ldmatrix.sync.aligned.m8n8.x4.shared.b16 {%0,%1,%2,%3}, [%4];"
        : "=r"(r[0]), "=r"(r[1]), "=r"(r[2]), "=r"(r[3]) : "r"(a));
}
__device__ __forceinline__ void ldsm4t(uint32_t r[4], uint32_t a) {
    asm volatile("ldmatrix.sync.aligned.m8n8.x4.trans.shared.b16 {%0,%1,%2,%3}, [%4];"
        : "=r"(r[0]), "=r"(r[1]), "=r"(r[2]), "=r"(r[3]) : "r"(a));
}
__device__ __forceinline__ void mmah(float d[4], const uint32_t a[4], const uint32_t b[2]) {
    asm volatile("mma.sync.aligned.m16n8k16.row.col.f32.f16.f16.f32 "
        "{%0,%1,%2,%3}, {%4,%5,%6,%7}, {%8,%9}, {%0,%1,%2,%3};"
        : "+f"(d[0]), "+f"(d[1]), "+f"(d[2]), "+f"(d[3])
        : "r"(a[0]), "r"(a[1]), "r"(a[2]), "r"(a[3]), "r"(b[0]), "r"(b[1]));
}
__device__ __forceinline__ uint32_t packh(float e, float o) {
    uint32_t r; asm("cvt.rn.f16x2.f32 %0, %1, %2;" : "=r"(r) : "f"(o), "f"(e)); return r;
}
__device__ __forceinline__ void cpa16(uint32_t dst, const void* src) {
    asm volatile("cp.async.cg.shared.global [%0], [%1], 16;" :: "r"(dst), "l"(src));
}
#define CP_COMMIT() asm volatile("cp.async.commit_group;" ::: "memory")
#define CP_WAIT(n)  asm volatile("cp.async.wait_group %0;" :: "n"(n) : "memory")

// ---------------------------------------------------------------------------
__global__ __launch_bounds__(256) void round_x(
    const float* __restrict__ src, __half* __restrict__ dst, int n4)
{
    int i = blockIdx.x * 256 + threadIdx.x;
    if (i >= n4) return;
    float4 v = *(const float4*)(src + (size_t)i * 4);
    __half h[4] = { __float2half(v.x), __float2half(v.y),
                    __float2half(v.z), __float2half(v.w) };
    *(uint2*)(dst + (size_t)i * 4) = *(uint2*)h;
}

__global__ __launch_bounds__(256) void round_weights(
    const float* __restrict__ Wq, const float* __restrict__ Wk,
    const float* __restrict__ Wv, const float* __restrict__ Wp)
{
    int i = blockIdx.x * 256 + threadIdx.x;
    const float* src; __half* dst; size_t off, s4;
    if (i < 262144)      { src = Wq; dst = g_Wh; off = (size_t)i;            s4 = (size_t)i; }
    else if (i < 327680) { src = Wk; dst = g_Wh; off = (size_t)i;            s4 = (size_t)(i - 262144); }
    else if (i < 393216) { src = Wv; dst = g_Wh; off = (size_t)i;            s4 = (size_t)(i - 327680); }
    else if (i < 655360) { src = Wp; dst = g_Ph; off = (size_t)(i - 393216); s4 = (size_t)(i - 393216); }
    else return;
    float4 v = *(const float4*)(src + s4 * 4);
    __half h[4] = { __float2half(v.x), __float2half(v.y),
                    __float2half(v.z), __float2half(v.w) };
    *(uint2*)(dst + off * 4) = *(uint2*)h;
}

// ---------------------------------------------------------------------------
// fp16 1-pass HMMA GEMM: C = A @ B^T, 128x128 tile, cp.async 2-stage.
// smem/stage: 2 arrays (A, B) x [128][40] halves = 20480 B.
// ---------------------------------------------------------------------------
#define G_AR   10240
#define G_STG  (2 * G_AR)
#define G_SMEM (2 * G_STG)

__device__ __forceinline__ void mma_gemm(
    const __half* __restrict__ A, const __half* __restrict__ B,
    float* __restrict__ Cb, int ldc, int m0)
{
    extern __shared__ char smdyn[];
    uint32_t sb0 = smem_u32(smdyn);

    int t = threadIdx.x;
    int wid = t >> 5, lane = t & 31;
    int wr = wid >> 2, wc = wid & 3;

    const __half* srcs[2] = { A + (size_t)m0 * 1024, B };

    float acc[4][4][4];
    #pragma unroll
    for (int mt = 0; mt < 4; mt++)
        #pragma unroll
        for (int nt = 0; nt < 4; nt++)
            #pragma unroll
            for (int e = 0; e < 4; e++) acc[mt][nt][e] = 0.f;

    {
        #pragma unroll
        for (int i = 0; i < 4; i++) {
            int c = t + i * 256;
            int arr = c >> 9, cc = c & 511, row = cc >> 2, seg = (cc & 3) * 8;
            cpa16(sb0 + (uint32_t)(arr * G_AR + row * 80 + seg * 2),
                  srcs[arr] + (size_t)row * 1024 + seg);
        }
        CP_COMMIT();
    }

    for (int it = 0; it < 32; it++) {
        if (it + 1 < 32) {
            uint32_t base = sb0 + ((it + 1) & 1) * G_STG;
            int k0 = (it + 1) * 32;
            #pragma unroll
            for (int i = 0; i < 4; i++) {
                int c = t + i * 256;
                int arr = c >> 9, cc = c & 511, row = cc >> 2, seg = (cc & 3) * 8;
                cpa16(base + (uint32_t)(arr * G_AR + row * 80 + seg * 2),
                      srcs[arr] + (size_t)row * 1024 + k0 + seg);
            }
            CP_COMMIT();
            CP_WAIT(1);
        } else {
            CP_WAIT(0);
        }
        __syncthreads();

        uint32_t sb = sb0 + (it & 1) * G_STG;
        uint32_t aA = sb, aB = sb + G_AR;

        #pragma unroll
        for (int ks = 0; ks < 2; ks++) {
            int kk = ks * 16;
            uint32_t fA[4][4], fB[4][2];
            int arow = lane & 15;
            int acol = kk + (lane >> 4) * 8;
            #pragma unroll
            for (int mt = 0; mt < 4; mt++) {
                uint32_t off = (uint32_t)((wr * 64 + mt * 16 + arow) * 80 + acol * 2);
                ldsm4(fA[mt], aA + off);
            }
            // paired B fragment loads: one ldsm4 covers nt, nt+1
            #pragma unroll
            for (int nt2 = 0; nt2 < 4; nt2 += 2) {
                int ntl = nt2 + (lane >> 4);     // lanes 0-15 -> nt2, 16-31 -> nt2+1
                uint32_t bk[4];
                uint32_t off = (uint32_t)((wc * 32 + ntl * 8 + (lane & 7)) * 80
                                          + (kk + (lane & 8)) * 2);
                ldsm4(bk, aB + off);
                fB[nt2][0] = bk[0];     fB[nt2][1] = bk[1];
                fB[nt2+1][0] = bk[2];   fB[nt2+1][1] = bk[3];
            }
            #pragma unroll
            for (int mt = 0; mt < 4; mt++)
                #pragma unroll
                for (int nt = 0; nt < 4; nt++)
                    mmah(acc[mt][nt], fA[mt], fB[nt]);
        }
        __syncthreads();
    }

    #pragma unroll
    for (int mt = 0; mt < 4; mt++)
        #pragma unroll
        for (int nt = 0; nt < 4; nt++) {
            int r0 = m0 + wr * 64 + mt * 16 + (lane >> 2);
            int c0 = wc * 32 + nt * 8 + (lane & 3) * 2;
            float2 w0; w0.x = acc[mt][nt][0]; w0.y = acc[mt][nt][1];
            float2 w1; w1.x = acc[mt][nt][2]; w1.y = acc[mt][nt][3];
            *(float2*)&Cb[(size_t)r0 * ldc + c0]       = w0;
            *(float2*)&Cb[(size_t)(r0 + 8) * ldc + c0] = w1;
        }
}

__global__ __launch_bounds__(256) void qkv_gemm_mma()
{
    int n0 = blockIdx.x * 128;
    int m0 = blockIdx.y * 128;
    float* Cb; int ldc;
    if (n0 < 1024)      { Cb = g_Q + n0;          ldc = 1024; }
    else if (n0 < 1280) { Cb = g_K + (n0 - 1024); ldc = 256;  }
    else                { Cb = g_V + (n0 - 1280); ldc = 256;  }
    mma_gemm(g_Xh, g_Wh + (size_t)n0 * 1024, Cb, ldc, m0);
}

__global__ __launch_bounds__(256) void proj_gemm_mma(float* __restrict__ out)
{
    int n0 = blockIdx.x * 128;
    int m0 = blockIdx.y * 128;
    mma_gemm(g_Yh, g_Ph + (size_t)n0 * 1024, out + n0, 1024, m0);
}

// ---------------------------------------------------------------------------
__global__ __launch_bounds__(128) void postproc(
    const float* __restrict__ x, const float* __restrict__ ve,
    const float* __restrict__ cosb, const float* __restrict__ sinb,
    const float* __restrict__ Wgate)
{
    int tok = blockIdx.x;
    int s = tok & (SS - 1);
    int t = threadIdx.x;
    int w = t >> 5;
    int lane = t & 31;

    __shared__ float gate[4];
    __shared__ float x12[12];

    if (t < 12) x12[t] = x[(size_t)tok * EE + t];
    __syncthreads();
    if (t < 4) {
        float acc = 0.f;
        #pragma unroll
        for (int c = 0; c < 12; c++) acc += x12[c] * Wgate[t * 12 + c];
        gate[t] = 3.f / (1.f + __expf(-acc));
    }
    __syncthreads();

    for (int i = t; i < 256; i += 128) {
        int hh = i >> 6;
        float v = g_V[(size_t)tok * 256 + i] + gate[hh] * ve[(size_t)tok * 256 + i];
        g_Vh[(size_t)tok * 256 + i] = __float2half(v);
    }

    const float EPS = 1.1920929e-7f;
    float cv = cosb[s * 32 + lane];
    float sv = sinb[s * 32 + lane];

    #pragma unroll
    for (int i = 0; i < 4; i++) {
        int h = w + 4 * i;
        const float* qp = &g_Q[(size_t)tok * 1024 + h * 64];
        float x1 = qp[lane], x2 = qp[lane + 32];
        float r1 =  x1 * cv + x2 * sv;
        float r2 = -x1 * sv + x2 * cv;
        float ss = r1 * r1 + r2 * r2;
        #pragma unroll
        for (int o = 16; o; o >>= 1) ss += __shfl_xor_sync(0xFFFFFFFFu, ss, o);
        float scale = rsqrtf(ss * (1.f / 64.f) + EPS) * 1.2f;
        size_t base = (size_t)tok * 1024 + h * 64;
        g_Qh[base + lane]      = __float2half(r1 * scale);
        g_Qh[base + lane + 32] = __float2half(r2 * scale);
    }
    {
        const float* kp = &g_K[(size_t)tok * 256 + w * 64];
        float x1 = kp[lane], x2 = kp[lane + 32];
        float r1 =  x1 * cv + x2 * sv;
        float r2 = -x1 * sv + x2 * cv;
        float ss = r1 * r1 + r2 * r2;
        #pragma unroll
        for (int o = 16; o; o >>= 1) ss += __shfl_xor_sync(0xFFFFFFFFu, ss, o);
        float scale = rsqrtf(ss * (1.f / 64.f) + EPS) * 1.2f;
        size_t base = (size_t)tok * 256 + w * 64;
        g_Kh[base + lane]      = __float2half(r1 * scale);
        g_Kh[base + lane + 32] = __float2half(r2 * scale);
    }
}

// ---------------------------------------------------------------------------
// Flash attention, fp16 single-pass, paired ldsm4. Grid (8, NH, BB), 256 thr.
// CTA does q-blocks {15-p, p} (uniform 34 tiles). 2-stage cp.async K/V.
// ---------------------------------------------------------------------------
#define A_AR   9216
#define A_STG  (2 * A_AR)
#define A_SMEM (2 * A_STG)

__global__ __launch_bounds__(256) void attn_mma()
{
    extern __shared__ char smdyn[];
    uint32_t sb0 = smem_u32(smdyn);

    int p  = blockIdx.x;
    int h  = blockIdx.y;
    int b  = blockIdx.z;
    int hkv = h >> 2;
    int t = threadIdx.x;
    int wid = t >> 5, lane = t & 31;

    const __half* srcs[2] = { g_Kh, g_Vh };

    #pragma unroll 1
    for (int bi = 0; bi < 2; bi++) {
        int jblk = bi ? p : (15 - p);
        size_t tok0 = (size_t)b * SS + jblk * 128;
        int ntiles = 2 * jblk + 2;

        // ---- stage Q, build persistent fragments ----
        for (int idx = t; idx < 1024; idx += 256) {
            int row = idx >> 3, ch = (idx & 7) * 8;
            size_t g = (tok0 + row) * 1024 + h * 64 + ch;
            *(uint4*)(smdyn + row * 144 + ch * 2) = *(const uint4*)&g_Qh[g];
        }
        __syncthreads();

        uint32_t qh[4][4];
        {
            int arow = wid * 16 + (lane & 15);
            int acol = (lane >> 4) * 8;
            #pragma unroll
            for (int kc = 0; kc < 4; kc++) {
                uint32_t off = (uint32_t)(arow * 144 + (kc * 16 + acol) * 2);
                ldsm4(qh[kc], sb0 + off);
            }
        }
        __syncthreads();

        float accO[8][4];
        #pragma unroll
        for (int nt = 0; nt < 8; nt++)
            #pragma unroll
            for (int e = 0; e < 4; e++) accO[nt][e] = 0.f;
        float m0 = -1e30f, m1 = -1e30f, l0 = 0.f, l1 = 0.f;

        {
            size_t base = (size_t)b * SS;
            #pragma unroll
            for (int i = 0; i < 4; i++) {
                int c = t + i * 256;
                int arr = c >> 9, cc = c & 511, row = cc >> 3, seg = (cc & 7) * 8;
                cpa16(sb0 + (uint32_t)(arr * A_AR + row * 144 + seg * 2),
                      srcs[arr] + (base + row) * 256 + hkv * 64 + seg);
            }
            CP_COMMIT();
        }

        for (int kt = 0; kt < ntiles; kt++) {
            if (kt + 1 < ntiles) {
                uint32_t sbl = sb0 + ((kt + 1) & 1) * A_STG;
                size_t base = (size_t)b * SS + (kt + 1) * 64;
                #pragma unroll
                for (int i = 0; i < 4; i++) {
                    int c = t + i * 256;
                    int arr = c >> 9, cc = c & 511, row = cc >> 3, seg = (cc & 7) * 8;
                    cpa16(sbl + (uint32_t)(arr * A_AR + row * 144 + seg * 2),
                          srcs[arr] + (base + row) * 256 + hkv * 64 + seg);
                }
                CP_COMMIT();
                CP_WAIT(1);
            } else {
                CP_WAIT(0);
            }
            __syncthreads();

            uint32_t sb = sb0 + (kt & 1) * A_STG;
            uint32_t aK = sb, aV = sb + A_AR;

            // ---- S = Q K^T (single pass, paired ldsm4) ----
            float sacc[8][4];
            #pragma unroll
            for (int nt = 0; nt < 8; nt++)
                #pragma unroll
                for (int e = 0; e < 4; e++) sacc[nt][e] = 0.f;

            #pragma unroll
            for (int kc = 0; kc < 4; kc++) {
                int kk = kc * 16;
                #pragma unroll
                for (int nt2 = 0; nt2 < 8; nt2 += 2) {
                    int ntl = nt2 + (lane >> 4);   // lanes 0-15: nt2, 16-31: nt2+1
                    uint32_t bk[4];
                    uint32_t off = (uint32_t)((ntl * 8 + (lane & 7)) * 144
                                              + (kk + (lane & 8)) * 2);
                    ldsm4(bk, aK + off);
                    mmah(sacc[nt2],     qh[kc], bk);
                    mmah(sacc[nt2 + 1], qh[kc], bk + 2);
                }
            }

            #pragma unroll
            for (int nt = 0; nt < 8; nt++)
                #pragma unroll
                for (int e = 0; e < 4; e++) sacc[nt][e] *= 0.125f;

            if (kt >= 2 * jblk) {
                int cb2 = (kt - 2 * jblk) * 64;
                int rloc = wid * 16 + (lane >> 2);
                #pragma unroll
                for (int nt = 0; nt < 8; nt++) {
                    int cl = cb2 + nt * 8 + (lane & 3) * 2;
                    if (cl     > rloc)     sacc[nt][0] = -1e30f;
                    if (cl + 1 > rloc)     sacc[nt][1] = -1e30f;
                    if (cl     > rloc + 8) sacc[nt][2] = -1e30f;
                    if (cl + 1 > rloc + 8) sacc[nt][3] = -1e30f;
                }
            }

            // ---- online softmax ----
            float mx0 = -1e30f, mx1 = -1e30f;
            #pragma unroll
            for (int nt = 0; nt < 8; nt++) {
                mx0 = fmaxf(mx0, fmaxf(sacc[nt][0], sacc[nt][1]));
                mx1 = fmaxf(mx1, fmaxf(sacc[nt][2], sacc[nt][3]));
            }
            mx0 = fmaxf(mx0, __shfl_xor_sync(0xFFFFFFFFu, mx0, 1));
            mx0 = fmaxf(mx0, __shfl_xor_sync(0xFFFFFFFFu, mx0, 2));
            mx1 = fmaxf(mx1, __shfl_xor_sync(0xFFFFFFFFu, mx1, 1));
            mx1 = fmaxf(mx1, __shfl_xor_sync(0xFFFFFFFFu, mx1, 2));

            float mn0 = fmaxf(m0, mx0), mn1 = fmaxf(m1, mx1);
            float cr0 = __expf(m0 - mn0), cr1 = __expf(m1 - mn1);
            float rs0 = 0.f, rs1 = 0.f;
            #pragma unroll
            for (int nt = 0; nt < 8; nt++) {
                float p0 = __expf(sacc[nt][0] - mn0);
                float p1 = __expf(sacc[nt][1] - mn0);
                float p2 = __expf(sacc[nt][2] - mn1);
                float p3 = __expf(sacc[nt][3] - mn1);
                sacc[nt][0] = p0; sacc[nt][1] = p1; sacc[nt][2] = p2; sacc[nt][3] = p3;
                rs0 += p0 + p1; rs1 += p2 + p3;
            }
            rs0 += __shfl_xor_sync(0xFFFFFFFFu, rs0, 1);
            rs0 += __shfl_xor_sync(0xFFFFFFFFu, rs0, 2);
            rs1 += __shfl_xor_sync(0xFFFFFFFFu, rs1, 1);
            rs1 += __shfl_xor_sync(0xFFFFFFFFu, rs1, 2);
            l0 = l0 * cr0 + rs0; l1 = l1 * cr1 + rs1;
            m0 = mn0; m1 = mn1;
            #pragma unroll
            for (int nt = 0; nt < 8; nt++) {
                accO[nt][0] *= cr0; accO[nt][1] *= cr0;
                accO[nt][2] *= cr1; accO[nt][3] *= cr1;
            }

            // ---- O += P V (single pass, paired ldsm4.trans) ----
            #pragma unroll
            for (int kc = 0; kc < 4; kc++) {
                uint32_t ph[4];
                ph[0] = packh(sacc[2*kc][0],   sacc[2*kc][1]);
                ph[1] = packh(sacc[2*kc][2],   sacc[2*kc][3]);
                ph[2] = packh(sacc[2*kc+1][0], sacc[2*kc+1][1]);
                ph[3] = packh(sacc[2*kc+1][2], sacc[2*kc+1][3]);
                int vrow = kc * 16 + (lane & 15);
                #pragma unroll
                for (int nt2 = 0; nt2 < 8; nt2 += 2) {
                    int ntl = nt2 + (lane >> 4);
                    uint32_t vv[4];
                    uint32_t off = (uint32_t)(vrow * 144 + ntl * 16);
                    ldsm4t(vv, aV + off);
                    mmah(accO[nt2],     ph, vv);
                    mmah(accO[nt2 + 1], ph, vv + 2);
                }
            }
            __syncthreads();
        }

        // ---- epilogue: write rounded fp16 Y ----
        float inv0 = 1.f / l0, inv1 = 1.f / l1;
        int r0 = wid * 16 + (lane >> 2);
        #pragma unroll
        for (int nt = 0; nt < 8; nt++) {
            int col = h * 64 + nt * 8 + (lane & 3) * 2;
            size_t i0 = (tok0 + r0) * 1024 + col;
            size_t i1 = (tok0 + r0 + 8) * 1024 + col;
            *(uint32_t*)&g_Yh[i0] = packh(accO[nt][0] * inv0, accO[nt][1] * inv0);
            *(uint32_t*)&g_Yh[i1] = packh(accO[nt][2] * inv1, accO[nt][3] * inv1);
        }
        __syncthreads();
    }
}

// ---------------------------------------------------------------------------
extern "C" void kernel_launch(void* const* d_in, const int* in_sizes, int n_in,
                              void* d_out, int out_size)
{
    const float* x     = (const float*)d_in[0];
    const float* ve    = (const float*)d_in[1];
    const float* cosb  = (const float*)d_in[2];
    const float* sinb  = (const float*)d_in[3];
    const float* Wq    = (const float*)d_in[5];
    const float* Wk    = (const float*)d_in[6];
    const float* Wv    = (const float*)d_in[7];
    const float* Wproj = (const float*)d_in[8];
    const float* Wgate = (const float*)d_in[9];
    float* out = (float*)d_out;

    __half* Xh;
    cudaGetSymbolAddress((void**)&Xh, g_Xh);

    static bool attr_set = false;
    if (!attr_set) {
        cudaFuncSetAttribute(qkv_gemm_mma, cudaFuncAttributeMaxDynamicSharedMemorySize, G_SMEM);
        cudaFuncSetAttribute(proj_gemm_mma, cudaFuncAttributeMaxDynamicSharedMemorySize, G_SMEM);
        cudaFuncSetAttribute(attn_mma, cudaFuncAttributeMaxDynamicSharedMemorySize, A_SMEM);
        attr_set = true;
    }

    round_x<<<(TOKENS*EE/4 + 255)/256, 256>>>(x, Xh, TOKENS*EE/4);
    round_weights<<<(655360 + 255)/256, 256>>>(Wq, Wk, Wv, Wproj);

    dim3 g1(12, 32);
    qkv_gemm_mma<<<g1, 256, G_SMEM>>>();

    postproc<<<TOKENS, 128>>>(x, ve, cosb, sinb, Wgate);

    dim3 g3(8, NH, BB);
    attn_mma<<<g3, 256, A_SMEM>>>();

    dim3 g4(8, 32);
    proj_gemm_mma<<<g4, 256, G_SMEM>>>(out);
}

// round 11
// speedup vs baseline: 13.9353x; 1.0529x over previous
#include <cuda_runtime.h>
#include <cuda_fp16.h>
#include <cstdint>

#define BB 2
#define SS 2048
#define EE 1024
#define NH 16
#define NKV 4
#define HD 64
#define TOKENS (BB*SS)

__device__ float g_Q[TOKENS * NH * HD];
__device__ float g_K[TOKENS * NKV * HD];
__device__ float g_V[TOKENS * NKV * HD];

// fp16 operands, each rounded exactly once from fp32
__device__ __half g_Xh[TOKENS * EE];
__device__ __half g_Wh[1536 * EE];                    // [Wq;Wk;Wv]
__device__ __half g_Ph[EE * EE];                      // Wproj
__device__ __half g_Yh[TOKENS * EE];                  // attention out
__device__ __half g_Qh[TOKENS * NH * HD];             // includes 1/8 score scale
__device__ __half g_Kh[TOKENS * NKV * HD];
__device__ __half g_Vh[TOKENS * NKV * HD];

// ---- PTX helpers (baseline features only) ----
__device__ __forceinline__ uint32_t smem_u32(const void* p) {
    uint32_t a;
    asm("{ .reg .u64 t; cvta.to.shared.u64 t, %1; cvt.u32.u64 %0, t; }" : "=r"(a) : "l"(p));
    return a;
}
__device__ __forceinline__ void ldsm4(uint32_t r[4], uint32_t a) {
    asm volatile("ldmatrix.sync.aligned.m8n8.x4.shared.b16 {%0,%1,%2,%3}, [%4];"
        : "=r"(r[0]), "=r"(r[1]), "=r"(r[2]), "=r"(r[3]) : "r"(a));
}
__device__ __forceinline__ void ldsm4t(uint32_t r[4], uint32_t a) {
    asm volatile("ldmatrix.sync.aligned.m8n8.x4.trans.shared.b16 {%0,%1,%2,%3}, [%4];"
        : "=r"(r[0]), "=r"(r[1]), "=r"(r[2]), "=r"(r[3]) : "r"(a));
}
__device__ __forceinline__ void mmah(float d[4], const uint32_t a[4], const uint32_t b[2]) {
    asm volatile("mma.sync.aligned.m16n8k16.row.col.f32.f16.f16.f32 "
        "{%0,%1,%2,%3}, {%4,%5,%6,%7}, {%8,%9}, {%0,%1,%2,%3};"
        : "+f"(d[0]), "+f"(d[1]), "+f"(d[2]), "+f"(d[3])
        : "r"(a[0]), "r"(a[1]), "r"(a[2]), "r"(a[3]), "r"(b[0]), "r"(b[1]));
}
__device__ __forceinline__ uint32_t packh(float e, float o) {
    uint32_t r; asm("cvt.rn.f16x2.f32 %0, %1, %2;" : "=r"(r) : "f"(o), "f"(e)); return r;
}
__device__ __forceinline__ void cpa16(uint32_t dst, const void* src) {
    asm volatile("cp.async.cg.shared.global [%0], [%1], 16;" :: "r"(dst), "l"(src));
}
#define CP_COMMIT() asm volatile("cp.async.commit_group;" ::: "memory")
#define CP_WAIT(n)  asm volatile("cp.async.wait_group %0;" :: "n"(n) : "memory")

// ---------------------------------------------------------------------------
// All fp32 -> fp16 roundings in ONE launch: X, Wq, Wk, Wv, Wproj.
// Chunks of 4 floats. Layout: X [0,1048576) | Wq | Wk | Wv | Wp.
// ---------------------------------------------------------------------------
__global__ __launch_bounds__(256) void round_all(
    const float* __restrict__ x,
    const float* __restrict__ Wq, const float* __restrict__ Wk,
    const float* __restrict__ Wv, const float* __restrict__ Wp)
{
    int i = blockIdx.x * 256 + threadIdx.x;
    const float* src; __half* dst; size_t off, s4;
    if (i < 1048576)      { src = x;  dst = g_Xh; off = (size_t)i;             s4 = (size_t)i; }
    else if (i < 1310720) { src = Wq; dst = g_Wh; off = (size_t)(i - 1048576); s4 = (size_t)(i - 1048576); }
    else if (i < 1376256) { src = Wk; dst = g_Wh; off = (size_t)(i - 1310720) + 262144; s4 = (size_t)(i - 1310720); }
    else if (i < 1441792) { src = Wv; dst = g_Wh; off = (size_t)(i - 1376256) + 327680; s4 = (size_t)(i - 1376256); }
    else if (i < 1703936) { src = Wp; dst = g_Ph; off = (size_t)(i - 1441792); s4 = (size_t)(i - 1441792); }
    else return;
    float4 v = *(const float4*)(src + s4 * 4);
    __half h[4] = { __float2half(v.x), __float2half(v.y),
                    __float2half(v.z), __float2half(v.w) };
    *(uint2*)(dst + off * 4) = *(uint2*)h;
}

// ---------------------------------------------------------------------------
// fp16 1-pass HMMA GEMM: C = A @ B^T, 128x128 tile, 3-stage cp.async,
// single barrier per K-iteration (prefetch issued after the barrier).
// ---------------------------------------------------------------------------
#define G_AR   10240
#define G_STG  (2 * G_AR)       // A + B per stage
#define G_SMEM (3 * G_STG)

__device__ __forceinline__ void mma_gemm(
    const __half* __restrict__ A, const __half* __restrict__ B,
    float* __restrict__ Cb, int ldc, int m0)
{
    extern __shared__ char smdyn[];
    uint32_t sb0 = smem_u32(smdyn);

    int t = threadIdx.x;
    int wid = t >> 5, lane = t & 31;
    int wr = wid >> 2, wc = wid & 3;

    const __half* srcs[2] = { A + (size_t)m0 * 1024, B };

    float acc[4][4][4];
    #pragma unroll
    for (int mt = 0; mt < 4; mt++)
        #pragma unroll
        for (int nt = 0; nt < 4; nt++)
            #pragma unroll
            for (int e = 0; e < 4; e++) acc[mt][nt][e] = 0.f;

    // prologue: stages 0, 1
    #pragma unroll
    for (int s = 0; s < 2; s++) {
        uint32_t base = sb0 + s * G_STG;
        #pragma unroll
        for (int i = 0; i < 4; i++) {
            int c = t + i * 256;
            int arr = c >> 9, cc = c & 511, row = cc >> 2, seg = (cc & 3) * 8;
            cpa16(base + (uint32_t)(arr * G_AR + row * 80 + seg * 2),
                  srcs[arr] + (size_t)row * 1024 + s * 32 + seg);
        }
        CP_COMMIT();
    }

    for (int it = 0; it < 32; it++) {
        if (it + 1 < 32) { CP_WAIT(1); } else { CP_WAIT(0); }
        __syncthreads();

        if (it + 2 < 32) {
            int st = (it + 2) % 3;
            uint32_t base = sb0 + st * G_STG;
            int k0 = (it + 2) * 32;
            #pragma unroll
            for (int i = 0; i < 4; i++) {
                int c = t + i * 256;
                int arr = c >> 9, cc = c & 511, row = cc >> 2, seg = (cc & 3) * 8;
                cpa16(base + (uint32_t)(arr * G_AR + row * 80 + seg * 2),
                      srcs[arr] + (size_t)row * 1024 + k0 + seg);
            }
            CP_COMMIT();
        }

        uint32_t sb = sb0 + (it % 3) * G_STG;
        uint32_t aA = sb, aB = sb + G_AR;

        #pragma unroll
        for (int ks = 0; ks < 2; ks++) {
            int kk = ks * 16;
            uint32_t fA[4][4], fB[4][2];
            int arow = lane & 15;
            int acol = kk + (lane >> 4) * 8;
            #pragma unroll
            for (int mt = 0; mt < 4; mt++) {
                uint32_t off = (uint32_t)((wr * 64 + mt * 16 + arow) * 80 + acol * 2);
                ldsm4(fA[mt], aA + off);
            }
            #pragma unroll
            for (int nt2 = 0; nt2 < 4; nt2 += 2) {
                int ntl = nt2 + (lane >> 4);
                uint32_t bk[4];
                uint32_t off = (uint32_t)((wc * 32 + ntl * 8 + (lane & 7)) * 80
                                          + (kk + (lane & 8)) * 2);
                ldsm4(bk, aB + off);
                fB[nt2][0] = bk[0];     fB[nt2][1] = bk[1];
                fB[nt2+1][0] = bk[2];   fB[nt2+1][1] = bk[3];
            }
            #pragma unroll
            for (int mt = 0; mt < 4; mt++)
                #pragma unroll
                for (int nt = 0; nt < 4; nt++)
                    mmah(acc[mt][nt], fA[mt], fB[nt]);
        }
    }

    #pragma unroll
    for (int mt = 0; mt < 4; mt++)
        #pragma unroll
        for (int nt = 0; nt < 4; nt++) {
            int r0 = m0 + wr * 64 + mt * 16 + (lane >> 2);
            int c0 = wc * 32 + nt * 8 + (lane & 3) * 2;
            float2 w0; w0.x = acc[mt][nt][0]; w0.y = acc[mt][nt][1];
            float2 w1; w1.x = acc[mt][nt][2]; w1.y = acc[mt][nt][3];
            *(float2*)&Cb[(size_t)r0 * ldc + c0]       = w0;
            *(float2*)&Cb[(size_t)(r0 + 8) * ldc + c0] = w1;
        }
}

__global__ __launch_bounds__(256) void qkv_gemm_mma()
{
    int n0 = blockIdx.x * 128;
    int m0 = blockIdx.y * 128;
    float* Cb; int ldc;
    if (n0 < 1024)      { Cb = g_Q + n0;          ldc = 1024; }
    else if (n0 < 1280) { Cb = g_K + (n0 - 1024); ldc = 256;  }
    else                { Cb = g_V + (n0 - 1280); ldc = 256;  }
    mma_gemm(g_Xh, g_Wh + (size_t)n0 * 1024, Cb, ldc, m0);
}

__global__ __launch_bounds__(256) void proj_gemm_mma(float* __restrict__ out)
{
    int n0 = blockIdx.x * 128;
    int m0 = blockIdx.y * 128;
    mma_gemm(g_Yh, g_Ph + (size_t)n0 * 1024, out + n0, 1024, m0);
}

// ---------------------------------------------------------------------------
// Postproc: gate+ve into V, RoPE + RMS-norm on Q/K; Q gets 1/8 score scale
// folded in (exact power of 2).
// ---------------------------------------------------------------------------
__global__ __launch_bounds__(128) void postproc(
    const float* __restrict__ x, const float* __restrict__ ve,
    const float* __restrict__ cosb, const float* __restrict__ sinb,
    const float* __restrict__ Wgate)
{
    int tok = blockIdx.x;
    int s = tok & (SS - 1);
    int t = threadIdx.x;
    int w = t >> 5;
    int lane = t & 31;

    __shared__ float gate[4];
    __shared__ float x12[12];

    if (t < 12) x12[t] = x[(size_t)tok * EE + t];
    __syncthreads();
    if (t < 4) {
        float acc = 0.f;
        #pragma unroll
        for (int c = 0; c < 12; c++) acc += x12[c] * Wgate[t * 12 + c];
        gate[t] = 3.f / (1.f + __expf(-acc));
    }
    __syncthreads();

    for (int i = t; i < 256; i += 128) {
        int hh = i >> 6;
        float v = g_V[(size_t)tok * 256 + i] + gate[hh] * ve[(size_t)tok * 256 + i];
        g_Vh[(size_t)tok * 256 + i] = __float2half(v);
    }

    const float EPS = 1.1920929e-7f;
    float cv = cosb[s * 32 + lane];
    float sv = sinb[s * 32 + lane];

    #pragma unroll
    for (int i = 0; i < 4; i++) {
        int h = w + 4 * i;
        const float* qp = &g_Q[(size_t)tok * 1024 + h * 64];
        float x1 = qp[lane], x2 = qp[lane + 32];
        float r1 =  x1 * cv + x2 * sv;
        float r2 = -x1 * sv + x2 * cv;
        float ss = r1 * r1 + r2 * r2;
        #pragma unroll
        for (int o = 16; o; o >>= 1) ss += __shfl_xor_sync(0xFFFFFFFFu, ss, o);
        float scale = rsqrtf(ss * (1.f / 64.f) + EPS) * (1.2f * 0.125f);
        size_t base = (size_t)tok * 1024 + h * 64;
        g_Qh[base + lane]      = __float2half(r1 * scale);
        g_Qh[base + lane + 32] = __float2half(r2 * scale);
    }
    {
        const float* kp = &g_K[(size_t)tok * 256 + w * 64];
        float x1 = kp[lane], x2 = kp[lane + 32];
        float r1 =  x1 * cv + x2 * sv;
        float r2 = -x1 * sv + x2 * cv;
        float ss = r1 * r1 + r2 * r2;
        #pragma unroll
        for (int o = 16; o; o >>= 1) ss += __shfl_xor_sync(0xFFFFFFFFu, ss, o);
        float scale = rsqrtf(ss * (1.f / 64.f) + EPS) * 1.2f;
        size_t base = (size_t)tok * 256 + w * 64;
        g_Kh[base + lane]      = __float2half(r1 * scale);
        g_Kh[base + lane + 32] = __float2half(r2 * scale);
    }
}

// ---------------------------------------------------------------------------
// Flash attention, fp16 single-pass, 3-stage cp.async, one barrier per tile.
// Grid (8, NH, BB), 256 threads. CTA does q-blocks {15-p, p} (34 tiles each).
// ---------------------------------------------------------------------------
#define A_AR   9216
#define A_STG  (2 * A_AR)       // K + V per stage
#define A_SMEM (3 * A_STG)

__global__ __launch_bounds__(256) void attn_mma()
{
    extern __shared__ char smdyn[];
    uint32_t sb0 = smem_u32(smdyn);

    int p  = blockIdx.x;
    int h  = blockIdx.y;
    int b  = blockIdx.z;
    int hkv = h >> 2;
    int t = threadIdx.x;
    int wid = t >> 5, lane = t & 31;

    const __half* srcs[2] = { g_Kh, g_Vh };

    #pragma unroll 1
    for (int bi = 0; bi < 2; bi++) {
        int jblk = bi ? p : (15 - p);
        size_t tok0 = (size_t)b * SS + jblk * 128;
        int ntiles = 2 * jblk + 2;

        // ---- stage Q (stage-0 region), build persistent fragments ----
        for (int idx = t; idx < 1024; idx += 256) {
            int row = idx >> 3, ch = (idx & 7) * 8;
            size_t g = (tok0 + row) * 1024 + h * 64 + ch;
            *(uint4*)(smdyn + row * 144 + ch * 2) = *(const uint4*)&g_Qh[g];
        }
        __syncthreads();

        uint32_t qh[4][4];
        {
            int arow = wid * 16 + (lane & 15);
            int acol = (lane >> 4) * 8;
            #pragma unroll
            for (int kc = 0; kc < 4; kc++) {
                uint32_t off = (uint32_t)(arow * 144 + (kc * 16 + acol) * 2);
                ldsm4(qh[kc], sb0 + off);
            }
        }
        __syncthreads();

        float accO[8][4];
        #pragma unroll
        for (int nt = 0; nt < 8; nt++)
            #pragma unroll
            for (int e = 0; e < 4; e++) accO[nt][e] = 0.f;
        float m0 = -1e30f, m1 = -1e30f, l0 = 0.f, l1 = 0.f;

        // prologue: tiles 0, 1 into stages 0, 1
        #pragma unroll
        for (int s = 0; s < 2; s++) {
            if (s < ntiles) {
                uint32_t base = sb0 + s * A_STG;
                size_t gb = (size_t)b * SS + s * 64;
                #pragma unroll
                for (int i = 0; i < 4; i++) {
                    int c = t + i * 256;
                    int arr = c >> 9, cc = c & 511, row = cc >> 3, seg = (cc & 7) * 8;
                    cpa16(base + (uint32_t)(arr * A_AR + row * 144 + seg * 2),
                          srcs[arr] + (gb + row) * 256 + hkv * 64 + seg);
                }
                CP_COMMIT();
            }
        }

        for (int kt = 0; kt < ntiles; kt++) {
            if (kt + 1 < ntiles) { CP_WAIT(1); } else { CP_WAIT(0); }
            __syncthreads();

            if (kt + 2 < ntiles) {
                uint32_t base = sb0 + ((kt + 2) % 3) * A_STG;
                size_t gb = (size_t)b * SS + (kt + 2) * 64;
                #pragma unroll
                for (int i = 0; i < 4; i++) {
                    int c = t + i * 256;
                    int arr = c >> 9, cc = c & 511, row = cc >> 3, seg = (cc & 7) * 8;
                    cpa16(base + (uint32_t)(arr * A_AR + row * 144 + seg * 2),
                          srcs[arr] + (gb + row) * 256 + hkv * 64 + seg);
                }
                CP_COMMIT();
            }

            uint32_t sb = sb0 + (kt % 3) * A_STG;
            uint32_t aK = sb, aV = sb + A_AR;

            // ---- S = Q K^T (scale pre-folded into Q) ----
            float sacc[8][4];
            #pragma unroll
            for (int nt = 0; nt < 8; nt++)
                #pragma unroll
                for (int e = 0; e < 4; e++) sacc[nt][e] = 0.f;

            #pragma unroll
            for (int kc = 0; kc < 4; kc++) {
                int kk = kc * 16;
                #pragma unroll
                for (int nt2 = 0; nt2 < 8; nt2 += 2) {
                    int ntl = nt2 + (lane >> 4);
                    uint32_t bk[4];
                    uint32_t off = (uint32_t)((ntl * 8 + (lane & 7)) * 144
                                              + (kk + (lane & 8)) * 2);
                    ldsm4(bk, aK + off);
                    mmah(sacc[nt2],     qh[kc], bk);
                    mmah(sacc[nt2 + 1], qh[kc], bk + 2);
                }
            }

            if (kt >= 2 * jblk) {
                int cb2 = (kt - 2 * jblk) * 64;
                int rloc = wid * 16 + (lane >> 2);
                #pragma unroll
                for (int nt = 0; nt < 8; nt++) {
                    int cl = cb2 + nt * 8 + (lane & 3) * 2;
                    if (cl     > rloc)     sacc[nt][0] = -1e30f;
                    if (cl + 1 > rloc)     sacc[nt][1] = -1e30f;
                    if (cl     > rloc + 8) sacc[nt][2] = -1e30f;
                    if (cl + 1 > rloc + 8) sacc[nt][3] = -1e30f;
                }
            }

            // ---- online softmax ----
            float mx0 = -1e30f, mx1 = -1e30f;
            #pragma unroll
            for (int nt = 0; nt < 8; nt++) {
                mx0 = fmaxf(mx0, fmaxf(sacc[nt][0], sacc[nt][1]));
                mx1 = fmaxf(mx1, fmaxf(sacc[nt][2], sacc[nt][3]));
            }
            mx0 = fmaxf(mx0, __shfl_xor_sync(0xFFFFFFFFu, mx0, 1));
            mx0 = fmaxf(mx0, __shfl_xor_sync(0xFFFFFFFFu, mx0, 2));
            mx1 = fmaxf(mx1, __shfl_xor_sync(0xFFFFFFFFu, mx1, 1));
            mx1 = fmaxf(mx1, __shfl_xor_sync(0xFFFFFFFFu, mx1, 2));

            float mn0 = fmaxf(m0, mx0), mn1 = fmaxf(m1, mx1);
            float cr0 = __expf(m0 - mn0), cr1 = __expf(m1 - mn1);
            float rs0 = 0.f, rs1 = 0.f;
            #pragma unroll
            for (int nt = 0; nt < 8; nt++) {
                float p0 = __expf(sacc[nt][0] - mn0);
                float p1 = __expf(sacc[nt][1] - mn0);
                float p2 = __expf(sacc[nt][2] - mn1);
                float p3 = __expf(sacc[nt][3] - mn1);
                sacc[nt][0] = p0; sacc[nt][1] = p1; sacc[nt][2] = p2; sacc[nt][3] = p3;
                rs0 += p0 + p1; rs1 += p2 + p3;
            }
            rs0 += __shfl_xor_sync(0xFFFFFFFFu, rs0, 1);
            rs0 += __shfl_xor_sync(0xFFFFFFFFu, rs0, 2);
            rs1 += __shfl_xor_sync(0xFFFFFFFFu, rs1, 1);
            rs1 += __shfl_xor_sync(0xFFFFFFFFu, rs1, 2);
            l0 = l0 * cr0 + rs0; l1 = l1 * cr1 + rs1;
            m0 = mn0; m1 = mn1;
            #pragma unroll
            for (int nt = 0; nt < 8; nt++) {
                accO[nt][0] *= cr0; accO[nt][1] *= cr0;
                accO[nt][2] *= cr1; accO[nt][3] *= cr1;
            }

            // ---- O += P V ----
            #pragma unroll
            for (int kc = 0; kc < 4; kc++) {
                uint32_t ph[4];
                ph[0] = packh(sacc[2*kc][0],   sacc[2*kc][1]);
                ph[1] = packh(sacc[2*kc][2],   sacc[2*kc][3]);
                ph[2] = packh(sacc[2*kc+1][0], sacc[2*kc+1][1]);
                ph[3] = packh(sacc[2*kc+1][2], sacc[2*kc+1][3]);
                int vrow = kc * 16 + (lane & 15);
                #pragma unroll
                for (int nt2 = 0; nt2 < 8; nt2 += 2) {
                    int ntl = nt2 + (lane >> 4);
                    uint32_t vv[4];
                    uint32_t off = (uint32_t)(vrow * 144 + ntl * 16);
                    ldsm4t(vv, aV + off);
                    mmah(accO[nt2],     ph, vv);
                    mmah(accO[nt2 + 1], ph, vv + 2);
                }
            }
        }

        // ---- epilogue: write rounded fp16 Y ----
        float inv0 = 1.f / l0, inv1 = 1.f / l1;
        int r0 = wid * 16 + (lane >> 2);
        #pragma unroll
        for (int nt = 0; nt < 8; nt++) {
            int col = h * 64 + nt * 8 + (lane & 3) * 2;
            size_t i0 = (tok0 + r0) * 1024 + col;
            size_t i1 = (tok0 + r0 + 8) * 1024 + col;
            *(uint32_t*)&g_Yh[i0] = packh(accO[nt][0] * inv0, accO[nt][1] * inv0);
            *(uint32_t*)&g_Yh[i1] = packh(accO[nt][2] * inv1, accO[nt][3] * inv1);
        }
        __syncthreads();
    }
}

// ---------------------------------------------------------------------------
extern "C" void kernel_launch(void* const* d_in, const int* in_sizes, int n_in,
                              void* d_out, int out_size)
{
    const float* x     = (const float*)d_in[0];
    const float* ve    = (const float*)d_in[1];
    const float* cosb  = (const float*)d_in[2];
    const float* sinb  = (const float*)d_in[3];
    const float* Wq    = (const float*)d_in[5];
    const float* Wk    = (const float*)d_in[6];
    const float* Wv    = (const float*)d_in[7];
    const float* Wproj = (const float*)d_in[8];
    const float* Wgate = (const float*)d_in[9];
    float* out = (float*)d_out;

    static bool attr_set = false;
    if (!attr_set) {
        cudaFuncSetAttribute(qkv_gemm_mma, cudaFuncAttributeMaxDynamicSharedMemorySize, G_SMEM);
        cudaFuncSetAttribute(proj_gemm_mma, cudaFuncAttributeMaxDynamicSharedMemorySize, G_SMEM);
        cudaFuncSetAttribute(attn_mma, cudaFuncAttributeMaxDynamicSharedMemorySize, A_SMEM);
        attr_set = true;
    }

    round_all<<<1703936 / 256, 256>>>(x, Wq, Wk, Wv, Wproj);

    dim3 g1(12, 32);
    qkv_gemm_mma<<<g1, 256, G_SMEM>>>();

    postproc<<<TOKENS, 128>>>(x, ve, cosb, sinb, Wgate);

    dim3 g3(8, NH, BB);
    attn_mma<<<g3, 256, A_SMEM>>>();

    dim3 g4(8, 32);
    proj_gemm_mma<<<g4, 256, G_SMEM>>>(out);
}